// round 8
// baseline (speedup 1.0000x reference)
#include <cuda_runtime.h>
#include <cuda_bf16.h>
#include <math.h>
#include <stdint.h>

// Problem constants
#define NXC   32768
#define NTOT  66560
#define DIMC  28
#define HC    300
#define FD    100
#define GD    28
#define JC    1024

#define PWH   320
#define FDP   112
#define GDP   32
#define WOFF  (320 * 320)

// ---------------- scratch ----------------------------------------------------
__device__ float g_in0 [(size_t)NTOT * DIMC];
__device__ __align__(16) __nv_bfloat16 g_inh[(size_t)NTOT * 32];
__device__ __align__(16) __nv_bfloat16 g_inl[(size_t)NTOT * 32];
__device__ __align__(16) __nv_bfloat16 g_Ah0[(size_t)NTOT * PWH];
__device__ __align__(16) __nv_bfloat16 g_Al0[(size_t)NTOT * PWH];
__device__ __align__(16) __nv_bfloat16 g_Ah1[(size_t)NTOT * PWH];
__device__ __align__(16) __nv_bfloat16 g_Al1[(size_t)NTOT * PWH];
__device__ __align__(16) __nv_bfloat16 g_Bh0[(size_t)NTOT * PWH];
__device__ __align__(16) __nv_bfloat16 g_Bl0[(size_t)NTOT * PWH];
__device__ __align__(16) __nv_bfloat16 g_Bh1[(size_t)NTOT * PWH];
__device__ __align__(16) __nv_bfloat16 g_Bl1[(size_t)NTOT * PWH];
__device__ __align__(16) __nv_bfloat16 g_Wh[12 * WOFF];
__device__ __align__(16) __nv_bfloat16 g_Wl[12 * WOFF];
__device__ __align__(16) __nv_bfloat16 g_Fh[(size_t)NTOT * FDP];
__device__ __align__(16) __nv_bfloat16 g_Fl[(size_t)NTOT * FDP];
__device__ __align__(16) __nv_bfloat16 g_Gh[(size_t)NTOT * GDP];
__device__ __align__(16) __nv_bfloat16 g_Gl[(size_t)NTOT * GDP];
__device__ __align__(16) __nv_bfloat16 g_FvTh[FDP * JC];
__device__ __align__(16) __nv_bfloat16 g_FvTl[FDP * JC];
__device__ __align__(16) __nv_bfloat16 g_GvTh[GDP * JC];
__device__ __align__(16) __nv_bfloat16 g_GvTl[GDP * JC];
__device__ float g_nF  [NTOT];
__device__ float g_nG  [NTOT];
__device__ float g_fm  [(size_t)NXC * JC];
__device__ float g_colsum[JC];
__device__ float g_mu    [JC];
__device__ float g_scal  [8];

__device__ __forceinline__ void split2(float x, __nv_bfloat16& h, __nv_bfloat16& l) {
    h = __float2bfloat16(x);
    l = __float2bfloat16(x - __bfloat162float(h));
}
__device__ __forceinline__ float fexp2(float x) {
    float r;
    asm("ex2.approx.ftz.f32 %0, %1;" : "=f"(r) : "f"(x));
    return r;
}

// ---------------- prep kernels ----------------------------------------------
__global__ void concat_kernel(const float* __restrict__ XY, const float* __restrict__ V) {
    int t = blockIdx.x * blockDim.x + threadIdx.x;
    const int total = NTOT * DIMC;
    const int xyn   = 2 * NXC * DIMC;
    if (t >= total) return;
    g_in0[t] = (t < xyn) ? XY[t] : V[t - xyn];
}
__global__ void concat_split_kernel(const float* __restrict__ XY, const float* __restrict__ V) {
    int t = blockIdx.x * blockDim.x + threadIdx.x;
    if (t >= NTOT * 32) return;
    int r = t >> 5, c = t & 31;
    float v = 0.0f;
    if (c < DIMC) {
        int idx = r * DIMC + c;
        v = (r < 2 * NXC) ? XY[idx] : V[(r - 2 * NXC) * DIMC + c];
    }
    __nv_bfloat16 h, l; split2(v, h, l);
    g_inh[t] = h; g_inl[t] = l;
}
__global__ void pad_zero_kernel() {
    int t = blockIdx.x * blockDim.x + threadIdx.x;
    if (t >= NTOT * (PWH - HC)) return;
    int r = t / (PWH - HC), c = HC + t % (PWH - HC);
    size_t o = (size_t)r * PWH + c;
    __nv_bfloat16 z = __float2bfloat16(0.0f);
    g_Ah0[o] = z; g_Al0[o] = z; g_Ah1[o] = z; g_Al1[o] = z;
    g_Bh0[o] = z; g_Bl0[o] = z; g_Bh1[o] = z; g_Bl1[o] = z;
}
__global__ void pad_fg_kernel() {
    int t = blockIdx.x * blockDim.x + threadIdx.x;
    if (t >= NTOT * 12) return;
    int r = t / 12, c = t % 12;
    __nv_bfloat16 z = __float2bfloat16(0.0f);
    size_t of = (size_t)r * FDP + 100 + c;
    g_Fh[of] = z; g_Fl[of] = z;
    if (c < 4) {
        size_t og = (size_t)r * GDP + 28 + c;
        g_Gh[og] = z; g_Gl[og] = z;
    }
}
__global__ void init_acc_kernel() {
    int t = threadIdx.x;
    if (t < JC) g_colsum[t] = 0.0f;
    if (t < 8)  g_scal[t]   = 0.0f;
}
struct WPrepArgs {
    const float* W[12];
    int Fi[12];
    int Fo[12];
};
__global__ void prep_w_all(WPrepArgs a) {
    int layer = blockIdx.y;
    int idx = blockIdx.x * blockDim.x + threadIdx.x;
    if (idx >= WOFF) return;
    int k = idx / 320, n = idx - k * 320;
    int Fi = a.Fi[layer], Fo = a.Fo[layer];
    float v = (k < Fi && n < Fo) ? a.W[layer][(size_t)k * Fo + n] : 0.0f;
    __nv_bfloat16 h, l; split2(v, h, l);
    g_Wh[(size_t)layer * WOFF + idx] = h;
    g_Wl[(size_t)layer * WOFF + idx] = l;
}
__global__ void transpose_v_kernel() {
    int t = blockIdx.x * blockDim.x + threadIdx.x;
    if (t < FDP * JC) {
        int k = t >> 10, j = t & 1023;
        size_t src = (size_t)(2 * NXC + j) * FDP + k;
        g_FvTh[t] = g_Fh[src];
        g_FvTl[t] = g_Fl[src];
    }
    if (t < GDP * JC) {
        int k = t >> 10, j = t & 1023;
        size_t src = (size_t)(2 * NXC + j) * GDP + k;
        g_GvTh[t] = g_Gh[src];
        g_GvTl[t] = g_Gl[src];
    }
}

// =============== shared MMA helpers ==========================================
__device__ __forceinline__ uint32_t smem_u32(const void* p) {
    uint32_t a;
    asm("{ .reg .u64 t; cvta.to.shared.u64 t, %1; cvt.u32.u64 %0, t; }" : "=r"(a) : "l"(p));
    return a;
}
__device__ __forceinline__ void ldsm_x4(uint32_t addr, uint32_t r[4]) {
    asm volatile("ldmatrix.sync.aligned.m8n8.x4.shared.b16 {%0,%1,%2,%3}, [%4];"
        : "=r"(r[0]), "=r"(r[1]), "=r"(r[2]), "=r"(r[3]) : "r"(addr));
}
__device__ __forceinline__ void ldsm_x4_t(uint32_t addr, uint32_t r[4]) {
    asm volatile("ldmatrix.sync.aligned.m8n8.x4.trans.shared.b16 {%0,%1,%2,%3}, [%4];"
        : "=r"(r[0]), "=r"(r[1]), "=r"(r[2]), "=r"(r[3]) : "r"(addr));
}
__device__ __forceinline__ void mma_bf16(float c[4], const uint32_t a[4],
                                         uint32_t b0, uint32_t b1) {
    asm volatile(
        "mma.sync.aligned.m16n8k16.row.col.f32.bf16.bf16.f32 "
        "{%0,%1,%2,%3}, {%4,%5,%6,%7}, {%8,%9}, {%0,%1,%2,%3};"
        : "+f"(c[0]), "+f"(c[1]), "+f"(c[2]), "+f"(c[3])
        : "r"(a[0]), "r"(a[1]), "r"(a[2]), "r"(a[3]), "r"(b0), "r"(b1));
}
#define CP_ASYNC16(dst_u32, src_ptr) \
    asm volatile("cp.async.cg.shared.global [%0], [%1], 16;" \
        :: "r"(dst_u32), "l"(src_ptr) : "memory")
#define CP_COMMIT() asm volatile("cp.async.commit_group;" ::: "memory")
#define CP_WAIT(n)  asm volatile("cp.async.wait_group %0;" :: "n"(n) : "memory")

// =============== bf16-split GEMM: 4 warps, warp tile 32x64 ====================
#define BMM 128
#define BNN 64
#define BKK 32
#define A_STRIDE 40
#define B_STRIDE 72
// 3 stages: AH 3x5120, AL 3x5120, BH 3x2304, BL 3x2304 (bf16 units)
#define SM_AH 0
#define SM_AL 15360
#define SM_BH 30720
#define SM_BL 37632
#define GEMM_SMEM_BYTES 89088

__global__ __launch_bounds__(128, 2)
void mma_gemm4(const __nv_bfloat16* __restrict__ AhD, const __nv_bfloat16* __restrict__ AlD,
               const __nv_bfloat16* __restrict__ AhA, const __nv_bfloat16* __restrict__ AlA,
               int PWa,
               const __nv_bfloat16* __restrict__ WhB, const __nv_bfloat16* __restrict__ WlB,
               int layer,
               const float* __restrict__ biasD, const float* __restrict__ biasA,
               int FoD, int FoA,
               __nv_bfloat16* __restrict__ ChD, __nv_bfloat16* __restrict__ ClD,
               __nv_bfloat16* __restrict__ ChA, __nv_bfloat16* __restrict__ ClA,
               int PWcD, int PWcA,
               const float* __restrict__ resA,
               int nC, int doRelu)
{
    extern __shared__ __nv_bfloat16 dyn[];

    const int net = blockIdx.z;
    const __nv_bfloat16* Ah = net ? AhA : AhD;
    const __nv_bfloat16* Al = net ? AlA : AlD;
    const __nv_bfloat16* Wh = WhB + (size_t)(layer + 6 * net) * WOFF;
    const __nv_bfloat16* Wl = WlB + (size_t)(layer + 6 * net) * WOFF;
    const float* bias = net ? biasA : biasD;
    const int Fo  = net ? FoA : FoD;
    __nv_bfloat16* Ch = net ? ChA : ChD;
    __nv_bfloat16* Cl = net ? ClA : ClD;
    const int PWc = net ? PWcA : PWcD;
    const float* res = net ? resA : (const float*)0;

    const int n0 = blockIdx.x * BNN;
    if (n0 >= Fo) return;

    const int tid    = threadIdx.x;
    const int lane   = tid & 31;
    const int wid    = tid >> 5;          // 0..3
    const int warp_m = wid;               // 32 rows each
    const int rbase  = blockIdx.y * BMM;

    // cp.async lane mapping (128 threads)
    const int a_row0 = tid >> 2;          // 0..31 (+32*i)
    const int a_kk   = (tid & 3) * 8;
    const int bk     = tid >> 3;          // 0..15 (+16*i)
    const int bn     = (tid & 7) * 8;

    const uint32_t dyn32 = smem_u32(dyn);
    const int a_row  = warp_m * 32 + (lane & 15);
    const int a_kadd = (lane >> 4) * 8;
    const uint32_t aHiB = dyn32 + (uint32_t)(SM_AH + a_row * A_STRIDE + a_kadd) * 2u;
    const uint32_t aLoB = dyn32 + (uint32_t)(SM_AL + a_row * A_STRIDE + a_kadd) * 2u;
    const int b_k    = (lane & 7) + ((lane & 8) ? 8 : 0);
    const int b_nb   = (lane & 16) ? 8 : 0;        // warp covers all 64 cols
    const uint32_t bHiB = dyn32 + (uint32_t)(SM_BH + b_k * B_STRIDE + b_nb) * 2u;
    const uint32_t bLoB = dyn32 + (uint32_t)(SM_BL + b_k * B_STRIDE + b_nb) * 2u;

    const uint32_t dA0 = dyn32 + (uint32_t)(a_row0 * A_STRIDE + a_kk) * 2u;
    const uint32_t dB0 = dyn32 + (uint32_t)(SM_BH + bk * B_STRIDE + bn) * 2u;

    float acc[2][8][4];
    #pragma unroll
    for (int i = 0; i < 2; i++)
        #pragma unroll
        for (int j = 0; j < 8; j++)
            #pragma unroll
            for (int q = 0; q < 4; q++) acc[i][j][q] = 0.0f;

    #define ISSUE_CHUNK(k0, bf) do { \
        uint32_t od = (uint32_t)(bf) * 10240u; \
        uint32_t ob = (uint32_t)(bf) * 4608u; \
        _Pragma("unroll") \
        for (int i = 0; i < 4; i++) { \
            size_t o = (size_t)(rbase + a_row0 + 32 * i) * PWa + (k0) + a_kk; \
            uint32_t d = dA0 + od + (uint32_t)(32 * i * A_STRIDE) * 2u; \
            CP_ASYNC16(d,           Ah + o); \
            CP_ASYNC16(d + 30720u,  Al + o); \
        } \
        _Pragma("unroll") \
        for (int i = 0; i < 2; i++) { \
            size_t bo = (size_t)((k0) + bk + 16 * i) * 320 + n0 + bn; \
            uint32_t db = dB0 + ob + (uint32_t)(16 * i * B_STRIDE) * 2u; \
            CP_ASYNC16(db,           Wh + bo); \
            CP_ASYNC16(db + 13824u,  Wl + bo); \
        } \
        CP_COMMIT(); \
    } while (0)

    ISSUE_CHUNK(0, 0);
    if (nC > 1) ISSUE_CHUNK(32, 1);

    for (int c = 0; c < nC; c++) {
        const int buf = c % 3;
        const uint32_t aOff = (uint32_t)buf * 10240u;
        const uint32_t bOff = (uint32_t)buf * 4608u;

        if (c + 2 < nC) { ISSUE_CHUNK((c + 2) * BKK, (c + 2) % 3); CP_WAIT(2); }
        else if (c + 1 < nC) { CP_WAIT(1); }
        else { CP_WAIT(0); }
        __syncthreads();

        #pragma unroll
        for (int ks = 0; ks < 2; ks++) {
            uint32_t Ahr[2][4], Alr[2][4], Bhr[4][4], Blr[4][4];
            #pragma unroll
            for (int mi = 0; mi < 2; mi++) {
                uint32_t off = aOff + (uint32_t)(mi * 16 * A_STRIDE + ks * 16) * 2u;
                ldsm_x4(aHiB + off, Ahr[mi]);
                ldsm_x4(aLoB + off, Alr[mi]);
            }
            #pragma unroll
            for (int np = 0; np < 4; np++) {
                uint32_t off = bOff + (uint32_t)(np * 16 + ks * 16 * B_STRIDE) * 2u;
                ldsm_x4_t(bHiB + off, Bhr[np]);
                ldsm_x4_t(bLoB + off, Blr[np]);
            }
            #pragma unroll
            for (int mi = 0; mi < 2; mi++)
                #pragma unroll
                for (int nj = 0; nj < 8; nj++) {
                    const int np = nj >> 1, hf = (nj & 1) * 2;
                    mma_bf16(acc[mi][nj], Ahr[mi], Bhr[np][hf], Bhr[np][hf + 1]);
                    mma_bf16(acc[mi][nj], Ahr[mi], Blr[np][hf], Blr[np][hf + 1]);
                    mma_bf16(acc[mi][nj], Alr[mi], Bhr[np][hf], Bhr[np][hf + 1]);
                }
        }
        __syncthreads();
    }
    #undef ISSUE_CHUNK

    // epilogue: warp owns 32 rows x 64 cols
    #pragma unroll
    for (int mi = 0; mi < 2; mi++)
        #pragma unroll
        for (int nj = 0; nj < 8; nj++) {
            int col = n0 + nj * 8 + (lane & 3) * 2;
            if (col >= Fo) continue;
            float2 b2 = *(const float2*)(bias + col);
            #pragma unroll
            for (int half = 0; half < 2; half++) {
                int row = rbase + warp_m * 32 + mi * 16 + (lane >> 2) + half * 8;
                float vx = acc[mi][nj][half * 2 + 0] + b2.x;
                float vy = acc[mi][nj][half * 2 + 1] + b2.y;
                if (res) {
                    float2 r2 = *(const float2*)(res + (size_t)row * Fo + col);
                    vx += r2.x; vy += r2.y;
                }
                if (doRelu) { vx = fmaxf(vx, 0.0f); vy = fmaxf(vy, 0.0f); }
                __nv_bfloat16 hx, lx, hy, ly;
                split2(vx, hx, lx); split2(vy, hy, ly);
                *(__nv_bfloat162*)(Ch + (size_t)row * PWc + col) = __halves2bfloat162(hx, hy);
                *(__nv_bfloat162*)(Cl + (size_t)row * PWc + col) = __halves2bfloat162(lx, ly);
            }
        }
}

// ---------------- row squared norms from hi/lo bf16 --------------------------
__global__ void row_norms_hl(const __nv_bfloat16* __restrict__ H,
                             const __nv_bfloat16* __restrict__ L,
                             float* __restrict__ out, int D)
{
    int warp = (blockIdx.x * blockDim.x + threadIdx.x) >> 5;
    int lane = threadIdx.x & 31;
    if (warp >= NTOT) return;
    float s = 0.0f;
    for (int k = lane; k < D; k += 32) {
        size_t o = (size_t)warp * D + k;
        float v = __bfloat162float(H[o]) + __bfloat162float(L[o]);
        s += v * v;
    }
    #pragma unroll
    for (int o = 16; o; o >>= 1) s += __shfl_xor_sync(0xffffffffu, s, o);
    if (lane == 0) out[warp] = s;
}

// ---------------- fused fm kernel: 512 threads, 16 warps ---------------------
#define FMI 64
#define FMJ 128
#define AF_S 120
#define BF_S 136
#define AG_S 40
#define OF_AXH 0
#define OF_AXL 7680
#define OF_AYH 15360
#define OF_AYL 23040
#define OF_BH  30720
#define OF_BL  45952
#define OG_AXH 0
#define OG_AXL 2560
#define OG_AYH 5120
#define OG_AYL 7680
#define OG_BH  10240
#define OG_BL  14592
#define FM_DYN_BYTES (61184 * 2)

__global__ __launch_bounds__(512)
void fm2_kernel(const float* __restrict__ eps_p, const float* __restrict__ sig_p,
                const float* __restrict__ sig0_p, const float* __restrict__ cst_p)
{
    extern __shared__ __nv_bfloat16 dynb[];
    __shared__ float nfx[64], nfy[64], ngx[64], ngy[64];
    __shared__ float nfv[128], ngv[128];
    __shared__ float scs[128];
    __shared__ float red[512];

    const int tid    = threadIdx.x;
    const int lane   = tid & 31;
    const int wid    = tid >> 5;
    const int warp_m = wid >> 3;
    const int warp_n = wid & 7;
    const int ibase  = blockIdx.y * FMI;
    const int jbase  = blockIdx.x * FMJ;
    const int XR = ibase, YR = NXC + ibase, VR = 2 * NXC + jbase;

    if (tid < 64) {
        nfx[tid] = g_nF[XR + tid]; nfy[tid] = g_nF[YR + tid];
        ngx[tid] = g_nG[XR + tid]; ngy[tid] = g_nG[YR + tid];
    } else if (tid < 192) {
        int j = tid - 64;
        nfv[j] = g_nF[VR + j]; ngv[j] = g_nG[VR + j];
    } else if (tid < 320) {
        scs[tid - 192] = 0.0f;
    }

    for (int e = tid; e < 896; e += 512) {
        int r = e / 14, kv = (e % 14) * 8;
        *(uint4*)&dynb[OF_AXH + r * AF_S + kv] = *(const uint4*)&g_Fh[(size_t)(XR + r) * FDP + kv];
        *(uint4*)&dynb[OF_AXL + r * AF_S + kv] = *(const uint4*)&g_Fl[(size_t)(XR + r) * FDP + kv];
        *(uint4*)&dynb[OF_AYH + r * AF_S + kv] = *(const uint4*)&g_Fh[(size_t)(YR + r) * FDP + kv];
        *(uint4*)&dynb[OF_AYL + r * AF_S + kv] = *(const uint4*)&g_Fl[(size_t)(YR + r) * FDP + kv];
    }
    for (int e = tid; e < 1792; e += 512) {
        int k = e >> 4, jv = (e & 15) * 8;
        *(uint4*)&dynb[OF_BH + k * BF_S + jv] = *(const uint4*)&g_FvTh[k * 1024 + jbase + jv];
        *(uint4*)&dynb[OF_BL + k * BF_S + jv] = *(const uint4*)&g_FvTl[k * 1024 + jbase + jv];
    }
    __syncthreads();

    const uint32_t dyn32 = smem_u32(dynb);
    const int a_row  = warp_m * 32 + (lane & 15);
    const int a_kadd = (lane >> 4) * 8;
    const int b_k    = lane & 15;
    const int b_n    = warp_n * 16 + ((lane & 16) ? 8 : 0);

    float accX[2][2][4], accY[2][2][4];
    #pragma unroll
    for (int i = 0; i < 2; i++)
        #pragma unroll
        for (int j = 0; j < 2; j++)
            #pragma unroll
            for (int q = 0; q < 4; q++) { accX[i][j][q] = 0.0f; accY[i][j][q] = 0.0f; }

    #pragma unroll
    for (int ks = 0; ks < 7; ks++) {
        uint32_t AXh[2][4], AXl[2][4], AYh[2][4], AYl[2][4], Bh[4], Bl[4];
        #pragma unroll
        for (int mi = 0; mi < 2; mi++) {
            uint32_t ao = (uint32_t)((a_row + mi * 16) * AF_S + ks * 16 + a_kadd) * 2u;
            ldsm_x4(dyn32 + OF_AXH * 2u + ao, AXh[mi]);
            ldsm_x4(dyn32 + OF_AXL * 2u + ao, AXl[mi]);
            ldsm_x4(dyn32 + OF_AYH * 2u + ao, AYh[mi]);
            ldsm_x4(dyn32 + OF_AYL * 2u + ao, AYl[mi]);
        }
        {
            uint32_t bo = (uint32_t)((b_k + ks * 16) * BF_S + b_n) * 2u;
            ldsm_x4_t(dyn32 + OF_BH * 2u + bo, Bh);
            ldsm_x4_t(dyn32 + OF_BL * 2u + bo, Bl);
        }
        #pragma unroll
        for (int mi = 0; mi < 2; mi++)
            #pragma unroll
            for (int nj = 0; nj < 2; nj++) {
                const int hf = nj * 2;
                mma_bf16(accX[mi][nj], AXh[mi], Bh[hf], Bh[hf + 1]);
                mma_bf16(accX[mi][nj], AXh[mi], Bl[hf], Bl[hf + 1]);
                mma_bf16(accX[mi][nj], AXl[mi], Bh[hf], Bh[hf + 1]);
                mma_bf16(accY[mi][nj], AYh[mi], Bh[hf], Bh[hf + 1]);
                mma_bf16(accY[mi][nj], AYh[mi], Bl[hf], Bl[hf + 1]);
                mma_bf16(accY[mi][nj], AYl[mi], Bh[hf], Bh[hf + 1]);
            }
    }

    const float LOG2E  = 1.4426950408889634f;
    const float ep     = 1.0f / (1.0f + __expf(-eps_p[0]));
    const float is2    = LOG2E / (sig_p[0]  * sig_p[0]);
    const float is0    = LOG2E / (sig0_p[0] * sig0_p[0]);
    const float cstv   = cst_p[0];
    const float one_ep = 1.0f - ep;

    #pragma unroll
    for (int mi = 0; mi < 2; mi++)
        #pragma unroll
        for (int nj = 0; nj < 2; nj++)
            #pragma unroll
            for (int q = 0; q < 4; q++) {
                int rl = warp_m * 32 + mi * 16 + (lane >> 2) + (q >> 1) * 8;
                int cl = warp_n * 16 + nj * 8 + (lane & 3) * 2 + (q & 1);
                float Dx = fmaxf(nfx[rl] + nfv[cl] - 2.0f * accX[mi][nj][q], 0.0f);
                float Dy = fmaxf(nfy[rl] + nfv[cl] - 2.0f * accY[mi][nj][q], 0.0f);
                accX[mi][nj][q] = fmaf(one_ep, fexp2(-Dx * is0), ep);
                accY[mi][nj][q] = fmaf(one_ep, fexp2(-Dy * is0), ep);
            }

    __syncthreads();
    if (tid < 256) {
        int r = tid >> 2, kv = (tid & 3) * 8;
        *(uint4*)&dynb[OG_AXH + r * AG_S + kv] = *(const uint4*)&g_Gh[(size_t)(XR + r) * GDP + kv];
        *(uint4*)&dynb[OG_AXL + r * AG_S + kv] = *(const uint4*)&g_Gl[(size_t)(XR + r) * GDP + kv];
        *(uint4*)&dynb[OG_AYH + r * AG_S + kv] = *(const uint4*)&g_Gh[(size_t)(YR + r) * GDP + kv];
        *(uint4*)&dynb[OG_AYL + r * AG_S + kv] = *(const uint4*)&g_Gl[(size_t)(YR + r) * GDP + kv];
    }
    {
        int k = tid >> 4, jv = (tid & 15) * 8;
        *(uint4*)&dynb[OG_BH + k * BF_S + jv] = *(const uint4*)&g_GvTh[k * 1024 + jbase + jv];
        *(uint4*)&dynb[OG_BL + k * BF_S + jv] = *(const uint4*)&g_GvTl[k * 1024 + jbase + jv];
    }
    __syncthreads();

    float gX[2][2][4], gY[2][2][4];
    #pragma unroll
    for (int i = 0; i < 2; i++)
        #pragma unroll
        for (int j = 0; j < 2; j++)
            #pragma unroll
            for (int q = 0; q < 4; q++) { gX[i][j][q] = 0.0f; gY[i][j][q] = 0.0f; }

    #pragma unroll
    for (int ks = 0; ks < 2; ks++) {
        uint32_t AXh[2][4], AXl[2][4], AYh[2][4], AYl[2][4], Bh[4], Bl[4];
        #pragma unroll
        for (int mi = 0; mi < 2; mi++) {
            uint32_t ao = (uint32_t)((a_row + mi * 16) * AG_S + ks * 16 + a_kadd) * 2u;
            ldsm_x4(dyn32 + OG_AXH * 2u + ao, AXh[mi]);
            ldsm_x4(dyn32 + OG_AXL * 2u + ao, AXl[mi]);
            ldsm_x4(dyn32 + OG_AYH * 2u + ao, AYh[mi]);
            ldsm_x4(dyn32 + OG_AYL * 2u + ao, AYl[mi]);
        }
        {
            uint32_t bo = (uint32_t)((b_k + ks * 16) * BF_S + b_n) * 2u;
            ldsm_x4_t(dyn32 + OG_BH * 2u + bo, Bh);
            ldsm_x4_t(dyn32 + OG_BL * 2u + bo, Bl);
        }
        #pragma unroll
        for (int mi = 0; mi < 2; mi++)
            #pragma unroll
            for (int nj = 0; nj < 2; nj++) {
                const int hf = nj * 2;
                mma_bf16(gX[mi][nj], AXh[mi], Bh[hf], Bh[hf + 1]);
                mma_bf16(gX[mi][nj], AXh[mi], Bl[hf], Bl[hf + 1]);
                mma_bf16(gX[mi][nj], AXl[mi], Bh[hf], Bh[hf + 1]);
                mma_bf16(gY[mi][nj], AYh[mi], Bh[hf], Bh[hf + 1]);
                mma_bf16(gY[mi][nj], AYh[mi], Bl[hf], Bl[hf + 1]);
                mma_bf16(gY[mi][nj], AYl[mi], Bh[hf], Bh[hf + 1]);
            }
    }

    const float RS = 0.03125f;
    float csum[4];
    #pragma unroll
    for (int i = 0; i < 4; i++) csum[i] = 0.0f;
    float qacc = 0.0f;

    #pragma unroll
    for (int mi = 0; mi < 2; mi++)
        #pragma unroll
        for (int nj = 0; nj < 2; nj++) {
            float vq[4];
            #pragma unroll
            for (int q = 0; q < 4; q++) {
                int rl = warp_m * 32 + mi * 16 + (lane >> 2) + (q >> 1) * 8;
                int cl = warp_n * 16 + nj * 8 + (lane & 3) * 2 + (q & 1);
                float Dgx = fmaxf(ngx[rl] + ngv[cl] - 2.0f * gX[mi][nj][q], 0.0f);
                float Dgy = fmaxf(ngy[rl] + ngv[cl] - 2.0f * gY[mi][nj][q], 0.0f);
                float KX = cstv * accX[mi][nj][q] * fexp2(-Dgx * is2);
                float KY = cstv * accY[mi][nj][q] * fexp2(-Dgy * is2);
                float v = (KX - KY) * RS;
                vq[q] = v;
                csum[nj * 2 + (q & 1)] += v;
                qacc += v * v;
            }
            int colg = jbase + warp_n * 16 + nj * 8 + (lane & 3) * 2;
            int row0 = ibase + warp_m * 32 + mi * 16 + (lane >> 2);
            *(float2*)&g_fm[(size_t)row0 * JC + colg]       = make_float2(vq[0], vq[1]);
            *(float2*)&g_fm[(size_t)(row0 + 8) * JC + colg] = make_float2(vq[2], vq[3]);
        }

    #pragma unroll
    for (int c4 = 0; c4 < 4; c4++) {
        int cl = warp_n * 16 + (c4 >> 1) * 8 + (lane & 3) * 2 + (c4 & 1);
        atomicAdd(&scs[cl], csum[c4]);
    }
    red[tid] = qacc;
    __syncthreads();
    for (int s = 256; s; s >>= 1) {
        if (tid < s) red[tid] += red[tid + s];
        __syncthreads();
    }
    if (tid == 0) atomicAdd(&g_scal[0], red[0]);
    if (tid < 128) atomicAdd(&g_colsum[jbase + tid], scs[tid]);
}

// ---------------- mu + sum(mu^2) ----------------------------------------------
__global__ void mu_kernel() {
    __shared__ float red[JC];
    int j = threadIdx.x;
    float m = g_colsum[j] * (1.0f / (float)NXC);
    g_mu[j] = m;
    red[j] = m * m;
    __syncthreads();
    for (int s = 512; s; s >>= 1) {
        if (j < s) red[j] += red[j + s];
        __syncthreads();
    }
    if (j == 0) g_scal[2] = red[0];
}

// ---------------- s_i = fm[i]·mu ; accumulate s_i^2 ---------------------------
__global__ __launch_bounds__(256) void s2_kernel() {
    __shared__ float smu[JC];
    int tid = threadIdx.x;
    for (int e = tid; e < JC; e += 256) smu[e] = g_mu[e];
    __syncthreads();
    int row  = blockIdx.x * 8 + (tid >> 5);
    int lane = tid & 31;
    float s = 0.0f;
    #pragma unroll 4
    for (int t = 0; t < 32; t++) {
        int c = lane + 32 * t;
        s += g_fm[(size_t)row * JC + c] * smu[c];
    }
    #pragma unroll
    for (int o = 16; o; o >>= 1) s += __shfl_xor_sync(0xffffffffu, s, o);
    if (lane == 0) atomicAdd(&g_scal[1], s * s);
}

// ---------------- finalize ------------------------------------------------------
__global__ void finalize_kernel(float* out) {
    double sumfm2 = (double)g_scal[0];
    double sums2  = (double)g_scal[1];
    double summu2 = (double)g_scal[2];
    double nx = (double)NXC;
    double t1 = summu2 * (nx / (nx - 1.0));
    double t2 = sumfm2 / nx / (nx - 1.0);
    double mean = t1 - t2;
    double var  = 4.0 * (sums2 / nx) - 4.0 * summu2 * summu2;
    out[0] = (float)(-(mean / sqrt(var + 1e-6)));
}

// ---------------- launch ---------------------------------------------------------
extern "C" void kernel_launch(void* const* d_in, const int* in_sizes, int n_in,
                              void* d_out, int out_size)
{
    const float* XY = (const float*)d_in[0];
    const float* V  = (const float*)d_in[1];
    const float *dnW[6], *dnb[6], *anW[6], *anb[6];
    for (int i = 0; i < 6; i++) {
        dnW[i] = (const float*)d_in[2 + 2 * i];
        dnb[i] = (const float*)d_in[3 + 2 * i];
        anW[i] = (const float*)d_in[14 + 2 * i];
        anb[i] = (const float*)d_in[15 + 2 * i];
    }
    const float* eps   = (const float*)d_in[26];
    const float* sig   = (const float*)d_in[27];
    const float* sig0  = (const float*)d_in[28];
    const float* cstp  = (const float*)d_in[29];

    float *in0, *nF, *nG;
    __nv_bfloat16 *inh, *inl, *h0, *l0, *h1, *l1, *b0h, *b0l, *b1h, *b1l;
    __nv_bfloat16 *Wh, *Wl, *Fh, *Fl, *Gh, *Gl;
    cudaGetSymbolAddress((void**)&in0, g_in0);
    cudaGetSymbolAddress((void**)&nF,  g_nF);
    cudaGetSymbolAddress((void**)&nG,  g_nG);
    cudaGetSymbolAddress((void**)&inh, g_inh);
    cudaGetSymbolAddress((void**)&inl, g_inl);
    cudaGetSymbolAddress((void**)&h0,  g_Ah0);
    cudaGetSymbolAddress((void**)&l0,  g_Al0);
    cudaGetSymbolAddress((void**)&h1,  g_Ah1);
    cudaGetSymbolAddress((void**)&l1,  g_Al1);
    cudaGetSymbolAddress((void**)&b0h, g_Bh0);
    cudaGetSymbolAddress((void**)&b0l, g_Bl0);
    cudaGetSymbolAddress((void**)&b1h, g_Bh1);
    cudaGetSymbolAddress((void**)&b1l, g_Bl1);
    cudaGetSymbolAddress((void**)&Wh,  g_Wh);
    cudaGetSymbolAddress((void**)&Wl,  g_Wl);
    cudaGetSymbolAddress((void**)&Fh,  g_Fh);
    cudaGetSymbolAddress((void**)&Fl,  g_Fl);
    cudaGetSymbolAddress((void**)&Gh,  g_Gh);
    cudaGetSymbolAddress((void**)&Gl,  g_Gl);

    const int GY = NTOT / BMM;     // 520
    const dim3 blk(128);

    concat_kernel<<<(NTOT * DIMC + 255) / 256, 256>>>(XY, V);
    concat_split_kernel<<<(NTOT * 32 + 255) / 256, 256>>>(XY, V);
    pad_zero_kernel<<<(NTOT * (PWH - HC) + 255) / 256, 256>>>();
    pad_fg_kernel<<<(NTOT * 12 + 255) / 256, 256>>>();
    init_acc_kernel<<<1, 1024>>>();

    WPrepArgs wa;
    for (int i = 0; i < 6; i++) {
        wa.W[i]     = dnW[i];  wa.W[i + 6] = anW[i];
        wa.Fi[i]    = (i == 0) ? DIMC : HC;
        wa.Fi[i+6]  = (i == 0) ? DIMC : HC;
        wa.Fo[i]    = (i == 5) ? FD : HC;
        wa.Fo[i+6]  = (i == 5) ? GD : HC;
    }
    prep_w_all<<<dim3((WOFF + 255) / 256, 12), 256>>>(wa);

    cudaFuncSetAttribute(mma_gemm4, cudaFuncAttributeMaxDynamicSharedMemorySize,
                         GEMM_SMEM_BYTES);
    const dim3 gH(5, GY, 2);
    const dim3 gL5(2, GY, 2);

    #define GEMM4(grid, AhD,AlD,AhA,AlA, PWa, L, bD,bA, FoD,FoA, ChD,ClD,ChA,ClA, PWcD,PWcA, resA, nC, relu) \
        mma_gemm4<<<grid, blk, GEMM_SMEM_BYTES>>>(AhD,AlD,AhA,AlA, PWa, Wh, Wl, L, \
            bD,bA, FoD,FoA, ChD,ClD,ChA,ClA, PWcD,PWcA, resA, nC, relu)

    GEMM4(gH, inh,inl, inh,inl, 32, 0, dnb[0],anb[0], HC,HC, h0,l0, b0h,b0l, PWH,PWH, (const float*)0, 1, 1);
    GEMM4(gH, h0,l0, b0h,b0l, PWH, 1, dnb[1],anb[1], HC,HC, h1,l1, b1h,b1l, PWH,PWH, (const float*)0, 10, 1);
    GEMM4(gH, h1,l1, b1h,b1l, PWH, 2, dnb[2],anb[2], HC,HC, h0,l0, b0h,b0l, PWH,PWH, (const float*)0, 10, 1);
    GEMM4(gH, h0,l0, b0h,b0l, PWH, 3, dnb[3],anb[3], HC,HC, h1,l1, b1h,b1l, PWH,PWH, (const float*)0, 10, 1);
    GEMM4(gH, h1,l1, b1h,b1l, PWH, 4, dnb[4],anb[4], HC,HC, h0,l0, b0h,b0l, PWH,PWH, (const float*)0, 10, 1);
    GEMM4(gL5, h0,l0, b0h,b0l, PWH, 5, dnb[5],anb[5], FD,GD, Fh,Fl, Gh,Gl, FDP,GDP, in0, 10, 0);

    transpose_v_kernel<<<(FDP * JC + 255) / 256, 256>>>();
    row_norms_hl<<<NTOT / 8, 256>>>(Fh, Fl, nF, FDP);
    row_norms_hl<<<NTOT / 8, 256>>>(Gh, Gl, nG, GDP);

    cudaFuncSetAttribute(fm2_kernel, cudaFuncAttributeMaxDynamicSharedMemorySize,
                         FM_DYN_BYTES);
    fm2_kernel<<<dim3(JC / FMJ, NXC / FMI), 512, FM_DYN_BYTES>>>(eps, sig, sig0, cstp);

    mu_kernel<<<1, JC>>>();
    s2_kernel<<<NXC / 8, 256>>>();
    finalize_kernel<<<1, 1>>>((float*)d_out);
}

// round 9
// speedup vs baseline: 1.0400x; 1.0400x over previous
#include <cuda_runtime.h>
#include <cuda_bf16.h>
#include <math.h>
#include <stdint.h>

// Problem constants
#define NXC   32768
#define NTOT  66560
#define DIMC  28
#define HC    300
#define FD    100
#define GD    28
#define JC    1024

#define PWH   320
#define FDP   112
#define GDP   32
#define WOFF  (320 * 320)

// ---------------- scratch ----------------------------------------------------
__device__ float g_in0 [(size_t)NTOT * DIMC];
__device__ __align__(16) __nv_bfloat16 g_inh[(size_t)NTOT * 32];
__device__ __align__(16) __nv_bfloat16 g_inl[(size_t)NTOT * 32];
__device__ __align__(16) __nv_bfloat16 g_Ah0[(size_t)NTOT * PWH];
__device__ __align__(16) __nv_bfloat16 g_Al0[(size_t)NTOT * PWH];
__device__ __align__(16) __nv_bfloat16 g_Ah1[(size_t)NTOT * PWH];
__device__ __align__(16) __nv_bfloat16 g_Al1[(size_t)NTOT * PWH];
__device__ __align__(16) __nv_bfloat16 g_Bh0[(size_t)NTOT * PWH];
__device__ __align__(16) __nv_bfloat16 g_Bl0[(size_t)NTOT * PWH];
__device__ __align__(16) __nv_bfloat16 g_Bh1[(size_t)NTOT * PWH];
__device__ __align__(16) __nv_bfloat16 g_Bl1[(size_t)NTOT * PWH];
__device__ __align__(16) __nv_bfloat16 g_Wh[12 * WOFF];
__device__ __align__(16) __nv_bfloat16 g_Wl[12 * WOFF];
__device__ __align__(16) __nv_bfloat16 g_Fh[(size_t)NTOT * FDP];
__device__ __align__(16) __nv_bfloat16 g_Fl[(size_t)NTOT * FDP];
__device__ __align__(16) __nv_bfloat16 g_Gh[(size_t)NTOT * GDP];
__device__ __align__(16) __nv_bfloat16 g_Gl[(size_t)NTOT * GDP];
__device__ __align__(16) __nv_bfloat16 g_FvTh[FDP * JC];
__device__ __align__(16) __nv_bfloat16 g_FvTl[FDP * JC];
__device__ __align__(16) __nv_bfloat16 g_GvTh[GDP * JC];
__device__ __align__(16) __nv_bfloat16 g_GvTl[GDP * JC];
__device__ float g_nF  [NTOT];
__device__ float g_nG  [NTOT];
__device__ __align__(16) __nv_bfloat16 g_fmb[(size_t)NXC * JC];   // bf16 fm (s2 only)
__device__ float g_colsum[JC];
__device__ float g_mu    [JC];
__device__ float g_scal  [8];

__device__ __forceinline__ void split2(float x, __nv_bfloat16& h, __nv_bfloat16& l) {
    h = __float2bfloat16(x);
    l = __float2bfloat16(x - __bfloat162float(h));
}
__device__ __forceinline__ float fexp2(float x) {
    float r;
    asm("ex2.approx.ftz.f32 %0, %1;" : "=f"(r) : "f"(x));
    return r;
}

// ---------------- prep kernels ----------------------------------------------
// concat + bf16 split fused
__global__ void prep_in_kernel(const float* __restrict__ XY, const float* __restrict__ V) {
    int t = blockIdx.x * blockDim.x + threadIdx.x;
    if (t >= NTOT * 32) return;
    int r = t >> 5, c = t & 31;
    float v = 0.0f;
    if (c < DIMC) {
        int idx = r * DIMC + c;
        v = (r < 2 * NXC) ? XY[idx] : V[(r - 2 * NXC) * DIMC + c];
        g_in0[idx] = v;
    }
    __nv_bfloat16 h, l; split2(v, h, l);
    g_inh[t] = h; g_inl[t] = l;
}
// all pad-zeroing fused (act k-pads + F/G pads)
__global__ void pad_all_kernel() {
    int t = blockIdx.x * blockDim.x + threadIdx.x;
    if (t >= NTOT * 20) return;
    int r = t / 20, c = t % 20;
    __nv_bfloat16 z = __float2bfloat16(0.0f);
    size_t o = (size_t)r * PWH + HC + c;
    g_Ah0[o] = z; g_Al0[o] = z; g_Ah1[o] = z; g_Al1[o] = z;
    g_Bh0[o] = z; g_Bl0[o] = z; g_Bh1[o] = z; g_Bl1[o] = z;
    if (c < 12) {
        size_t of = (size_t)r * FDP + 100 + c;
        g_Fh[of] = z; g_Fl[of] = z;
    }
    if (c < 4) {
        size_t og = (size_t)r * GDP + 28 + c;
        g_Gh[og] = z; g_Gl[og] = z;
    }
}
__global__ void init_acc_kernel() {
    int t = threadIdx.x;
    if (t < JC) g_colsum[t] = 0.0f;
    if (t < 8)  g_scal[t]   = 0.0f;
}
struct WPrepArgs {
    const float* W[12];
    int Fi[12];
    int Fo[12];
};
__global__ void prep_w_all(WPrepArgs a) {
    int layer = blockIdx.y;
    int idx = blockIdx.x * blockDim.x + threadIdx.x;
    if (idx >= WOFF) return;
    int k = idx / 320, n = idx - k * 320;
    int Fi = a.Fi[layer], Fo = a.Fo[layer];
    float v = (k < Fi && n < Fo) ? a.W[layer][(size_t)k * Fo + n] : 0.0f;
    __nv_bfloat16 h, l; split2(v, h, l);
    g_Wh[(size_t)layer * WOFF + idx] = h;
    g_Wl[(size_t)layer * WOFF + idx] = l;
}
__global__ void transpose_v_kernel() {
    int t = blockIdx.x * blockDim.x + threadIdx.x;
    if (t < FDP * JC) {
        int k = t >> 10, j = t & 1023;
        size_t src = (size_t)(2 * NXC + j) * FDP + k;
        g_FvTh[t] = g_Fh[src];
        g_FvTl[t] = g_Fl[src];
    }
    if (t < GDP * JC) {
        int k = t >> 10, j = t & 1023;
        size_t src = (size_t)(2 * NXC + j) * GDP + k;
        g_GvTh[t] = g_Gh[src];
        g_GvTl[t] = g_Gl[src];
    }
}

// =============== shared MMA helpers ==========================================
__device__ __forceinline__ uint32_t smem_u32(const void* p) {
    uint32_t a;
    asm("{ .reg .u64 t; cvta.to.shared.u64 t, %1; cvt.u32.u64 %0, t; }" : "=r"(a) : "l"(p));
    return a;
}
__device__ __forceinline__ void ldsm_x4(uint32_t addr, uint32_t r[4]) {
    asm volatile("ldmatrix.sync.aligned.m8n8.x4.shared.b16 {%0,%1,%2,%3}, [%4];"
        : "=r"(r[0]), "=r"(r[1]), "=r"(r[2]), "=r"(r[3]) : "r"(addr));
}
__device__ __forceinline__ void ldsm_x4_t(uint32_t addr, uint32_t r[4]) {
    asm volatile("ldmatrix.sync.aligned.m8n8.x4.trans.shared.b16 {%0,%1,%2,%3}, [%4];"
        : "=r"(r[0]), "=r"(r[1]), "=r"(r[2]), "=r"(r[3]) : "r"(addr));
}
__device__ __forceinline__ void mma_bf16(float c[4], const uint32_t a[4],
                                         uint32_t b0, uint32_t b1) {
    asm volatile(
        "mma.sync.aligned.m16n8k16.row.col.f32.bf16.bf16.f32 "
        "{%0,%1,%2,%3}, {%4,%5,%6,%7}, {%8,%9}, {%0,%1,%2,%3};"
        : "+f"(c[0]), "+f"(c[1]), "+f"(c[2]), "+f"(c[3])
        : "r"(a[0]), "r"(a[1]), "r"(a[2]), "r"(a[3]), "r"(b0), "r"(b1));
}
#define CP_ASYNC16(dst_u32, src_ptr) \
    asm volatile("cp.async.cg.shared.global [%0], [%1], 16;" \
        :: "r"(dst_u32), "l"(src_ptr) : "memory")
#define CP_COMMIT() asm volatile("cp.async.commit_group;" ::: "memory")
#define CP_WAIT(n)  asm volatile("cp.async.wait_group %0;" :: "n"(n) : "memory")

// =============== bf16-split GEMM (R7 config: 256 thr, 8 warps, 3-stage) ======
#define BMM 128
#define BNN 64
#define BKK 32
#define A_STRIDE 40
#define B_STRIDE 72
#define SM_AH 0
#define SM_AL 15360
#define SM_BH 30720
#define SM_BL 37632
#define GEMM_SMEM_BYTES 89088

__global__ __launch_bounds__(256, 2)
void mma_gemm3(const __nv_bfloat16* __restrict__ AhD, const __nv_bfloat16* __restrict__ AlD,
               const __nv_bfloat16* __restrict__ AhA, const __nv_bfloat16* __restrict__ AlA,
               int PWa,
               const __nv_bfloat16* __restrict__ WhB, const __nv_bfloat16* __restrict__ WlB,
               int layer,
               const float* __restrict__ biasD, const float* __restrict__ biasA,
               int FoD, int FoA,
               __nv_bfloat16* __restrict__ ChD, __nv_bfloat16* __restrict__ ClD,
               __nv_bfloat16* __restrict__ ChA, __nv_bfloat16* __restrict__ ClA,
               int PWcD, int PWcA,
               const float* __restrict__ resA,
               int nC, int doRelu)
{
    extern __shared__ __nv_bfloat16 dyn[];

    const int net = blockIdx.z;
    const __nv_bfloat16* Ah = net ? AhA : AhD;
    const __nv_bfloat16* Al = net ? AlA : AlD;
    const __nv_bfloat16* Wh = WhB + (size_t)(layer + 6 * net) * WOFF;
    const __nv_bfloat16* Wl = WlB + (size_t)(layer + 6 * net) * WOFF;
    const float* bias = net ? biasA : biasD;
    const int Fo  = net ? FoA : FoD;
    __nv_bfloat16* Ch = net ? ChA : ChD;
    __nv_bfloat16* Cl = net ? ClA : ClD;
    const int PWc = net ? PWcA : PWcD;
    const float* res = net ? resA : (const float*)0;

    const int n0 = blockIdx.x * BNN;
    if (n0 >= Fo) return;

    const int tid    = threadIdx.x;
    const int lane   = tid & 31;
    const int wid    = tid >> 5;
    const int warp_m = wid >> 1;
    const int warp_n = wid & 1;
    const int rbase  = blockIdx.y * BMM;

    const int a_row0 = tid >> 2;
    const int a_kk   = (tid & 3) * 8;
    const int bk     = tid >> 3;
    const int bn     = (tid & 7) * 8;

    const uint32_t dyn32 = smem_u32(dyn);
    const int a_row  = warp_m * 32 + (lane & 15);
    const int a_kadd = (lane >> 4) * 8;
    const uint32_t aHiB = dyn32 + (uint32_t)(SM_AH + a_row * A_STRIDE + a_kadd) * 2u;
    const uint32_t aLoB = dyn32 + (uint32_t)(SM_AL + a_row * A_STRIDE + a_kadd) * 2u;
    const int b_k = (lane & 7) + ((lane & 8) ? 8 : 0);
    const int b_n = warp_n * 32 + ((lane & 16) ? 8 : 0);
    const uint32_t bHiB = dyn32 + (uint32_t)(SM_BH + b_k * B_STRIDE + b_n) * 2u;
    const uint32_t bLoB = dyn32 + (uint32_t)(SM_BL + b_k * B_STRIDE + b_n) * 2u;

    const uint32_t dA0 = dyn32 + (uint32_t)(a_row0 * A_STRIDE + a_kk) * 2u;
    const uint32_t dB0 = dyn32 + (uint32_t)(SM_BH + bk * B_STRIDE + bn) * 2u;

    float acc[2][4][4];
    #pragma unroll
    for (int i = 0; i < 2; i++)
        #pragma unroll
        for (int j = 0; j < 4; j++)
            #pragma unroll
            for (int q = 0; q < 4; q++) acc[i][j][q] = 0.0f;

    #define ISSUE_CHUNK(k0, bf) do { \
        uint32_t od = (uint32_t)(bf) * 10240u; \
        uint32_t ob = (uint32_t)(bf) * 4608u; \
        size_t o0 = (size_t)(rbase + a_row0) * PWa + (k0) + a_kk; \
        size_t o1 = (size_t)(rbase + a_row0 + 64) * PWa + (k0) + a_kk; \
        uint32_t d1 = dA0 + od + (uint32_t)(64 * A_STRIDE) * 2u; \
        CP_ASYNC16(dA0 + od,           Ah + o0); \
        CP_ASYNC16(dA0 + od + 30720u,  Al + o0); \
        CP_ASYNC16(d1,                 Ah + o1); \
        CP_ASYNC16(d1 + 30720u,        Al + o1); \
        size_t bo = (size_t)((k0) + bk) * 320 + n0 + bn; \
        CP_ASYNC16(dB0 + ob,           Wh + bo); \
        CP_ASYNC16(dB0 + ob + 13824u,  Wl + bo); \
        CP_COMMIT(); \
    } while (0)

    ISSUE_CHUNK(0, 0);
    if (nC > 1) ISSUE_CHUNK(32, 1);

    for (int c = 0; c < nC; c++) {
        const int buf = c % 3;
        const uint32_t aOff = (uint32_t)buf * 10240u;
        const uint32_t bOff = (uint32_t)buf * 4608u;

        if (c + 2 < nC) { ISSUE_CHUNK((c + 2) * BKK, (c + 2) % 3); CP_WAIT(2); }
        else if (c + 1 < nC) { CP_WAIT(1); }
        else { CP_WAIT(0); }
        __syncthreads();

        #pragma unroll
        for (int ks = 0; ks < 2; ks++) {
            uint32_t Ahr[2][4], Alr[2][4], Bhr[2][4], Blr[2][4];
            #pragma unroll
            for (int mi = 0; mi < 2; mi++) {
                uint32_t off = aOff + (uint32_t)(mi * 16 * A_STRIDE + ks * 16) * 2u;
                ldsm_x4(aHiB + off, Ahr[mi]);
                ldsm_x4(aLoB + off, Alr[mi]);
            }
            #pragma unroll
            for (int np = 0; np < 2; np++) {
                uint32_t off = bOff + (uint32_t)(np * 16 + ks * 16 * B_STRIDE) * 2u;
                ldsm_x4_t(bHiB + off, Bhr[np]);
                ldsm_x4_t(bLoB + off, Blr[np]);
            }
            #pragma unroll
            for (int mi = 0; mi < 2; mi++)
                #pragma unroll
                for (int nj = 0; nj < 4; nj++) {
                    const int np = nj >> 1, hf = (nj & 1) * 2;
                    mma_bf16(acc[mi][nj], Ahr[mi], Bhr[np][hf], Bhr[np][hf + 1]);
                    mma_bf16(acc[mi][nj], Ahr[mi], Blr[np][hf], Blr[np][hf + 1]);
                    mma_bf16(acc[mi][nj], Alr[mi], Bhr[np][hf], Bhr[np][hf + 1]);
                }
        }
        __syncthreads();
    }
    #undef ISSUE_CHUNK

    // epilogue — writes bf16 hi/lo at stride PWc
    #pragma unroll
    for (int mi = 0; mi < 2; mi++)
        #pragma unroll
        for (int nj = 0; nj < 4; nj++) {
            int col = n0 + warp_n * 32 + nj * 8 + (lane & 3) * 2;
            if (col >= Fo) continue;
            float2 b2 = *(const float2*)(bias + col);
            #pragma unroll
            for (int half = 0; half < 2; half++) {
                int row = rbase + warp_m * 32 + mi * 16 + (lane >> 2) + half * 8;
                float vx = acc[mi][nj][half * 2 + 0] + b2.x;
                float vy = acc[mi][nj][half * 2 + 1] + b2.y;
                if (res) {
                    float2 r2 = *(const float2*)(res + (size_t)row * Fo + col);
                    vx += r2.x; vy += r2.y;
                }
                if (doRelu) { vx = fmaxf(vx, 0.0f); vy = fmaxf(vy, 0.0f); }
                __nv_bfloat16 hx, lx, hy, ly;
                split2(vx, hx, lx); split2(vy, hy, ly);
                *(__nv_bfloat162*)(Ch + (size_t)row * PWc + col) = __halves2bfloat162(hx, hy);
                *(__nv_bfloat162*)(Cl + (size_t)row * PWc + col) = __halves2bfloat162(lx, ly);
            }
        }
}

// ---------------- row squared norms from hi/lo bf16 --------------------------
__global__ void row_norms_hl(const __nv_bfloat16* __restrict__ H,
                             const __nv_bfloat16* __restrict__ L,
                             float* __restrict__ out, int D)
{
    int warp = (blockIdx.x * blockDim.x + threadIdx.x) >> 5;
    int lane = threadIdx.x & 31;
    if (warp >= NTOT) return;
    float s = 0.0f;
    for (int k = lane; k < D; k += 32) {
        size_t o = (size_t)warp * D + k;
        float v = __bfloat162float(H[o]) + __bfloat162float(L[o]);
        s += v * v;
    }
    #pragma unroll
    for (int o = 16; o; o >>= 1) s += __shfl_xor_sync(0xffffffffu, s, o);
    if (lane == 0) out[warp] = s;
}

// ---------------- fused fm kernel: 512 threads, 16 warps ---------------------
#define FMI 64
#define FMJ 128
#define AF_S 120
#define BF_S 136
#define AG_S 40
#define OF_AXH 0
#define OF_AXL 7680
#define OF_AYH 15360
#define OF_AYL 23040
#define OF_BH  30720
#define OF_BL  45952
#define OG_AXH 0
#define OG_AXL 2560
#define OG_AYH 5120
#define OG_AYL 7680
#define OG_BH  10240
#define OG_BL  14592
#define FM_DYN_BYTES (61184 * 2)

__global__ __launch_bounds__(512)
void fm2_kernel(const float* __restrict__ eps_p, const float* __restrict__ sig_p,
                const float* __restrict__ sig0_p, const float* __restrict__ cst_p)
{
    extern __shared__ __nv_bfloat16 dynb[];
    __shared__ float nfx[64], nfy[64], ngx[64], ngy[64];
    __shared__ float nfv[128], ngv[128];
    __shared__ float scs[128];
    __shared__ float red[512];

    const int tid    = threadIdx.x;
    const int lane   = tid & 31;
    const int wid    = tid >> 5;
    const int warp_m = wid >> 3;
    const int warp_n = wid & 7;
    const int ibase  = blockIdx.y * FMI;
    const int jbase  = blockIdx.x * FMJ;
    const int XR = ibase, YR = NXC + ibase, VR = 2 * NXC + jbase;

    if (tid < 64) {
        nfx[tid] = g_nF[XR + tid]; nfy[tid] = g_nF[YR + tid];
        ngx[tid] = g_nG[XR + tid]; ngy[tid] = g_nG[YR + tid];
    } else if (tid < 192) {
        int j = tid - 64;
        nfv[j] = g_nF[VR + j]; ngv[j] = g_nG[VR + j];
    } else if (tid < 320) {
        scs[tid - 192] = 0.0f;
    }

    for (int e = tid; e < 896; e += 512) {
        int r = e / 14, kv = (e % 14) * 8;
        *(uint4*)&dynb[OF_AXH + r * AF_S + kv] = *(const uint4*)&g_Fh[(size_t)(XR + r) * FDP + kv];
        *(uint4*)&dynb[OF_AXL + r * AF_S + kv] = *(const uint4*)&g_Fl[(size_t)(XR + r) * FDP + kv];
        *(uint4*)&dynb[OF_AYH + r * AF_S + kv] = *(const uint4*)&g_Fh[(size_t)(YR + r) * FDP + kv];
        *(uint4*)&dynb[OF_AYL + r * AF_S + kv] = *(const uint4*)&g_Fl[(size_t)(YR + r) * FDP + kv];
    }
    for (int e = tid; e < 1792; e += 512) {
        int k = e >> 4, jv = (e & 15) * 8;
        *(uint4*)&dynb[OF_BH + k * BF_S + jv] = *(const uint4*)&g_FvTh[k * 1024 + jbase + jv];
        *(uint4*)&dynb[OF_BL + k * BF_S + jv] = *(const uint4*)&g_FvTl[k * 1024 + jbase + jv];
    }
    __syncthreads();

    const uint32_t dyn32 = smem_u32(dynb);
    const int a_row  = warp_m * 32 + (lane & 15);
    const int a_kadd = (lane >> 4) * 8;
    const int b_k    = lane & 15;
    const int b_n    = warp_n * 16 + ((lane & 16) ? 8 : 0);

    float accX[2][2][4], accY[2][2][4];
    #pragma unroll
    for (int i = 0; i < 2; i++)
        #pragma unroll
        for (int j = 0; j < 2; j++)
            #pragma unroll
            for (int q = 0; q < 4; q++) { accX[i][j][q] = 0.0f; accY[i][j][q] = 0.0f; }

    #pragma unroll
    for (int ks = 0; ks < 7; ks++) {
        uint32_t AXh[2][4], AXl[2][4], AYh[2][4], AYl[2][4], Bh[4], Bl[4];
        #pragma unroll
        for (int mi = 0; mi < 2; mi++) {
            uint32_t ao = (uint32_t)((a_row + mi * 16) * AF_S + ks * 16 + a_kadd) * 2u;
            ldsm_x4(dyn32 + OF_AXH * 2u + ao, AXh[mi]);
            ldsm_x4(dyn32 + OF_AXL * 2u + ao, AXl[mi]);
            ldsm_x4(dyn32 + OF_AYH * 2u + ao, AYh[mi]);
            ldsm_x4(dyn32 + OF_AYL * 2u + ao, AYl[mi]);
        }
        {
            uint32_t bo = (uint32_t)((b_k + ks * 16) * BF_S + b_n) * 2u;
            ldsm_x4_t(dyn32 + OF_BH * 2u + bo, Bh);
            ldsm_x4_t(dyn32 + OF_BL * 2u + bo, Bl);
        }
        #pragma unroll
        for (int mi = 0; mi < 2; mi++)
            #pragma unroll
            for (int nj = 0; nj < 2; nj++) {
                const int hf = nj * 2;
                mma_bf16(accX[mi][nj], AXh[mi], Bh[hf], Bh[hf + 1]);
                mma_bf16(accX[mi][nj], AXh[mi], Bl[hf], Bl[hf + 1]);
                mma_bf16(accX[mi][nj], AXl[mi], Bh[hf], Bh[hf + 1]);
                mma_bf16(accY[mi][nj], AYh[mi], Bh[hf], Bh[hf + 1]);
                mma_bf16(accY[mi][nj], AYh[mi], Bl[hf], Bl[hf + 1]);
                mma_bf16(accY[mi][nj], AYl[mi], Bh[hf], Bh[hf + 1]);
            }
    }

    const float LOG2E  = 1.4426950408889634f;
    const float ep     = 1.0f / (1.0f + __expf(-eps_p[0]));
    const float is2    = LOG2E / (sig_p[0]  * sig_p[0]);
    const float is0    = LOG2E / (sig0_p[0] * sig0_p[0]);
    const float cstv   = cst_p[0];
    const float one_ep = 1.0f - ep;

    #pragma unroll
    for (int mi = 0; mi < 2; mi++)
        #pragma unroll
        for (int nj = 0; nj < 2; nj++)
            #pragma unroll
            for (int q = 0; q < 4; q++) {
                int rl = warp_m * 32 + mi * 16 + (lane >> 2) + (q >> 1) * 8;
                int cl = warp_n * 16 + nj * 8 + (lane & 3) * 2 + (q & 1);
                float Dx = fmaxf(nfx[rl] + nfv[cl] - 2.0f * accX[mi][nj][q], 0.0f);
                float Dy = fmaxf(nfy[rl] + nfv[cl] - 2.0f * accY[mi][nj][q], 0.0f);
                accX[mi][nj][q] = fmaf(one_ep, fexp2(-Dx * is0), ep);
                accY[mi][nj][q] = fmaf(one_ep, fexp2(-Dy * is0), ep);
            }

    __syncthreads();
    if (tid < 256) {
        int r = tid >> 2, kv = (tid & 3) * 8;
        *(uint4*)&dynb[OG_AXH + r * AG_S + kv] = *(const uint4*)&g_Gh[(size_t)(XR + r) * GDP + kv];
        *(uint4*)&dynb[OG_AXL + r * AG_S + kv] = *(const uint4*)&g_Gl[(size_t)(XR + r) * GDP + kv];
        *(uint4*)&dynb[OG_AYH + r * AG_S + kv] = *(const uint4*)&g_Gh[(size_t)(YR + r) * GDP + kv];
        *(uint4*)&dynb[OG_AYL + r * AG_S + kv] = *(const uint4*)&g_Gl[(size_t)(YR + r) * GDP + kv];
    }
    {
        int k = tid >> 4, jv = (tid & 15) * 8;
        *(uint4*)&dynb[OG_BH + k * BF_S + jv] = *(const uint4*)&g_GvTh[k * 1024 + jbase + jv];
        *(uint4*)&dynb[OG_BL + k * BF_S + jv] = *(const uint4*)&g_GvTl[k * 1024 + jbase + jv];
    }
    __syncthreads();

    float gX[2][2][4], gY[2][2][4];
    #pragma unroll
    for (int i = 0; i < 2; i++)
        #pragma unroll
        for (int j = 0; j < 2; j++)
            #pragma unroll
            for (int q = 0; q < 4; q++) { gX[i][j][q] = 0.0f; gY[i][j][q] = 0.0f; }

    #pragma unroll
    for (int ks = 0; ks < 2; ks++) {
        uint32_t AXh[2][4], AXl[2][4], AYh[2][4], AYl[2][4], Bh[4], Bl[4];
        #pragma unroll
        for (int mi = 0; mi < 2; mi++) {
            uint32_t ao = (uint32_t)((a_row + mi * 16) * AG_S + ks * 16 + a_kadd) * 2u;
            ldsm_x4(dyn32 + OG_AXH * 2u + ao, AXh[mi]);
            ldsm_x4(dyn32 + OG_AXL * 2u + ao, AXl[mi]);
            ldsm_x4(dyn32 + OG_AYH * 2u + ao, AYh[mi]);
            ldsm_x4(dyn32 + OG_AYL * 2u + ao, AYl[mi]);
        }
        {
            uint32_t bo = (uint32_t)((b_k + ks * 16) * BF_S + b_n) * 2u;
            ldsm_x4_t(dyn32 + OG_BH * 2u + bo, Bh);
            ldsm_x4_t(dyn32 + OG_BL * 2u + bo, Bl);
        }
        #pragma unroll
        for (int mi = 0; mi < 2; mi++)
            #pragma unroll
            for (int nj = 0; nj < 2; nj++) {
                const int hf = nj * 2;
                mma_bf16(gX[mi][nj], AXh[mi], Bh[hf], Bh[hf + 1]);
                mma_bf16(gX[mi][nj], AXh[mi], Bl[hf], Bl[hf + 1]);
                mma_bf16(gX[mi][nj], AXl[mi], Bh[hf], Bh[hf + 1]);
                mma_bf16(gY[mi][nj], AYh[mi], Bh[hf], Bh[hf + 1]);
                mma_bf16(gY[mi][nj], AYh[mi], Bl[hf], Bl[hf + 1]);
                mma_bf16(gY[mi][nj], AYl[mi], Bh[hf], Bh[hf + 1]);
            }
    }

    const float RS = 0.03125f;
    float csum[4];
    #pragma unroll
    for (int i = 0; i < 4; i++) csum[i] = 0.0f;
    float qacc = 0.0f;

    #pragma unroll
    for (int mi = 0; mi < 2; mi++)
        #pragma unroll
        for (int nj = 0; nj < 2; nj++) {
            float vq[4];
            #pragma unroll
            for (int q = 0; q < 4; q++) {
                int rl = warp_m * 32 + mi * 16 + (lane >> 2) + (q >> 1) * 8;
                int cl = warp_n * 16 + nj * 8 + (lane & 3) * 2 + (q & 1);
                float Dgx = fmaxf(ngx[rl] + ngv[cl] - 2.0f * gX[mi][nj][q], 0.0f);
                float Dgy = fmaxf(ngy[rl] + ngv[cl] - 2.0f * gY[mi][nj][q], 0.0f);
                float KX = cstv * accX[mi][nj][q] * fexp2(-Dgx * is2);
                float KY = cstv * accY[mi][nj][q] * fexp2(-Dgy * is2);
                float v = (KX - KY) * RS;
                vq[q] = v;
                csum[nj * 2 + (q & 1)] += v;
                qacc += v * v;
            }
            int colg = jbase + warp_n * 16 + nj * 8 + (lane & 3) * 2;
            int row0 = ibase + warp_m * 32 + mi * 16 + (lane >> 2);
            *(__nv_bfloat162*)&g_fmb[(size_t)row0 * JC + colg] =
                __floats2bfloat162_rn(vq[0], vq[1]);
            *(__nv_bfloat162*)&g_fmb[(size_t)(row0 + 8) * JC + colg] =
                __floats2bfloat162_rn(vq[2], vq[3]);
        }

    #pragma unroll
    for (int c4 = 0; c4 < 4; c4++) {
        int cl = warp_n * 16 + (c4 >> 1) * 8 + (lane & 3) * 2 + (c4 & 1);
        atomicAdd(&scs[cl], csum[c4]);
    }
    red[tid] = qacc;
    __syncthreads();
    for (int s = 256; s; s >>= 1) {
        if (tid < s) red[tid] += red[tid + s];
        __syncthreads();
    }
    if (tid == 0) atomicAdd(&g_scal[0], red[0]);
    if (tid < 128) atomicAdd(&g_colsum[jbase + tid], scs[tid]);
}

// ---------------- mu + sum(mu^2) ----------------------------------------------
__global__ void mu_kernel() {
    __shared__ float red[JC];
    int j = threadIdx.x;
    float m = g_colsum[j] * (1.0f / (float)NXC);
    g_mu[j] = m;
    red[j] = m * m;
    __syncthreads();
    for (int s = 512; s; s >>= 1) {
        if (j < s) red[j] += red[j + s];
        __syncthreads();
    }
    if (j == 0) g_scal[2] = red[0];
}

// ---------------- s_i = fm[i]·mu (bf16 fm) ; accumulate s_i^2 -----------------
__global__ __launch_bounds__(256) void s2_kernel() {
    __shared__ float smu[JC];
    int tid = threadIdx.x;
    for (int e = tid; e < JC; e += 256) smu[e] = g_mu[e];
    __syncthreads();
    int row  = blockIdx.x * 8 + (tid >> 5);
    int lane = tid & 31;
    const __nv_bfloat16* rp = g_fmb + (size_t)row * JC;
    float s = 0.0f;
    #pragma unroll
    for (int t = 0; t < 4; t++) {
        int c = lane * 8 + 256 * t;
        uint4 v = *(const uint4*)(rp + c);
        const __nv_bfloat16* pv = (const __nv_bfloat16*)&v;
        #pragma unroll
        for (int e = 0; e < 8; e++)
            s += __bfloat162float(pv[e]) * smu[c + e];
    }
    #pragma unroll
    for (int o = 16; o; o >>= 1) s += __shfl_xor_sync(0xffffffffu, s, o);
    if (lane == 0) atomicAdd(&g_scal[1], s * s);
}

// ---------------- finalize ------------------------------------------------------
__global__ void finalize_kernel(float* out) {
    double sumfm2 = (double)g_scal[0];
    double sums2  = (double)g_scal[1];
    double summu2 = (double)g_scal[2];
    double nx = (double)NXC;
    double t1 = summu2 * (nx / (nx - 1.0));
    double t2 = sumfm2 / nx / (nx - 1.0);
    double mean = t1 - t2;
    double var  = 4.0 * (sums2 / nx) - 4.0 * summu2 * summu2;
    out[0] = (float)(-(mean / sqrt(var + 1e-6)));
}

// ---------------- launch ---------------------------------------------------------
extern "C" void kernel_launch(void* const* d_in, const int* in_sizes, int n_in,
                              void* d_out, int out_size)
{
    const float* XY = (const float*)d_in[0];
    const float* V  = (const float*)d_in[1];
    const float *dnW[6], *dnb[6], *anW[6], *anb[6];
    for (int i = 0; i < 6; i++) {
        dnW[i] = (const float*)d_in[2 + 2 * i];
        dnb[i] = (const float*)d_in[3 + 2 * i];
        anW[i] = (const float*)d_in[14 + 2 * i];
        anb[i] = (const float*)d_in[15 + 2 * i];
    }
    const float* eps   = (const float*)d_in[26];
    const float* sig   = (const float*)d_in[27];
    const float* sig0  = (const float*)d_in[28];
    const float* cstp  = (const float*)d_in[29];

    float *in0, *nF, *nG;
    __nv_bfloat16 *inh, *inl, *h0, *l0, *h1, *l1, *b0h, *b0l, *b1h, *b1l;
    __nv_bfloat16 *Wh, *Wl, *Fh, *Fl, *Gh, *Gl;
    cudaGetSymbolAddress((void**)&in0, g_in0);
    cudaGetSymbolAddress((void**)&nF,  g_nF);
    cudaGetSymbolAddress((void**)&nG,  g_nG);
    cudaGetSymbolAddress((void**)&inh, g_inh);
    cudaGetSymbolAddress((void**)&inl, g_inl);
    cudaGetSymbolAddress((void**)&h0,  g_Ah0);
    cudaGetSymbolAddress((void**)&l0,  g_Al0);
    cudaGetSymbolAddress((void**)&h1,  g_Ah1);
    cudaGetSymbolAddress((void**)&l1,  g_Al1);
    cudaGetSymbolAddress((void**)&b0h, g_Bh0);
    cudaGetSymbolAddress((void**)&b0l, g_Bl0);
    cudaGetSymbolAddress((void**)&b1h, g_Bh1);
    cudaGetSymbolAddress((void**)&b1l, g_Bl1);
    cudaGetSymbolAddress((void**)&Wh,  g_Wh);
    cudaGetSymbolAddress((void**)&Wl,  g_Wl);
    cudaGetSymbolAddress((void**)&Fh,  g_Fh);
    cudaGetSymbolAddress((void**)&Fl,  g_Fl);
    cudaGetSymbolAddress((void**)&Gh,  g_Gh);
    cudaGetSymbolAddress((void**)&Gl,  g_Gl);

    const int GY = NTOT / BMM;     // 520
    const dim3 blk(256);

    prep_in_kernel<<<(NTOT * 32 + 255) / 256, 256>>>(XY, V);
    pad_all_kernel<<<(NTOT * 20 + 255) / 256, 256>>>();
    init_acc_kernel<<<1, 1024>>>();

    WPrepArgs wa;
    for (int i = 0; i < 6; i++) {
        wa.W[i]     = dnW[i];  wa.W[i + 6] = anW[i];
        wa.Fi[i]    = (i == 0) ? DIMC : HC;
        wa.Fi[i+6]  = (i == 0) ? DIMC : HC;
        wa.Fo[i]    = (i == 5) ? FD : HC;
        wa.Fo[i+6]  = (i == 5) ? GD : HC;
    }
    prep_w_all<<<dim3((WOFF + 255) / 256, 12), 256>>>(wa);

    cudaFuncSetAttribute(mma_gemm3, cudaFuncAttributeMaxDynamicSharedMemorySize,
                         GEMM_SMEM_BYTES);
    const dim3 gH(5, GY, 2);
    const dim3 gL5(2, GY, 2);

    #define GEMM3(grid, AhD,AlD,AhA,AlA, PWa, L, bD,bA, FoD,FoA, ChD,ClD,ChA,ClA, PWcD,PWcA, resA, nC, relu) \
        mma_gemm3<<<grid, blk, GEMM_SMEM_BYTES>>>(AhD,AlD,AhA,AlA, PWa, Wh, Wl, L, \
            bD,bA, FoD,FoA, ChD,ClD,ChA,ClA, PWcD,PWcA, resA, nC, relu)

    GEMM3(gH, inh,inl, inh,inl, 32, 0, dnb[0],anb[0], HC,HC, h0,l0, b0h,b0l, PWH,PWH, (const float*)0, 1, 1);
    GEMM3(gH, h0,l0, b0h,b0l, PWH, 1, dnb[1],anb[1], HC,HC, h1,l1, b1h,b1l, PWH,PWH, (const float*)0, 10, 1);
    GEMM3(gH, h1,l1, b1h,b1l, PWH, 2, dnb[2],anb[2], HC,HC, h0,l0, b0h,b0l, PWH,PWH, (const float*)0, 10, 1);
    GEMM3(gH, h0,l0, b0h,b0l, PWH, 3, dnb[3],anb[3], HC,HC, h1,l1, b1h,b1l, PWH,PWH, (const float*)0, 10, 1);
    GEMM3(gH, h1,l1, b1h,b1l, PWH, 4, dnb[4],anb[4], HC,HC, h0,l0, b0h,b0l, PWH,PWH, (const float*)0, 10, 1);
    GEMM3(gL5, h0,l0, b0h,b0l, PWH, 5, dnb[5],anb[5], FD,GD, Fh,Fl, Gh,Gl, FDP,GDP, in0, 10, 0);

    transpose_v_kernel<<<(FDP * JC + 255) / 256, 256>>>();
    row_norms_hl<<<NTOT / 8, 256>>>(Fh, Fl, nF, FDP);
    row_norms_hl<<<NTOT / 8, 256>>>(Gh, Gl, nG, GDP);

    cudaFuncSetAttribute(fm2_kernel, cudaFuncAttributeMaxDynamicSharedMemorySize,
                         FM_DYN_BYTES);
    fm2_kernel<<<dim3(JC / FMJ, NXC / FMI), 512, FM_DYN_BYTES>>>(eps, sig, sig0, cstp);

    mu_kernel<<<1, JC>>>();
    s2_kernel<<<NXC / 8, 256>>>();
    finalize_kernel<<<1, 1>>>((float*)d_out);
}

// round 10
// speedup vs baseline: 1.0856x; 1.0439x over previous
#include <cuda_runtime.h>
#include <cuda_bf16.h>
#include <math.h>
#include <stdint.h>

// Problem constants
#define NXC   32768
#define NTOT  66560
#define DIMC  28
#define HC    300
#define FD    100
#define GD    28
#define JC    1024

#define PWH   320
#define FDP   112
#define GDP   32
#define WOFF  (320 * 320)

// ---------------- scratch ----------------------------------------------------
__device__ float g_in0 [(size_t)NTOT * DIMC];
__device__ __align__(16) __nv_bfloat16 g_inh[(size_t)NTOT * 32];
__device__ __align__(16) __nv_bfloat16 g_inl[(size_t)NTOT * 32];
__device__ __align__(16) __nv_bfloat16 g_Ah0[(size_t)NTOT * PWH];
__device__ __align__(16) __nv_bfloat16 g_Al0[(size_t)NTOT * PWH];
__device__ __align__(16) __nv_bfloat16 g_Ah1[(size_t)NTOT * PWH];
__device__ __align__(16) __nv_bfloat16 g_Al1[(size_t)NTOT * PWH];
__device__ __align__(16) __nv_bfloat16 g_Bh0[(size_t)NTOT * PWH];
__device__ __align__(16) __nv_bfloat16 g_Bl0[(size_t)NTOT * PWH];
__device__ __align__(16) __nv_bfloat16 g_Bh1[(size_t)NTOT * PWH];
__device__ __align__(16) __nv_bfloat16 g_Bl1[(size_t)NTOT * PWH];
__device__ __align__(16) __nv_bfloat16 g_Wh[12 * WOFF];
__device__ __align__(16) __nv_bfloat16 g_Wl[12 * WOFF];
__device__ __align__(16) __nv_bfloat16 g_Fh[(size_t)NTOT * FDP];
__device__ __align__(16) __nv_bfloat16 g_Fl[(size_t)NTOT * FDP];
__device__ __align__(16) __nv_bfloat16 g_Gh[(size_t)NTOT * GDP];
__device__ __align__(16) __nv_bfloat16 g_Gl[(size_t)NTOT * GDP];
__device__ __align__(16) __nv_bfloat16 g_FvTh[FDP * JC];
__device__ __align__(16) __nv_bfloat16 g_FvTl[FDP * JC];
__device__ __align__(16) __nv_bfloat16 g_GvTh[GDP * JC];
__device__ __align__(16) __nv_bfloat16 g_GvTl[GDP * JC];
__device__ float g_nF  [NTOT];
__device__ float g_nG  [NTOT];
__device__ __align__(16) __nv_bfloat16 g_fmb[(size_t)NXC * JC];   // bf16 fm (s2 only)
__device__ float g_colsum[JC];
__device__ float g_mu    [JC];
__device__ float g_scal  [8];

__device__ __forceinline__ void split2(float x, __nv_bfloat16& h, __nv_bfloat16& l) {
    h = __float2bfloat16(x);
    l = __float2bfloat16(x - __bfloat162float(h));
}
__device__ __forceinline__ float fexp2(float x) {
    float r;
    asm("ex2.approx.ftz.f32 %0, %1;" : "=f"(r) : "f"(x));
    return r;
}

// ---------------- prep kernels ----------------------------------------------
__global__ void prep_in_kernel(const float* __restrict__ XY, const float* __restrict__ V) {
    int t = blockIdx.x * blockDim.x + threadIdx.x;
    if (t >= NTOT * 32) return;
    int r = t >> 5, c = t & 31;
    float v = 0.0f;
    if (c < DIMC) {
        int idx = r * DIMC + c;
        v = (r < 2 * NXC) ? XY[idx] : V[(r - 2 * NXC) * DIMC + c];
        g_in0[idx] = v;
    }
    __nv_bfloat16 h, l; split2(v, h, l);
    g_inh[t] = h; g_inl[t] = l;
}
__global__ void pad_all_kernel() {
    int t = blockIdx.x * blockDim.x + threadIdx.x;
    if (t >= NTOT * 20) return;
    int r = t / 20, c = t % 20;
    __nv_bfloat16 z = __float2bfloat16(0.0f);
    size_t o = (size_t)r * PWH + HC + c;
    g_Ah0[o] = z; g_Al0[o] = z; g_Ah1[o] = z; g_Al1[o] = z;
    g_Bh0[o] = z; g_Bl0[o] = z; g_Bh1[o] = z; g_Bl1[o] = z;
    if (c < 12) {
        size_t of = (size_t)r * FDP + 100 + c;
        g_Fh[of] = z; g_Fl[of] = z;
    }
    if (c < 4) {
        size_t og = (size_t)r * GDP + 28 + c;
        g_Gh[og] = z; g_Gl[og] = z;
    }
}
__global__ void init_acc_kernel() {
    int t = threadIdx.x;
    if (t < JC) g_colsum[t] = 0.0f;
    if (t < 8)  g_scal[t]   = 0.0f;
}
struct WPrepArgs {
    const float* W[12];
    int Fi[12];
    int Fo[12];
};
__global__ void prep_w_all(WPrepArgs a) {
    int layer = blockIdx.y;
    int idx = blockIdx.x * blockDim.x + threadIdx.x;
    if (idx >= WOFF) return;
    int k = idx / 320, n = idx - k * 320;
    int Fi = a.Fi[layer], Fo = a.Fo[layer];
    float v = (k < Fi && n < Fo) ? a.W[layer][(size_t)k * Fo + n] : 0.0f;
    __nv_bfloat16 h, l; split2(v, h, l);
    g_Wh[(size_t)layer * WOFF + idx] = h;
    g_Wl[(size_t)layer * WOFF + idx] = l;
}
__global__ void transpose_v_kernel() {
    int t = blockIdx.x * blockDim.x + threadIdx.x;
    if (t < FDP * JC) {
        int k = t >> 10, j = t & 1023;
        size_t src = (size_t)(2 * NXC + j) * FDP + k;
        g_FvTh[t] = g_Fh[src];
        g_FvTl[t] = g_Fl[src];
    }
    if (t < GDP * JC) {
        int k = t >> 10, j = t & 1023;
        size_t src = (size_t)(2 * NXC + j) * GDP + k;
        g_GvTh[t] = g_Gh[src];
        g_GvTl[t] = g_Gl[src];
    }
}

// =============== shared MMA helpers ==========================================
__device__ __forceinline__ uint32_t smem_u32(const void* p) {
    uint32_t a;
    asm("{ .reg .u64 t; cvta.to.shared.u64 t, %1; cvt.u32.u64 %0, t; }" : "=r"(a) : "l"(p));
    return a;
}
__device__ __forceinline__ void ldsm_x4(uint32_t addr, uint32_t r[4]) {
    asm volatile("ldmatrix.sync.aligned.m8n8.x4.shared.b16 {%0,%1,%2,%3}, [%4];"
        : "=r"(r[0]), "=r"(r[1]), "=r"(r[2]), "=r"(r[3]) : "r"(addr));
}
__device__ __forceinline__ void ldsm_x4_t(uint32_t addr, uint32_t r[4]) {
    asm volatile("ldmatrix.sync.aligned.m8n8.x4.trans.shared.b16 {%0,%1,%2,%3}, [%4];"
        : "=r"(r[0]), "=r"(r[1]), "=r"(r[2]), "=r"(r[3]) : "r"(addr));
}
__device__ __forceinline__ void mma_bf16(float c[4], const uint32_t a[4],
                                         uint32_t b0, uint32_t b1) {
    asm volatile(
        "mma.sync.aligned.m16n8k16.row.col.f32.bf16.bf16.f32 "
        "{%0,%1,%2,%3}, {%4,%5,%6,%7}, {%8,%9}, {%0,%1,%2,%3};"
        : "+f"(c[0]), "+f"(c[1]), "+f"(c[2]), "+f"(c[3])
        : "r"(a[0]), "r"(a[1]), "r"(a[2]), "r"(a[3]), "r"(b0), "r"(b1));
}
#define CP_ASYNC16(dst_u32, src_ptr) \
    asm volatile("cp.async.cg.shared.global [%0], [%1], 16;" \
        :: "r"(dst_u32), "l"(src_ptr) : "memory")
#define CP_COMMIT() asm volatile("cp.async.commit_group;" ::: "memory")
#define CP_WAIT(n)  asm volatile("cp.async.wait_group %0;" :: "n"(n) : "memory")

// =============== bf16-split GEMM (R7 config: 256 thr, 8 warps, 3-stage) ======
#define BMM 128
#define BNN 64
#define BKK 32
#define A_STRIDE 40
#define B_STRIDE 72
#define SM_AH 0
#define SM_AL 15360
#define SM_BH 30720
#define SM_BL 37632
#define GEMM_SMEM_BYTES 89088

__global__ __launch_bounds__(256, 2)
void mma_gemm3(const __nv_bfloat16* __restrict__ AhD, const __nv_bfloat16* __restrict__ AlD,
               const __nv_bfloat16* __restrict__ AhA, const __nv_bfloat16* __restrict__ AlA,
               int PWa,
               const __nv_bfloat16* __restrict__ WhB, const __nv_bfloat16* __restrict__ WlB,
               int layer,
               const float* __restrict__ biasD, const float* __restrict__ biasA,
               int FoD, int FoA,
               __nv_bfloat16* __restrict__ ChD, __nv_bfloat16* __restrict__ ClD,
               __nv_bfloat16* __restrict__ ChA, __nv_bfloat16* __restrict__ ClA,
               int PWcD, int PWcA,
               const float* __restrict__ resA,
               int nC, int doRelu)
{
    extern __shared__ __nv_bfloat16 dyn[];

    const int net = blockIdx.z;
    const __nv_bfloat16* Ah = net ? AhA : AhD;
    const __nv_bfloat16* Al = net ? AlA : AlD;
    const __nv_bfloat16* Wh = WhB + (size_t)(layer + 6 * net) * WOFF;
    const __nv_bfloat16* Wl = WlB + (size_t)(layer + 6 * net) * WOFF;
    const float* bias = net ? biasA : biasD;
    const int Fo  = net ? FoA : FoD;
    __nv_bfloat16* Ch = net ? ChA : ChD;
    __nv_bfloat16* Cl = net ? ClA : ClD;
    const int PWc = net ? PWcA : PWcD;
    const float* res = net ? resA : (const float*)0;

    const int n0 = blockIdx.x * BNN;
    if (n0 >= Fo) return;

    const int tid    = threadIdx.x;
    const int lane   = tid & 31;
    const int wid    = tid >> 5;
    const int warp_m = wid >> 1;
    const int warp_n = wid & 1;
    const int rbase  = blockIdx.y * BMM;

    const int a_row0 = tid >> 2;
    const int a_kk   = (tid & 3) * 8;
    const int bk     = tid >> 3;
    const int bn     = (tid & 7) * 8;

    const uint32_t dyn32 = smem_u32(dyn);
    const int a_row  = warp_m * 32 + (lane & 15);
    const int a_kadd = (lane >> 4) * 8;
    const uint32_t aHiB = dyn32 + (uint32_t)(SM_AH + a_row * A_STRIDE + a_kadd) * 2u;
    const uint32_t aLoB = dyn32 + (uint32_t)(SM_AL + a_row * A_STRIDE + a_kadd) * 2u;
    const int b_k = (lane & 7) + ((lane & 8) ? 8 : 0);
    const int b_n = warp_n * 32 + ((lane & 16) ? 8 : 0);
    const uint32_t bHiB = dyn32 + (uint32_t)(SM_BH + b_k * B_STRIDE + b_n) * 2u;
    const uint32_t bLoB = dyn32 + (uint32_t)(SM_BL + b_k * B_STRIDE + b_n) * 2u;

    const uint32_t dA0 = dyn32 + (uint32_t)(a_row0 * A_STRIDE + a_kk) * 2u;
    const uint32_t dB0 = dyn32 + (uint32_t)(SM_BH + bk * B_STRIDE + bn) * 2u;

    float acc[2][4][4];
    #pragma unroll
    for (int i = 0; i < 2; i++)
        #pragma unroll
        for (int j = 0; j < 4; j++)
            #pragma unroll
            for (int q = 0; q < 4; q++) acc[i][j][q] = 0.0f;

    #define ISSUE_CHUNK(k0, bf) do { \
        uint32_t od = (uint32_t)(bf) * 10240u; \
        uint32_t ob = (uint32_t)(bf) * 4608u; \
        size_t o0 = (size_t)(rbase + a_row0) * PWa + (k0) + a_kk; \
        size_t o1 = (size_t)(rbase + a_row0 + 64) * PWa + (k0) + a_kk; \
        uint32_t d1 = dA0 + od + (uint32_t)(64 * A_STRIDE) * 2u; \
        CP_ASYNC16(dA0 + od,           Ah + o0); \
        CP_ASYNC16(dA0 + od + 30720u,  Al + o0); \
        CP_ASYNC16(d1,                 Ah + o1); \
        CP_ASYNC16(d1 + 30720u,        Al + o1); \
        size_t bo = (size_t)((k0) + bk) * 320 + n0 + bn; \
        CP_ASYNC16(dB0 + ob,           Wh + bo); \
        CP_ASYNC16(dB0 + ob + 13824u,  Wl + bo); \
        CP_COMMIT(); \
    } while (0)

    ISSUE_CHUNK(0, 0);
    if (nC > 1) ISSUE_CHUNK(32, 1);

    for (int c = 0; c < nC; c++) {
        const int buf = c % 3;
        const uint32_t aOff = (uint32_t)buf * 10240u;
        const uint32_t bOff = (uint32_t)buf * 4608u;

        if (c + 2 < nC) { ISSUE_CHUNK((c + 2) * BKK, (c + 2) % 3); CP_WAIT(2); }
        else if (c + 1 < nC) { CP_WAIT(1); }
        else { CP_WAIT(0); }
        __syncthreads();

        #pragma unroll
        for (int ks = 0; ks < 2; ks++) {
            uint32_t Ahr[2][4], Alr[2][4], Bhr[2][4], Blr[2][4];
            #pragma unroll
            for (int mi = 0; mi < 2; mi++) {
                uint32_t off = aOff + (uint32_t)(mi * 16 * A_STRIDE + ks * 16) * 2u;
                ldsm_x4(aHiB + off, Ahr[mi]);
                ldsm_x4(aLoB + off, Alr[mi]);
            }
            #pragma unroll
            for (int np = 0; np < 2; np++) {
                uint32_t off = bOff + (uint32_t)(np * 16 + ks * 16 * B_STRIDE) * 2u;
                ldsm_x4_t(bHiB + off, Bhr[np]);
                ldsm_x4_t(bLoB + off, Blr[np]);
            }
            #pragma unroll
            for (int mi = 0; mi < 2; mi++)
                #pragma unroll
                for (int nj = 0; nj < 4; nj++) {
                    const int np = nj >> 1, hf = (nj & 1) * 2;
                    mma_bf16(acc[mi][nj], Ahr[mi], Bhr[np][hf], Bhr[np][hf + 1]);
                    mma_bf16(acc[mi][nj], Ahr[mi], Blr[np][hf], Blr[np][hf + 1]);
                    mma_bf16(acc[mi][nj], Alr[mi], Bhr[np][hf], Bhr[np][hf + 1]);
                }
        }
        __syncthreads();
    }
    #undef ISSUE_CHUNK

    // epilogue — writes bf16 hi/lo at stride PWc
    #pragma unroll
    for (int mi = 0; mi < 2; mi++)
        #pragma unroll
        for (int nj = 0; nj < 4; nj++) {
            int col = n0 + warp_n * 32 + nj * 8 + (lane & 3) * 2;
            if (col >= Fo) continue;
            float2 b2 = *(const float2*)(bias + col);
            #pragma unroll
            for (int half = 0; half < 2; half++) {
                int row = rbase + warp_m * 32 + mi * 16 + (lane >> 2) + half * 8;
                float vx = acc[mi][nj][half * 2 + 0] + b2.x;
                float vy = acc[mi][nj][half * 2 + 1] + b2.y;
                if (res) {
                    float2 r2 = *(const float2*)(res + (size_t)row * Fo + col);
                    vx += r2.x; vy += r2.y;
                }
                if (doRelu) { vx = fmaxf(vx, 0.0f); vy = fmaxf(vy, 0.0f); }
                __nv_bfloat16 hx, lx, hy, ly;
                split2(vx, hx, lx); split2(vy, hy, ly);
                *(__nv_bfloat162*)(Ch + (size_t)row * PWc + col) = __halves2bfloat162(hx, hy);
                *(__nv_bfloat162*)(Cl + (size_t)row * PWc + col) = __halves2bfloat162(lx, ly);
            }
        }
}

// ---------------- row squared norms from hi/lo bf16 --------------------------
__global__ void row_norms_hl(const __nv_bfloat16* __restrict__ H,
                             const __nv_bfloat16* __restrict__ L,
                             float* __restrict__ out, int D)
{
    int warp = (blockIdx.x * blockDim.x + threadIdx.x) >> 5;
    int lane = threadIdx.x & 31;
    if (warp >= NTOT) return;
    float s = 0.0f;
    for (int k = lane; k < D; k += 32) {
        size_t o = (size_t)warp * D + k;
        float v = __bfloat162float(H[o]) + __bfloat162float(L[o]);
        s += v * v;
    }
    #pragma unroll
    for (int o = 16; o; o >>= 1) s += __shfl_xor_sync(0xffffffffu, s, o);
    if (lane == 0) out[warp] = s;
}

// ---------------- fused fm kernel: disjoint smem, single sync ----------------
#define FMI 64
#define FMJ 128
#define AF_S 120
#define BF_S 136
#define AG_S 40
// disjoint bf16-unit offsets (f and g tiles both live simultaneously)
#define OF_AXH 0
#define OF_AXL 7680
#define OF_AYH 15360
#define OF_AYL 23040
#define OF_BH  30720
#define OF_BL  45952
#define OG_AXH 61184
#define OG_AXL 63744
#define OG_AYH 66304
#define OG_AYL 68864
#define OG_BH  71424
#define OG_BL  75776
#define FM_DYN_BYTES (80128 * 2)

__global__ __launch_bounds__(512)
void fm3_kernel(const float* __restrict__ eps_p, const float* __restrict__ sig_p,
                const float* __restrict__ sig0_p, const float* __restrict__ cst_p)
{
    extern __shared__ __nv_bfloat16 dynb[];
    __shared__ float nfx[64], nfy[64], ngx[64], ngy[64];
    __shared__ float nfv[128], ngv[128];
    __shared__ float scs[128];
    __shared__ float red16[16];

    const int tid    = threadIdx.x;
    const int lane   = tid & 31;
    const int wid    = tid >> 5;
    const int warp_m = wid >> 3;
    const int warp_n = wid & 7;
    const int ibase  = blockIdx.y * FMI;
    const int jbase  = blockIdx.x * FMJ;
    const int XR = ibase, YR = NXC + ibase, VR = 2 * NXC + jbase;

    if (tid < 64) {
        nfx[tid] = g_nF[XR + tid]; nfy[tid] = g_nF[YR + tid];
        ngx[tid] = g_nG[XR + tid]; ngy[tid] = g_nG[YR + tid];
    } else if (tid < 192) {
        int j = tid - 64;
        nfv[j] = g_nF[VR + j]; ngv[j] = g_nG[VR + j];
    } else if (tid < 320) {
        scs[tid - 192] = 0.0f;
    }

    // ---- stage ALL tiles (f and g, disjoint), then one sync ----
    for (int e = tid; e < 896; e += 512) {           // f-A: 64 rows x 14 uint4
        int r = e / 14, kv = (e % 14) * 8;
        *(uint4*)&dynb[OF_AXH + r * AF_S + kv] = *(const uint4*)&g_Fh[(size_t)(XR + r) * FDP + kv];
        *(uint4*)&dynb[OF_AXL + r * AF_S + kv] = *(const uint4*)&g_Fl[(size_t)(XR + r) * FDP + kv];
        *(uint4*)&dynb[OF_AYH + r * AF_S + kv] = *(const uint4*)&g_Fh[(size_t)(YR + r) * FDP + kv];
        *(uint4*)&dynb[OF_AYL + r * AF_S + kv] = *(const uint4*)&g_Fl[(size_t)(YR + r) * FDP + kv];
    }
    for (int e = tid; e < 1792; e += 512) {          // f-B: 112 k x 16 uint4
        int k = e >> 4, jv = (e & 15) * 8;
        *(uint4*)&dynb[OF_BH + k * BF_S + jv] = *(const uint4*)&g_FvTh[k * 1024 + jbase + jv];
        *(uint4*)&dynb[OF_BL + k * BF_S + jv] = *(const uint4*)&g_FvTl[k * 1024 + jbase + jv];
    }
    if (tid < 256) {                                  // g-A: 64 rows x 4 uint4
        int r = tid >> 2, kv = (tid & 3) * 8;
        *(uint4*)&dynb[OG_AXH + r * AG_S + kv] = *(const uint4*)&g_Gh[(size_t)(XR + r) * GDP + kv];
        *(uint4*)&dynb[OG_AXL + r * AG_S + kv] = *(const uint4*)&g_Gl[(size_t)(XR + r) * GDP + kv];
        *(uint4*)&dynb[OG_AYH + r * AG_S + kv] = *(const uint4*)&g_Gh[(size_t)(YR + r) * GDP + kv];
        *(uint4*)&dynb[OG_AYL + r * AG_S + kv] = *(const uint4*)&g_Gl[(size_t)(YR + r) * GDP + kv];
    }
    {                                                 // g-B: 32 k x 16 uint4 = 512
        int k = tid >> 4, jv = (tid & 15) * 8;
        *(uint4*)&dynb[OG_BH + k * BF_S + jv] = *(const uint4*)&g_GvTh[k * 1024 + jbase + jv];
        *(uint4*)&dynb[OG_BL + k * BF_S + jv] = *(const uint4*)&g_GvTl[k * 1024 + jbase + jv];
    }
    __syncthreads();   // the ONLY pre-epilogue sync

    const uint32_t dyn32 = smem_u32(dynb);
    const int a_row  = warp_m * 32 + (lane & 15);
    const int a_kadd = (lane >> 4) * 8;
    const int b_k    = lane & 15;
    const int b_n    = warp_n * 16 + ((lane & 16) ? 8 : 0);

    float accX[2][2][4], accY[2][2][4];
    #pragma unroll
    for (int i = 0; i < 2; i++)
        #pragma unroll
        for (int j = 0; j < 2; j++)
            #pragma unroll
            for (int q = 0; q < 4; q++) { accX[i][j][q] = 0.0f; accY[i][j][q] = 0.0f; }

    // ---- f-phase MMA: K = 112 ----
    #pragma unroll
    for (int ks = 0; ks < 7; ks++) {
        uint32_t AXh[2][4], AXl[2][4], AYh[2][4], AYl[2][4], Bh[4], Bl[4];
        #pragma unroll
        for (int mi = 0; mi < 2; mi++) {
            uint32_t ao = (uint32_t)((a_row + mi * 16) * AF_S + ks * 16 + a_kadd) * 2u;
            ldsm_x4(dyn32 + OF_AXH * 2u + ao, AXh[mi]);
            ldsm_x4(dyn32 + OF_AXL * 2u + ao, AXl[mi]);
            ldsm_x4(dyn32 + OF_AYH * 2u + ao, AYh[mi]);
            ldsm_x4(dyn32 + OF_AYL * 2u + ao, AYl[mi]);
        }
        {
            uint32_t bo = (uint32_t)((b_k + ks * 16) * BF_S + b_n) * 2u;
            ldsm_x4_t(dyn32 + OF_BH * 2u + bo, Bh);
            ldsm_x4_t(dyn32 + OF_BL * 2u + bo, Bl);
        }
        #pragma unroll
        for (int mi = 0; mi < 2; mi++)
            #pragma unroll
            for (int nj = 0; nj < 2; nj++) {
                const int hf = nj * 2;
                mma_bf16(accX[mi][nj], AXh[mi], Bh[hf], Bh[hf + 1]);
                mma_bf16(accX[mi][nj], AXh[mi], Bl[hf], Bl[hf + 1]);
                mma_bf16(accX[mi][nj], AXl[mi], Bh[hf], Bh[hf + 1]);
                mma_bf16(accY[mi][nj], AYh[mi], Bh[hf], Bh[hf + 1]);
                mma_bf16(accY[mi][nj], AYh[mi], Bl[hf], Bl[hf + 1]);
                mma_bf16(accY[mi][nj], AYl[mi], Bh[hf], Bh[hf + 1]);
            }
    }

    // ---- convert f-dots -> K-factor (MUFU exp2) ----
    const float LOG2E  = 1.4426950408889634f;
    const float ep     = 1.0f / (1.0f + __expf(-eps_p[0]));
    const float is2    = LOG2E / (sig_p[0]  * sig_p[0]);
    const float is0    = LOG2E / (sig0_p[0] * sig0_p[0]);
    const float cstv   = cst_p[0];
    const float one_ep = 1.0f - ep;

    #pragma unroll
    for (int mi = 0; mi < 2; mi++)
        #pragma unroll
        for (int nj = 0; nj < 2; nj++)
            #pragma unroll
            for (int q = 0; q < 4; q++) {
                int rl = warp_m * 32 + mi * 16 + (lane >> 2) + (q >> 1) * 8;
                int cl = warp_n * 16 + nj * 8 + (lane & 3) * 2 + (q & 1);
                float Dx = fmaxf(nfx[rl] + nfv[cl] - 2.0f * accX[mi][nj][q], 0.0f);
                float Dy = fmaxf(nfy[rl] + nfv[cl] - 2.0f * accY[mi][nj][q], 0.0f);
                accX[mi][nj][q] = fmaf(one_ep, fexp2(-Dx * is0), ep);
                accY[mi][nj][q] = fmaf(one_ep, fexp2(-Dy * is0), ep);
            }

    // ---- g-phase MMA: K = 32 (tiles already staged; no sync needed) ----
    float gX[2][2][4], gY[2][2][4];
    #pragma unroll
    for (int i = 0; i < 2; i++)
        #pragma unroll
        for (int j = 0; j < 2; j++)
            #pragma unroll
            for (int q = 0; q < 4; q++) { gX[i][j][q] = 0.0f; gY[i][j][q] = 0.0f; }

    #pragma unroll
    for (int ks = 0; ks < 2; ks++) {
        uint32_t AXh[2][4], AXl[2][4], AYh[2][4], AYl[2][4], Bh[4], Bl[4];
        #pragma unroll
        for (int mi = 0; mi < 2; mi++) {
            uint32_t ao = (uint32_t)((a_row + mi * 16) * AG_S + ks * 16 + a_kadd) * 2u;
            ldsm_x4(dyn32 + OG_AXH * 2u + ao, AXh[mi]);
            ldsm_x4(dyn32 + OG_AXL * 2u + ao, AXl[mi]);
            ldsm_x4(dyn32 + OG_AYH * 2u + ao, AYh[mi]);
            ldsm_x4(dyn32 + OG_AYL * 2u + ao, AYl[mi]);
        }
        {
            uint32_t bo = (uint32_t)((b_k + ks * 16) * BF_S + b_n) * 2u;
            ldsm_x4_t(dyn32 + OG_BH * 2u + bo, Bh);
            ldsm_x4_t(dyn32 + OG_BL * 2u + bo, Bl);
        }
        #pragma unroll
        for (int mi = 0; mi < 2; mi++)
            #pragma unroll
            for (int nj = 0; nj < 2; nj++) {
                const int hf = nj * 2;
                mma_bf16(gX[mi][nj], AXh[mi], Bh[hf], Bh[hf + 1]);
                mma_bf16(gX[mi][nj], AXh[mi], Bl[hf], Bl[hf + 1]);
                mma_bf16(gX[mi][nj], AXl[mi], Bh[hf], Bh[hf + 1]);
                mma_bf16(gY[mi][nj], AYh[mi], Bh[hf], Bh[hf + 1]);
                mma_bf16(gY[mi][nj], AYh[mi], Bl[hf], Bl[hf + 1]);
                mma_bf16(gY[mi][nj], AYl[mi], Bh[hf], Bh[hf + 1]);
            }
    }

    // ---- final epilogue ----
    const float RS = 0.03125f;
    float csum[4];
    #pragma unroll
    for (int i = 0; i < 4; i++) csum[i] = 0.0f;
    float qacc = 0.0f;

    #pragma unroll
    for (int mi = 0; mi < 2; mi++)
        #pragma unroll
        for (int nj = 0; nj < 2; nj++) {
            float vq[4];
            #pragma unroll
            for (int q = 0; q < 4; q++) {
                int rl = warp_m * 32 + mi * 16 + (lane >> 2) + (q >> 1) * 8;
                int cl = warp_n * 16 + nj * 8 + (lane & 3) * 2 + (q & 1);
                float Dgx = fmaxf(ngx[rl] + ngv[cl] - 2.0f * gX[mi][nj][q], 0.0f);
                float Dgy = fmaxf(ngy[rl] + ngv[cl] - 2.0f * gY[mi][nj][q], 0.0f);
                float KX = cstv * accX[mi][nj][q] * fexp2(-Dgx * is2);
                float KY = cstv * accY[mi][nj][q] * fexp2(-Dgy * is2);
                float v = (KX - KY) * RS;
                vq[q] = v;
                csum[nj * 2 + (q & 1)] += v;
                qacc += v * v;
            }
            int colg = jbase + warp_n * 16 + nj * 8 + (lane & 3) * 2;
            int row0 = ibase + warp_m * 32 + mi * 16 + (lane >> 2);
            *(__nv_bfloat162*)&g_fmb[(size_t)row0 * JC + colg] =
                __floats2bfloat162_rn(vq[0], vq[1]);
            *(__nv_bfloat162*)&g_fmb[(size_t)(row0 + 8) * JC + colg] =
                __floats2bfloat162_rn(vq[2], vq[3]);
        }

    // column sums: shuffle-reduce over the 8 row-groups (lane bits 2..4),
    // leaving totals in lanes 0..3 -> 16 smem atomics per warp instead of 128
    #pragma unroll
    for (int off = 16; off >= 4; off >>= 1)
        #pragma unroll
        for (int c4 = 0; c4 < 4; c4++)
            csum[c4] += __shfl_down_sync(0xffffffffu, csum[c4], off);
    if (lane < 4) {
        #pragma unroll
        for (int c4 = 0; c4 < 4; c4++) {
            int cl = warp_n * 16 + (c4 >> 1) * 8 + lane * 2 + (c4 & 1);
            atomicAdd(&scs[cl], csum[c4]);
        }
    }
    // qacc: full warp reduce, one smem slot per warp
    #pragma unroll
    for (int off = 16; off; off >>= 1)
        qacc += __shfl_xor_sync(0xffffffffu, qacc, off);
    if (lane == 0) red16[wid] = qacc;
    __syncthreads();

    if (tid < 128) atomicAdd(&g_colsum[jbase + tid], scs[tid]);
    if (wid == 0) {
        float v = (lane < 16) ? red16[lane] : 0.0f;
        #pragma unroll
        for (int off = 8; off; off >>= 1)
            v += __shfl_xor_sync(0xffffffffu, v, off);
        if (lane == 0) atomicAdd(&g_scal[0], v);
    }
}

// ---------------- mu + sum(mu^2) ----------------------------------------------
__global__ void mu_kernel() {
    __shared__ float red[JC];
    int j = threadIdx.x;
    float m = g_colsum[j] * (1.0f / (float)NXC);
    g_mu[j] = m;
    red[j] = m * m;
    __syncthreads();
    for (int s = 512; s; s >>= 1) {
        if (j < s) red[j] += red[j + s];
        __syncthreads();
    }
    if (j == 0) g_scal[2] = red[0];
}

// ---------------- s_i = fm[i]·mu (bf16 fm) ; accumulate s_i^2 -----------------
__global__ __launch_bounds__(256) void s2_kernel() {
    __shared__ float smu[JC];
    int tid = threadIdx.x;
    for (int e = tid; e < JC; e += 256) smu[e] = g_mu[e];
    __syncthreads();
    int row  = blockIdx.x * 8 + (tid >> 5);
    int lane = tid & 31;
    const __nv_bfloat16* rp = g_fmb + (size_t)row * JC;
    float s = 0.0f;
    #pragma unroll
    for (int t = 0; t < 4; t++) {
        int c = lane * 8 + 256 * t;
        uint4 v = *(const uint4*)(rp + c);
        const __nv_bfloat16* pv = (const __nv_bfloat16*)&v;
        #pragma unroll
        for (int e = 0; e < 8; e++)
            s += __bfloat162float(pv[e]) * smu[c + e];
    }
    #pragma unroll
    for (int o = 16; o; o >>= 1) s += __shfl_xor_sync(0xffffffffu, s, o);
    if (lane == 0) atomicAdd(&g_scal[1], s * s);
}

// ---------------- finalize ------------------------------------------------------
__global__ void finalize_kernel(float* out) {
    double sumfm2 = (double)g_scal[0];
    double sums2  = (double)g_scal[1];
    double summu2 = (double)g_scal[2];
    double nx = (double)NXC;
    double t1 = summu2 * (nx / (nx - 1.0));
    double t2 = sumfm2 / nx / (nx - 1.0);
    double mean = t1 - t2;
    double var  = 4.0 * (sums2 / nx) - 4.0 * summu2 * summu2;
    out[0] = (float)(-(mean / sqrt(var + 1e-6)));
}

// ---------------- launch ---------------------------------------------------------
extern "C" void kernel_launch(void* const* d_in, const int* in_sizes, int n_in,
                              void* d_out, int out_size)
{
    const float* XY = (const float*)d_in[0];
    const float* V  = (const float*)d_in[1];
    const float *dnW[6], *dnb[6], *anW[6], *anb[6];
    for (int i = 0; i < 6; i++) {
        dnW[i] = (const float*)d_in[2 + 2 * i];
        dnb[i] = (const float*)d_in[3 + 2 * i];
        anW[i] = (const float*)d_in[14 + 2 * i];
        anb[i] = (const float*)d_in[15 + 2 * i];
    }
    const float* eps   = (const float*)d_in[26];
    const float* sig   = (const float*)d_in[27];
    const float* sig0  = (const float*)d_in[28];
    const float* cstp  = (const float*)d_in[29];

    float *in0, *nF, *nG;
    __nv_bfloat16 *inh, *inl, *h0, *l0, *h1, *l1, *b0h, *b0l, *b1h, *b1l;
    __nv_bfloat16 *Wh, *Wl, *Fh, *Fl, *Gh, *Gl;
    cudaGetSymbolAddress((void**)&in0, g_in0);
    cudaGetSymbolAddress((void**)&nF,  g_nF);
    cudaGetSymbolAddress((void**)&nG,  g_nG);
    cudaGetSymbolAddress((void**)&inh, g_inh);
    cudaGetSymbolAddress((void**)&inl, g_inl);
    cudaGetSymbolAddress((void**)&h0,  g_Ah0);
    cudaGetSymbolAddress((void**)&l0,  g_Al0);
    cudaGetSymbolAddress((void**)&h1,  g_Ah1);
    cudaGetSymbolAddress((void**)&l1,  g_Al1);
    cudaGetSymbolAddress((void**)&b0h, g_Bh0);
    cudaGetSymbolAddress((void**)&b0l, g_Bl0);
    cudaGetSymbolAddress((void**)&b1h, g_Bh1);
    cudaGetSymbolAddress((void**)&b1l, g_Bl1);
    cudaGetSymbolAddress((void**)&Wh,  g_Wh);
    cudaGetSymbolAddress((void**)&Wl,  g_Wl);
    cudaGetSymbolAddress((void**)&Fh,  g_Fh);
    cudaGetSymbolAddress((void**)&Fl,  g_Fl);
    cudaGetSymbolAddress((void**)&Gh,  g_Gh);
    cudaGetSymbolAddress((void**)&Gl,  g_Gl);

    const int GY = NTOT / BMM;     // 520
    const dim3 blk(256);

    prep_in_kernel<<<(NTOT * 32 + 255) / 256, 256>>>(XY, V);
    pad_all_kernel<<<(NTOT * 20 + 255) / 256, 256>>>();
    init_acc_kernel<<<1, 1024>>>();

    WPrepArgs wa;
    for (int i = 0; i < 6; i++) {
        wa.W[i]     = dnW[i];  wa.W[i + 6] = anW[i];
        wa.Fi[i]    = (i == 0) ? DIMC : HC;
        wa.Fi[i+6]  = (i == 0) ? DIMC : HC;
        wa.Fo[i]    = (i == 5) ? FD : HC;
        wa.Fo[i+6]  = (i == 5) ? GD : HC;
    }
    prep_w_all<<<dim3((WOFF + 255) / 256, 12), 256>>>(wa);

    cudaFuncSetAttribute(mma_gemm3, cudaFuncAttributeMaxDynamicSharedMemorySize,
                         GEMM_SMEM_BYTES);
    const dim3 gH(5, GY, 2);
    const dim3 gL5(2, GY, 2);

    #define GEMM3(grid, AhD,AlD,AhA,AlA, PWa, L, bD,bA, FoD,FoA, ChD,ClD,ChA,ClA, PWcD,PWcA, resA, nC, relu) \
        mma_gemm3<<<grid, blk, GEMM_SMEM_BYTES>>>(AhD,AlD,AhA,AlA, PWa, Wh, Wl, L, \
            bD,bA, FoD,FoA, ChD,ClD,ChA,ClA, PWcD,PWcA, resA, nC, relu)

    GEMM3(gH, inh,inl, inh,inl, 32, 0, dnb[0],anb[0], HC,HC, h0,l0, b0h,b0l, PWH,PWH, (const float*)0, 1, 1);
    GEMM3(gH, h0,l0, b0h,b0l, PWH, 1, dnb[1],anb[1], HC,HC, h1,l1, b1h,b1l, PWH,PWH, (const float*)0, 10, 1);
    GEMM3(gH, h1,l1, b1h,b1l, PWH, 2, dnb[2],anb[2], HC,HC, h0,l0, b0h,b0l, PWH,PWH, (const float*)0, 10, 1);
    GEMM3(gH, h0,l0, b0h,b0l, PWH, 3, dnb[3],anb[3], HC,HC, h1,l1, b1h,b1l, PWH,PWH, (const float*)0, 10, 1);
    GEMM3(gH, h1,l1, b1h,b1l, PWH, 4, dnb[4],anb[4], HC,HC, h0,l0, b0h,b0l, PWH,PWH, (const float*)0, 10, 1);
    GEMM3(gL5, h0,l0, b0h,b0l, PWH, 5, dnb[5],anb[5], FD,GD, Fh,Fl, Gh,Gl, FDP,GDP, in0, 10, 0);

    transpose_v_kernel<<<(FDP * JC + 255) / 256, 256>>>();
    row_norms_hl<<<NTOT / 8, 256>>>(Fh, Fl, nF, FDP);
    row_norms_hl<<<NTOT / 8, 256>>>(Gh, Gl, nG, GDP);

    cudaFuncSetAttribute(fm3_kernel, cudaFuncAttributeMaxDynamicSharedMemorySize,
                         FM_DYN_BYTES);
    fm3_kernel<<<dim3(JC / FMJ, NXC / FMI), 512, FM_DYN_BYTES>>>(eps, sig, sig0, cstp);

    mu_kernel<<<1, JC>>>();
    s2_kernel<<<NXC / 8, 256>>>();
    finalize_kernel<<<1, 1>>>((float*)d_out);
}

// round 11
// speedup vs baseline: 1.1487x; 1.0581x over previous
#include <cuda_runtime.h>
#include <cuda_bf16.h>
#include <math.h>
#include <stdint.h>

// Problem constants
#define NXC   32768
#define NTOT  66560
#define DIMC  28
#define HC    300
#define FD    100
#define GD    28
#define JC    1024

#define PWH   320
#define FDP   112
#define GDP   32
#define WOFF  (320 * 320)

// ---------------- scratch ----------------------------------------------------
__device__ float g_in0 [(size_t)NTOT * DIMC];
__device__ __align__(16) __nv_bfloat16 g_inh[(size_t)NTOT * 32];
__device__ __align__(16) __nv_bfloat16 g_inl[(size_t)NTOT * 32];
__device__ __align__(16) __nv_bfloat16 g_Ah0[(size_t)NTOT * PWH];
__device__ __align__(16) __nv_bfloat16 g_Al0[(size_t)NTOT * PWH];
__device__ __align__(16) __nv_bfloat16 g_Ah1[(size_t)NTOT * PWH];
__device__ __align__(16) __nv_bfloat16 g_Al1[(size_t)NTOT * PWH];
__device__ __align__(16) __nv_bfloat16 g_Bh0[(size_t)NTOT * PWH];
__device__ __align__(16) __nv_bfloat16 g_Bl0[(size_t)NTOT * PWH];
__device__ __align__(16) __nv_bfloat16 g_Bh1[(size_t)NTOT * PWH];
__device__ __align__(16) __nv_bfloat16 g_Bl1[(size_t)NTOT * PWH];
__device__ __align__(16) __nv_bfloat16 g_Wh[12 * WOFF];
__device__ __align__(16) __nv_bfloat16 g_Wl[12 * WOFF];
__device__ __align__(16) __nv_bfloat16 g_Fh[(size_t)NTOT * FDP];
__device__ __align__(16) __nv_bfloat16 g_Fl[(size_t)NTOT * FDP];
__device__ __align__(16) __nv_bfloat16 g_Gh[(size_t)NTOT * GDP];
__device__ __align__(16) __nv_bfloat16 g_Gl[(size_t)NTOT * GDP];
__device__ __align__(16) __nv_bfloat16 g_FvTh[FDP * JC];
__device__ __align__(16) __nv_bfloat16 g_FvTl[FDP * JC];
__device__ __align__(16) __nv_bfloat16 g_GvTh[GDP * JC];
__device__ __align__(16) __nv_bfloat16 g_GvTl[GDP * JC];
__device__ float g_nF  [NTOT];
__device__ float g_nG  [NTOT];
__device__ __align__(16) __nv_bfloat16 g_fmb[(size_t)NXC * JC];   // bf16 fm (s2 only)
__device__ float g_colsum[JC];
__device__ float g_mu    [JC];
__device__ float g_scal  [8];

__device__ __forceinline__ void split2(float x, __nv_bfloat16& h, __nv_bfloat16& l) {
    h = __float2bfloat16(x);
    l = __float2bfloat16(x - __bfloat162float(h));
}
__device__ __forceinline__ float fexp2(float x) {
    float r;
    asm("ex2.approx.ftz.f32 %0, %1;" : "=f"(r) : "f"(x));
    return r;
}

// ---------------- prep kernels ----------------------------------------------
__global__ void prep_in_kernel(const float* __restrict__ XY, const float* __restrict__ V) {
    int t = blockIdx.x * blockDim.x + threadIdx.x;
    if (t >= NTOT * 32) return;
    int r = t >> 5, c = t & 31;
    float v = 0.0f;
    if (c < DIMC) {
        int idx = r * DIMC + c;
        v = (r < 2 * NXC) ? XY[idx] : V[(r - 2 * NXC) * DIMC + c];
        g_in0[idx] = v;
    }
    __nv_bfloat16 h, l; split2(v, h, l);
    g_inh[t] = h; g_inl[t] = l;
}
__global__ void pad_all_kernel() {
    int t = blockIdx.x * blockDim.x + threadIdx.x;
    if (t >= NTOT * 20) return;
    int r = t / 20, c = t % 20;
    __nv_bfloat16 z = __float2bfloat16(0.0f);
    size_t o = (size_t)r * PWH + HC + c;
    g_Ah0[o] = z; g_Al0[o] = z; g_Ah1[o] = z; g_Al1[o] = z;
    g_Bh0[o] = z; g_Bl0[o] = z; g_Bh1[o] = z; g_Bl1[o] = z;
    if (c < 12) {
        size_t of = (size_t)r * FDP + 100 + c;
        g_Fh[of] = z; g_Fl[of] = z;
    }
    if (c < 4) {
        size_t og = (size_t)r * GDP + 28 + c;
        g_Gh[og] = z; g_Gl[og] = z;
    }
}
__global__ void init_acc_kernel() {
    int t = threadIdx.x;
    if (t < JC) g_colsum[t] = 0.0f;
    if (t < 8)  g_scal[t]   = 0.0f;
}
struct WPrepArgs {
    const float* W[12];
    int Fi[12];
    int Fo[12];
};
__global__ void prep_w_all(WPrepArgs a) {
    int layer = blockIdx.y;
    int idx = blockIdx.x * blockDim.x + threadIdx.x;
    if (idx >= WOFF) return;
    int k = idx / 320, n = idx - k * 320;
    int Fi = a.Fi[layer], Fo = a.Fo[layer];
    float v = (k < Fi && n < Fo) ? a.W[layer][(size_t)k * Fo + n] : 0.0f;
    __nv_bfloat16 h, l; split2(v, h, l);
    g_Wh[(size_t)layer * WOFF + idx] = h;
    g_Wl[(size_t)layer * WOFF + idx] = l;
}
__global__ void transpose_v_kernel() {
    int t = blockIdx.x * blockDim.x + threadIdx.x;
    if (t < FDP * JC) {
        int k = t >> 10, j = t & 1023;
        size_t src = (size_t)(2 * NXC + j) * FDP + k;
        g_FvTh[t] = g_Fh[src];
        g_FvTl[t] = g_Fl[src];
    }
    if (t < GDP * JC) {
        int k = t >> 10, j = t & 1023;
        size_t src = (size_t)(2 * NXC + j) * GDP + k;
        g_GvTh[t] = g_Gh[src];
        g_GvTl[t] = g_Gl[src];
    }
}

// =============== shared MMA helpers ==========================================
__device__ __forceinline__ uint32_t smem_u32(const void* p) {
    uint32_t a;
    asm("{ .reg .u64 t; cvta.to.shared.u64 t, %1; cvt.u32.u64 %0, t; }" : "=r"(a) : "l"(p));
    return a;
}
__device__ __forceinline__ void ldsm_x4(uint32_t addr, uint32_t r[4]) {
    asm volatile("ldmatrix.sync.aligned.m8n8.x4.shared.b16 {%0,%1,%2,%3}, [%4];"
        : "=r"(r[0]), "=r"(r[1]), "=r"(r[2]), "=r"(r[3]) : "r"(addr));
}
__device__ __forceinline__ void ldsm_x4_t(uint32_t addr, uint32_t r[4]) {
    asm volatile("ldmatrix.sync.aligned.m8n8.x4.trans.shared.b16 {%0,%1,%2,%3}, [%4];"
        : "=r"(r[0]), "=r"(r[1]), "=r"(r[2]), "=r"(r[3]) : "r"(addr));
}
__device__ __forceinline__ void mma_bf16(float c[4], const uint32_t a[4],
                                         uint32_t b0, uint32_t b1) {
    asm volatile(
        "mma.sync.aligned.m16n8k16.row.col.f32.bf16.bf16.f32 "
        "{%0,%1,%2,%3}, {%4,%5,%6,%7}, {%8,%9}, {%0,%1,%2,%3};"
        : "+f"(c[0]), "+f"(c[1]), "+f"(c[2]), "+f"(c[3])
        : "r"(a[0]), "r"(a[1]), "r"(a[2]), "r"(a[3]), "r"(b0), "r"(b1));
}
#define CP_ASYNC16(dst_u32, src_ptr) \
    asm volatile("cp.async.cg.shared.global [%0], [%1], 16;" \
        :: "r"(dst_u32), "l"(src_ptr) : "memory")
#define CP_COMMIT() asm volatile("cp.async.commit_group;" ::: "memory")
#define CP_WAIT(n)  asm volatile("cp.async.wait_group %0;" :: "n"(n) : "memory")

// =============== bf16-split GEMM: 3-stage, SINGLE sync per chunk =============
#define BMM 128
#define BNN 64
#define BKK 32
#define A_STRIDE 40
#define B_STRIDE 72
#define SM_AH 0
#define SM_AL 15360
#define SM_BH 30720
#define SM_BL 37632
#define GEMM_SMEM_BYTES 89088

__global__ __launch_bounds__(256, 2)
void mma_gemm3(const __nv_bfloat16* __restrict__ AhD, const __nv_bfloat16* __restrict__ AlD,
               const __nv_bfloat16* __restrict__ AhA, const __nv_bfloat16* __restrict__ AlA,
               int PWa,
               const __nv_bfloat16* __restrict__ WhB, const __nv_bfloat16* __restrict__ WlB,
               int layer,
               const float* __restrict__ biasD, const float* __restrict__ biasA,
               int FoD, int FoA,
               __nv_bfloat16* __restrict__ ChD, __nv_bfloat16* __restrict__ ClD,
               __nv_bfloat16* __restrict__ ChA, __nv_bfloat16* __restrict__ ClA,
               int PWcD, int PWcA,
               const float* __restrict__ resA,
               int nC, int doRelu)
{
    extern __shared__ __nv_bfloat16 dyn[];

    const int net = blockIdx.z;
    const __nv_bfloat16* Ah = net ? AhA : AhD;
    const __nv_bfloat16* Al = net ? AlA : AlD;
    const __nv_bfloat16* Wh = WhB + (size_t)(layer + 6 * net) * WOFF;
    const __nv_bfloat16* Wl = WlB + (size_t)(layer + 6 * net) * WOFF;
    const float* bias = net ? biasA : biasD;
    const int Fo  = net ? FoA : FoD;
    __nv_bfloat16* Ch = net ? ChA : ChD;
    __nv_bfloat16* Cl = net ? ClA : ClD;
    const int PWc = net ? PWcA : PWcD;
    const float* res = net ? resA : (const float*)0;

    const int n0 = blockIdx.x * BNN;
    if (n0 >= Fo) return;

    const int tid    = threadIdx.x;
    const int lane   = tid & 31;
    const int wid    = tid >> 5;
    const int warp_m = wid >> 1;
    const int warp_n = wid & 1;
    const int rbase  = blockIdx.y * BMM;

    const int a_row0 = tid >> 2;
    const int a_kk   = (tid & 3) * 8;
    const int bk     = tid >> 3;
    const int bn     = (tid & 7) * 8;

    const uint32_t dyn32 = smem_u32(dyn);
    const int a_row  = warp_m * 32 + (lane & 15);
    const int a_kadd = (lane >> 4) * 8;
    const uint32_t aHiB = dyn32 + (uint32_t)(SM_AH + a_row * A_STRIDE + a_kadd) * 2u;
    const uint32_t aLoB = dyn32 + (uint32_t)(SM_AL + a_row * A_STRIDE + a_kadd) * 2u;
    const int b_k = (lane & 7) + ((lane & 8) ? 8 : 0);
    const int b_n = warp_n * 32 + ((lane & 16) ? 8 : 0);
    const uint32_t bHiB = dyn32 + (uint32_t)(SM_BH + b_k * B_STRIDE + b_n) * 2u;
    const uint32_t bLoB = dyn32 + (uint32_t)(SM_BL + b_k * B_STRIDE + b_n) * 2u;

    const uint32_t dA0 = dyn32 + (uint32_t)(a_row0 * A_STRIDE + a_kk) * 2u;
    const uint32_t dB0 = dyn32 + (uint32_t)(SM_BH + bk * B_STRIDE + bn) * 2u;

    float acc[2][4][4];
    #pragma unroll
    for (int i = 0; i < 2; i++)
        #pragma unroll
        for (int j = 0; j < 4; j++)
            #pragma unroll
            for (int q = 0; q < 4; q++) acc[i][j][q] = 0.0f;

    #define ISSUE_CHUNK(k0, bf) do { \
        uint32_t od = (uint32_t)(bf) * 10240u; \
        uint32_t ob = (uint32_t)(bf) * 4608u; \
        size_t o0 = (size_t)(rbase + a_row0) * PWa + (k0) + a_kk; \
        size_t o1 = (size_t)(rbase + a_row0 + 64) * PWa + (k0) + a_kk; \
        uint32_t d1 = dA0 + od + (uint32_t)(64 * A_STRIDE) * 2u; \
        CP_ASYNC16(dA0 + od,           Ah + o0); \
        CP_ASYNC16(dA0 + od + 30720u,  Al + o0); \
        CP_ASYNC16(d1,                 Ah + o1); \
        CP_ASYNC16(d1 + 30720u,        Al + o1); \
        size_t bo = (size_t)((k0) + bk) * 320 + n0 + bn; \
        CP_ASYNC16(dB0 + ob,           Wh + bo); \
        CP_ASYNC16(dB0 + ob + 13824u,  Wl + bo); \
        CP_COMMIT(); \
    } while (0)

    // prologue: pre-issue chunks 0 and 1
    ISSUE_CHUNK(0, 0);
    if (nC > 1) ISSUE_CHUNK(32, 1);

    for (int c = 0; c < nC; c++) {
        const int buf = c % 3;
        const uint32_t aOff = (uint32_t)buf * 10240u;
        const uint32_t bOff = (uint32_t)buf * 4608u;

        // single sync per chunk:
        //  - CP_WAIT ensures group c's data landed (oldest of <=2 outstanding)
        //  - the sync makes it visible AND fences all warps past MMA of chunk c-1,
        //    so the issue below may safely overwrite buf (c+2)%3 == (c-1)%3
        if (c + 1 < nC) { CP_WAIT(1); } else { CP_WAIT(0); }
        __syncthreads();

        #pragma unroll
        for (int ks = 0; ks < 2; ks++) {
            uint32_t Ahr[2][4], Alr[2][4], Bhr[2][4], Blr[2][4];
            #pragma unroll
            for (int mi = 0; mi < 2; mi++) {
                uint32_t off = aOff + (uint32_t)(mi * 16 * A_STRIDE + ks * 16) * 2u;
                ldsm_x4(aHiB + off, Ahr[mi]);
                ldsm_x4(aLoB + off, Alr[mi]);
            }
            #pragma unroll
            for (int np = 0; np < 2; np++) {
                uint32_t off = bOff + (uint32_t)(np * 16 + ks * 16 * B_STRIDE) * 2u;
                ldsm_x4_t(bHiB + off, Bhr[np]);
                ldsm_x4_t(bLoB + off, Blr[np]);
            }
            #pragma unroll
            for (int mi = 0; mi < 2; mi++)
                #pragma unroll
                for (int nj = 0; nj < 4; nj++) {
                    const int np = nj >> 1, hf = (nj & 1) * 2;
                    mma_bf16(acc[mi][nj], Ahr[mi], Bhr[np][hf], Bhr[np][hf + 1]);
                    mma_bf16(acc[mi][nj], Ahr[mi], Blr[np][hf], Blr[np][hf + 1]);
                    mma_bf16(acc[mi][nj], Alr[mi], Bhr[np][hf], Bhr[np][hf + 1]);
                }
        }

        // issue chunk c+2 AFTER this chunk's MMA (ldsm already consumed buf c)
        if (c + 2 < nC) ISSUE_CHUNK((c + 2) * BKK, (c + 2) % 3);
    }
    #undef ISSUE_CHUNK

    // epilogue — writes bf16 hi/lo at stride PWc
    #pragma unroll
    for (int mi = 0; mi < 2; mi++)
        #pragma unroll
        for (int nj = 0; nj < 4; nj++) {
            int col = n0 + warp_n * 32 + nj * 8 + (lane & 3) * 2;
            if (col >= Fo) continue;
            float2 b2 = *(const float2*)(bias + col);
            #pragma unroll
            for (int half = 0; half < 2; half++) {
                int row = rbase + warp_m * 32 + mi * 16 + (lane >> 2) + half * 8;
                float vx = acc[mi][nj][half * 2 + 0] + b2.x;
                float vy = acc[mi][nj][half * 2 + 1] + b2.y;
                if (res) {
                    float2 r2 = *(const float2*)(res + (size_t)row * Fo + col);
                    vx += r2.x; vy += r2.y;
                }
                if (doRelu) { vx = fmaxf(vx, 0.0f); vy = fmaxf(vy, 0.0f); }
                __nv_bfloat16 hx, lx, hy, ly;
                split2(vx, hx, lx); split2(vy, hy, ly);
                *(__nv_bfloat162*)(Ch + (size_t)row * PWc + col) = __halves2bfloat162(hx, hy);
                *(__nv_bfloat162*)(Cl + (size_t)row * PWc + col) = __halves2bfloat162(lx, ly);
            }
        }
}

// ---------------- row squared norms from hi/lo bf16 --------------------------
__global__ void row_norms_hl(const __nv_bfloat16* __restrict__ H,
                             const __nv_bfloat16* __restrict__ L,
                             float* __restrict__ out, int D)
{
    int warp = (blockIdx.x * blockDim.x + threadIdx.x) >> 5;
    int lane = threadIdx.x & 31;
    if (warp >= NTOT) return;
    float s = 0.0f;
    for (int k = lane; k < D; k += 32) {
        size_t o = (size_t)warp * D + k;
        float v = __bfloat162float(H[o]) + __bfloat162float(L[o]);
        s += v * v;
    }
    #pragma unroll
    for (int o = 16; o; o >>= 1) s += __shfl_xor_sync(0xffffffffu, s, o);
    if (lane == 0) out[warp] = s;
}

// ---------------- fused fm kernel: disjoint smem, single sync ----------------
#define FMI 64
#define FMJ 128
#define AF_S 120
#define BF_S 136
#define AG_S 40
#define OF_AXH 0
#define OF_AXL 7680
#define OF_AYH 15360
#define OF_AYL 23040
#define OF_BH  30720
#define OF_BL  45952
#define OG_AXH 61184
#define OG_AXL 63744
#define OG_AYH 66304
#define OG_AYL 68864
#define OG_BH  71424
#define OG_BL  75776
#define FM_DYN_BYTES (80128 * 2)

__global__ __launch_bounds__(512)
void fm3_kernel(const float* __restrict__ eps_p, const float* __restrict__ sig_p,
                const float* __restrict__ sig0_p, const float* __restrict__ cst_p)
{
    extern __shared__ __nv_bfloat16 dynb[];
    __shared__ float nfx[64], nfy[64], ngx[64], ngy[64];
    __shared__ float nfv[128], ngv[128];
    __shared__ float scs[128];
    __shared__ float red16[16];

    const int tid    = threadIdx.x;
    const int lane   = tid & 31;
    const int wid    = tid >> 5;
    const int warp_m = wid >> 3;
    const int warp_n = wid & 7;
    const int ibase  = blockIdx.y * FMI;
    const int jbase  = blockIdx.x * FMJ;
    const int XR = ibase, YR = NXC + ibase, VR = 2 * NXC + jbase;

    if (tid < 64) {
        nfx[tid] = g_nF[XR + tid]; nfy[tid] = g_nF[YR + tid];
        ngx[tid] = g_nG[XR + tid]; ngy[tid] = g_nG[YR + tid];
    } else if (tid < 192) {
        int j = tid - 64;
        nfv[j] = g_nF[VR + j]; ngv[j] = g_nG[VR + j];
    } else if (tid < 320) {
        scs[tid - 192] = 0.0f;
    }

    for (int e = tid; e < 896; e += 512) {
        int r = e / 14, kv = (e % 14) * 8;
        *(uint4*)&dynb[OF_AXH + r * AF_S + kv] = *(const uint4*)&g_Fh[(size_t)(XR + r) * FDP + kv];
        *(uint4*)&dynb[OF_AXL + r * AF_S + kv] = *(const uint4*)&g_Fl[(size_t)(XR + r) * FDP + kv];
        *(uint4*)&dynb[OF_AYH + r * AF_S + kv] = *(const uint4*)&g_Fh[(size_t)(YR + r) * FDP + kv];
        *(uint4*)&dynb[OF_AYL + r * AF_S + kv] = *(const uint4*)&g_Fl[(size_t)(YR + r) * FDP + kv];
    }
    for (int e = tid; e < 1792; e += 512) {
        int k = e >> 4, jv = (e & 15) * 8;
        *(uint4*)&dynb[OF_BH + k * BF_S + jv] = *(const uint4*)&g_FvTh[k * 1024 + jbase + jv];
        *(uint4*)&dynb[OF_BL + k * BF_S + jv] = *(const uint4*)&g_FvTl[k * 1024 + jbase + jv];
    }
    if (tid < 256) {
        int r = tid >> 2, kv = (tid & 3) * 8;
        *(uint4*)&dynb[OG_AXH + r * AG_S + kv] = *(const uint4*)&g_Gh[(size_t)(XR + r) * GDP + kv];
        *(uint4*)&dynb[OG_AXL + r * AG_S + kv] = *(const uint4*)&g_Gl[(size_t)(XR + r) * GDP + kv];
        *(uint4*)&dynb[OG_AYH + r * AG_S + kv] = *(const uint4*)&g_Gh[(size_t)(YR + r) * GDP + kv];
        *(uint4*)&dynb[OG_AYL + r * AG_S + kv] = *(const uint4*)&g_Gl[(size_t)(YR + r) * GDP + kv];
    }
    {
        int k = tid >> 4, jv = (tid & 15) * 8;
        *(uint4*)&dynb[OG_BH + k * BF_S + jv] = *(const uint4*)&g_GvTh[k * 1024 + jbase + jv];
        *(uint4*)&dynb[OG_BL + k * BF_S + jv] = *(const uint4*)&g_GvTl[k * 1024 + jbase + jv];
    }
    __syncthreads();

    const uint32_t dyn32 = smem_u32(dynb);
    const int a_row  = warp_m * 32 + (lane & 15);
    const int a_kadd = (lane >> 4) * 8;
    const int b_k    = lane & 15;
    const int b_n    = warp_n * 16 + ((lane & 16) ? 8 : 0);

    float accX[2][2][4], accY[2][2][4];
    #pragma unroll
    for (int i = 0; i < 2; i++)
        #pragma unroll
        for (int j = 0; j < 2; j++)
            #pragma unroll
            for (int q = 0; q < 4; q++) { accX[i][j][q] = 0.0f; accY[i][j][q] = 0.0f; }

    #pragma unroll
    for (int ks = 0; ks < 7; ks++) {
        uint32_t AXh[2][4], AXl[2][4], AYh[2][4], AYl[2][4], Bh[4], Bl[4];
        #pragma unroll
        for (int mi = 0; mi < 2; mi++) {
            uint32_t ao = (uint32_t)((a_row + mi * 16) * AF_S + ks * 16 + a_kadd) * 2u;
            ldsm_x4(dyn32 + OF_AXH * 2u + ao, AXh[mi]);
            ldsm_x4(dyn32 + OF_AXL * 2u + ao, AXl[mi]);
            ldsm_x4(dyn32 + OF_AYH * 2u + ao, AYh[mi]);
            ldsm_x4(dyn32 + OF_AYL * 2u + ao, AYl[mi]);
        }
        {
            uint32_t bo = (uint32_t)((b_k + ks * 16) * BF_S + b_n) * 2u;
            ldsm_x4_t(dyn32 + OF_BH * 2u + bo, Bh);
            ldsm_x4_t(dyn32 + OF_BL * 2u + bo, Bl);
        }
        #pragma unroll
        for (int mi = 0; mi < 2; mi++)
            #pragma unroll
            for (int nj = 0; nj < 2; nj++) {
                const int hf = nj * 2;
                mma_bf16(accX[mi][nj], AXh[mi], Bh[hf], Bh[hf + 1]);
                mma_bf16(accX[mi][nj], AXh[mi], Bl[hf], Bl[hf + 1]);
                mma_bf16(accX[mi][nj], AXl[mi], Bh[hf], Bh[hf + 1]);
                mma_bf16(accY[mi][nj], AYh[mi], Bh[hf], Bh[hf + 1]);
                mma_bf16(accY[mi][nj], AYh[mi], Bl[hf], Bl[hf + 1]);
                mma_bf16(accY[mi][nj], AYl[mi], Bh[hf], Bh[hf + 1]);
            }
    }

    const float LOG2E  = 1.4426950408889634f;
    const float ep     = 1.0f / (1.0f + __expf(-eps_p[0]));
    const float is2    = LOG2E / (sig_p[0]  * sig_p[0]);
    const float is0    = LOG2E / (sig0_p[0] * sig0_p[0]);
    const float cstv   = cst_p[0];
    const float one_ep = 1.0f - ep;

    #pragma unroll
    for (int mi = 0; mi < 2; mi++)
        #pragma unroll
        for (int nj = 0; nj < 2; nj++)
            #pragma unroll
            for (int q = 0; q < 4; q++) {
                int rl = warp_m * 32 + mi * 16 + (lane >> 2) + (q >> 1) * 8;
                int cl = warp_n * 16 + nj * 8 + (lane & 3) * 2 + (q & 1);
                float Dx = fmaxf(nfx[rl] + nfv[cl] - 2.0f * accX[mi][nj][q], 0.0f);
                float Dy = fmaxf(nfy[rl] + nfv[cl] - 2.0f * accY[mi][nj][q], 0.0f);
                accX[mi][nj][q] = fmaf(one_ep, fexp2(-Dx * is0), ep);
                accY[mi][nj][q] = fmaf(one_ep, fexp2(-Dy * is0), ep);
            }

    float gX[2][2][4], gY[2][2][4];
    #pragma unroll
    for (int i = 0; i < 2; i++)
        #pragma unroll
        for (int j = 0; j < 2; j++)
            #pragma unroll
            for (int q = 0; q < 4; q++) { gX[i][j][q] = 0.0f; gY[i][j][q] = 0.0f; }

    #pragma unroll
    for (int ks = 0; ks < 2; ks++) {
        uint32_t AXh[2][4], AXl[2][4], AYh[2][4], AYl[2][4], Bh[4], Bl[4];
        #pragma unroll
        for (int mi = 0; mi < 2; mi++) {
            uint32_t ao = (uint32_t)((a_row + mi * 16) * AG_S + ks * 16 + a_kadd) * 2u;
            ldsm_x4(dyn32 + OG_AXH * 2u + ao, AXh[mi]);
            ldsm_x4(dyn32 + OG_AXL * 2u + ao, AXl[mi]);
            ldsm_x4(dyn32 + OG_AYH * 2u + ao, AYh[mi]);
            ldsm_x4(dyn32 + OG_AYL * 2u + ao, AYl[mi]);
        }
        {
            uint32_t bo = (uint32_t)((b_k + ks * 16) * BF_S + b_n) * 2u;
            ldsm_x4_t(dyn32 + OG_BH * 2u + bo, Bh);
            ldsm_x4_t(dyn32 + OG_BL * 2u + bo, Bl);
        }
        #pragma unroll
        for (int mi = 0; mi < 2; mi++)
            #pragma unroll
            for (int nj = 0; nj < 2; nj++) {
                const int hf = nj * 2;
                mma_bf16(gX[mi][nj], AXh[mi], Bh[hf], Bh[hf + 1]);
                mma_bf16(gX[mi][nj], AXh[mi], Bl[hf], Bl[hf + 1]);
                mma_bf16(gX[mi][nj], AXl[mi], Bh[hf], Bh[hf + 1]);
                mma_bf16(gY[mi][nj], AYh[mi], Bh[hf], Bh[hf + 1]);
                mma_bf16(gY[mi][nj], AYh[mi], Bl[hf], Bl[hf + 1]);
                mma_bf16(gY[mi][nj], AYl[mi], Bh[hf], Bh[hf + 1]);
            }
    }

    const float RS = 0.03125f;
    float csum[4];
    #pragma unroll
    for (int i = 0; i < 4; i++) csum[i] = 0.0f;
    float qacc = 0.0f;

    #pragma unroll
    for (int mi = 0; mi < 2; mi++)
        #pragma unroll
        for (int nj = 0; nj < 2; nj++) {
            float vq[4];
            #pragma unroll
            for (int q = 0; q < 4; q++) {
                int rl = warp_m * 32 + mi * 16 + (lane >> 2) + (q >> 1) * 8;
                int cl = warp_n * 16 + nj * 8 + (lane & 3) * 2 + (q & 1);
                float Dgx = fmaxf(ngx[rl] + ngv[cl] - 2.0f * gX[mi][nj][q], 0.0f);
                float Dgy = fmaxf(ngy[rl] + ngv[cl] - 2.0f * gY[mi][nj][q], 0.0f);
                float KX = cstv * accX[mi][nj][q] * fexp2(-Dgx * is2);
                float KY = cstv * accY[mi][nj][q] * fexp2(-Dgy * is2);
                float v = (KX - KY) * RS;
                vq[q] = v;
                csum[nj * 2 + (q & 1)] += v;
                qacc += v * v;
            }
            int colg = jbase + warp_n * 16 + nj * 8 + (lane & 3) * 2;
            int row0 = ibase + warp_m * 32 + mi * 16 + (lane >> 2);
            *(__nv_bfloat162*)&g_fmb[(size_t)row0 * JC + colg] =
                __floats2bfloat162_rn(vq[0], vq[1]);
            *(__nv_bfloat162*)&g_fmb[(size_t)(row0 + 8) * JC + colg] =
                __floats2bfloat162_rn(vq[2], vq[3]);
        }

    #pragma unroll
    for (int off = 16; off >= 4; off >>= 1)
        #pragma unroll
        for (int c4 = 0; c4 < 4; c4++)
            csum[c4] += __shfl_down_sync(0xffffffffu, csum[c4], off);
    if (lane < 4) {
        #pragma unroll
        for (int c4 = 0; c4 < 4; c4++) {
            int cl = warp_n * 16 + (c4 >> 1) * 8 + lane * 2 + (c4 & 1);
            atomicAdd(&scs[cl], csum[c4]);
        }
    }
    #pragma unroll
    for (int off = 16; off; off >>= 1)
        qacc += __shfl_xor_sync(0xffffffffu, qacc, off);
    if (lane == 0) red16[wid] = qacc;
    __syncthreads();

    if (tid < 128) atomicAdd(&g_colsum[jbase + tid], scs[tid]);
    if (wid == 0) {
        float v = (lane < 16) ? red16[lane] : 0.0f;
        #pragma unroll
        for (int off = 8; off; off >>= 1)
            v += __shfl_xor_sync(0xffffffffu, v, off);
        if (lane == 0) atomicAdd(&g_scal[0], v);
    }
}

// ---------------- mu + sum(mu^2) ----------------------------------------------
__global__ void mu_kernel() {
    __shared__ float red[JC];
    int j = threadIdx.x;
    float m = g_colsum[j] * (1.0f / (float)NXC);
    g_mu[j] = m;
    red[j] = m * m;
    __syncthreads();
    for (int s = 512; s; s >>= 1) {
        if (j < s) red[j] += red[j + s];
        __syncthreads();
    }
    if (j == 0) g_scal[2] = red[0];
}

// ---------------- s_i = fm[i]·mu (bf16 fm) ; accumulate s_i^2 -----------------
__global__ __launch_bounds__(256) void s2_kernel() {
    __shared__ float smu[JC];
    int tid = threadIdx.x;
    for (int e = tid; e < JC; e += 256) smu[e] = g_mu[e];
    __syncthreads();
    int row  = blockIdx.x * 8 + (tid >> 5);
    int lane = tid & 31;
    const __nv_bfloat16* rp = g_fmb + (size_t)row * JC;
    float s = 0.0f;
    #pragma unroll
    for (int t = 0; t < 4; t++) {
        int c = lane * 8 + 256 * t;
        uint4 v = *(const uint4*)(rp + c);
        const __nv_bfloat16* pv = (const __nv_bfloat16*)&v;
        #pragma unroll
        for (int e = 0; e < 8; e++)
            s += __bfloat162float(pv[e]) * smu[c + e];
    }
    #pragma unroll
    for (int o = 16; o; o >>= 1) s += __shfl_xor_sync(0xffffffffu, s, o);
    if (lane == 0) atomicAdd(&g_scal[1], s * s);
}

// ---------------- finalize ------------------------------------------------------
__global__ void finalize_kernel(float* out) {
    double sumfm2 = (double)g_scal[0];
    double sums2  = (double)g_scal[1];
    double summu2 = (double)g_scal[2];
    double nx = (double)NXC;
    double t1 = summu2 * (nx / (nx - 1.0));
    double t2 = sumfm2 / nx / (nx - 1.0);
    double mean = t1 - t2;
    double var  = 4.0 * (sums2 / nx) - 4.0 * summu2 * summu2;
    out[0] = (float)(-(mean / sqrt(var + 1e-6)));
}

// ---------------- launch ---------------------------------------------------------
extern "C" void kernel_launch(void* const* d_in, const int* in_sizes, int n_in,
                              void* d_out, int out_size)
{
    const float* XY = (const float*)d_in[0];
    const float* V  = (const float*)d_in[1];
    const float *dnW[6], *dnb[6], *anW[6], *anb[6];
    for (int i = 0; i < 6; i++) {
        dnW[i] = (const float*)d_in[2 + 2 * i];
        dnb[i] = (const float*)d_in[3 + 2 * i];
        anW[i] = (const float*)d_in[14 + 2 * i];
        anb[i] = (const float*)d_in[15 + 2 * i];
    }
    const float* eps   = (const float*)d_in[26];
    const float* sig   = (const float*)d_in[27];
    const float* sig0  = (const float*)d_in[28];
    const float* cstp  = (const float*)d_in[29];

    float *in0, *nF, *nG;
    __nv_bfloat16 *inh, *inl, *h0, *l0, *h1, *l1, *b0h, *b0l, *b1h, *b1l;
    __nv_bfloat16 *Wh, *Wl, *Fh, *Fl, *Gh, *Gl;
    cudaGetSymbolAddress((void**)&in0, g_in0);
    cudaGetSymbolAddress((void**)&nF,  g_nF);
    cudaGetSymbolAddress((void**)&nG,  g_nG);
    cudaGetSymbolAddress((void**)&inh, g_inh);
    cudaGetSymbolAddress((void**)&inl, g_inl);
    cudaGetSymbolAddress((void**)&h0,  g_Ah0);
    cudaGetSymbolAddress((void**)&l0,  g_Al0);
    cudaGetSymbolAddress((void**)&h1,  g_Ah1);
    cudaGetSymbolAddress((void**)&l1,  g_Al1);
    cudaGetSymbolAddress((void**)&b0h, g_Bh0);
    cudaGetSymbolAddress((void**)&b0l, g_Bl0);
    cudaGetSymbolAddress((void**)&b1h, g_Bh1);
    cudaGetSymbolAddress((void**)&b1l, g_Bl1);
    cudaGetSymbolAddress((void**)&Wh,  g_Wh);
    cudaGetSymbolAddress((void**)&Wl,  g_Wl);
    cudaGetSymbolAddress((void**)&Fh,  g_Fh);
    cudaGetSymbolAddress((void**)&Fl,  g_Fl);
    cudaGetSymbolAddress((void**)&Gh,  g_Gh);
    cudaGetSymbolAddress((void**)&Gl,  g_Gl);

    const int GY = NTOT / BMM;     // 520
    const dim3 blk(256);

    prep_in_kernel<<<(NTOT * 32 + 255) / 256, 256>>>(XY, V);
    pad_all_kernel<<<(NTOT * 20 + 255) / 256, 256>>>();
    init_acc_kernel<<<1, 1024>>>();

    WPrepArgs wa;
    for (int i = 0; i < 6; i++) {
        wa.W[i]     = dnW[i];  wa.W[i + 6] = anW[i];
        wa.Fi[i]    = (i == 0) ? DIMC : HC;
        wa.Fi[i+6]  = (i == 0) ? DIMC : HC;
        wa.Fo[i]    = (i == 5) ? FD : HC;
        wa.Fo[i+6]  = (i == 5) ? GD : HC;
    }
    prep_w_all<<<dim3((WOFF + 255) / 256, 12), 256>>>(wa);

    cudaFuncSetAttribute(mma_gemm3, cudaFuncAttributeMaxDynamicSharedMemorySize,
                         GEMM_SMEM_BYTES);
    const dim3 gH(5, GY, 2);
    const dim3 gL5(2, GY, 2);

    #define GEMM3(grid, AhD,AlD,AhA,AlA, PWa, L, bD,bA, FoD,FoA, ChD,ClD,ChA,ClA, PWcD,PWcA, resA, nC, relu) \
        mma_gemm3<<<grid, blk, GEMM_SMEM_BYTES>>>(AhD,AlD,AhA,AlA, PWa, Wh, Wl, L, \
            bD,bA, FoD,FoA, ChD,ClD,ChA,ClA, PWcD,PWcA, resA, nC, relu)

    GEMM3(gH, inh,inl, inh,inl, 32, 0, dnb[0],anb[0], HC,HC, h0,l0, b0h,b0l, PWH,PWH, (const float*)0, 1, 1);
    GEMM3(gH, h0,l0, b0h,b0l, PWH, 1, dnb[1],anb[1], HC,HC, h1,l1, b1h,b1l, PWH,PWH, (const float*)0, 10, 1);
    GEMM3(gH, h1,l1, b1h,b1l, PWH, 2, dnb[2],anb[2], HC,HC, h0,l0, b0h,b0l, PWH,PWH, (const float*)0, 10, 1);
    GEMM3(gH, h0,l0, b0h,b0l, PWH, 3, dnb[3],anb[3], HC,HC, h1,l1, b1h,b1l, PWH,PWH, (const float*)0, 10, 1);
    GEMM3(gH, h1,l1, b1h,b1l, PWH, 4, dnb[4],anb[4], HC,HC, h0,l0, b0h,b0l, PWH,PWH, (const float*)0, 10, 1);
    GEMM3(gL5, h0,l0, b0h,b0l, PWH, 5, dnb[5],anb[5], FD,GD, Fh,Fl, Gh,Gl, FDP,GDP, in0, 10, 0);

    transpose_v_kernel<<<(FDP * JC + 255) / 256, 256>>>();
    row_norms_hl<<<NTOT / 8, 256>>>(Fh, Fl, nF, FDP);
    row_norms_hl<<<NTOT / 8, 256>>>(Gh, Gl, nG, GDP);

    cudaFuncSetAttribute(fm3_kernel, cudaFuncAttributeMaxDynamicSharedMemorySize,
                         FM_DYN_BYTES);
    fm3_kernel<<<dim3(JC / FMJ, NXC / FMI), 512, FM_DYN_BYTES>>>(eps, sig, sig0, cstp);

    mu_kernel<<<1, JC>>>();
    s2_kernel<<<NXC / 8, 256>>>();
    finalize_kernel<<<1, 1>>>((float*)d_out);
}

// round 12
// speedup vs baseline: 1.1491x; 1.0003x over previous
#include <cuda_runtime.h>
#include <cuda_bf16.h>
#include <math.h>
#include <stdint.h>

// Problem constants
#define NXC   32768
#define NTOT  66560
#define DIMC  28
#define HC    300
#define FD    100
#define GD    28
#define JC    1024

#define PWH   320
#define FDP   112
#define GDP   32
#define WOFF  (320 * 320)

// ---------------- scratch ----------------------------------------------------
__device__ float g_in0 [(size_t)NTOT * DIMC];
__device__ __align__(16) __nv_bfloat16 g_inh[(size_t)NTOT * 32];
__device__ __align__(16) __nv_bfloat16 g_inl[(size_t)NTOT * 32];
__device__ __align__(16) __nv_bfloat16 g_Ah0[(size_t)NTOT * PWH];
__device__ __align__(16) __nv_bfloat16 g_Al0[(size_t)NTOT * PWH];
__device__ __align__(16) __nv_bfloat16 g_Ah1[(size_t)NTOT * PWH];
__device__ __align__(16) __nv_bfloat16 g_Al1[(size_t)NTOT * PWH];
__device__ __align__(16) __nv_bfloat16 g_Bh0[(size_t)NTOT * PWH];
__device__ __align__(16) __nv_bfloat16 g_Bl0[(size_t)NTOT * PWH];
__device__ __align__(16) __nv_bfloat16 g_Bh1[(size_t)NTOT * PWH];
__device__ __align__(16) __nv_bfloat16 g_Bl1[(size_t)NTOT * PWH];
__device__ __align__(16) __nv_bfloat16 g_Wh[12 * WOFF];
__device__ __align__(16) __nv_bfloat16 g_Wl[12 * WOFF];
__device__ __align__(16) __nv_bfloat16 g_Fh[(size_t)NTOT * FDP];
__device__ __align__(16) __nv_bfloat16 g_Fl[(size_t)NTOT * FDP];
__device__ __align__(16) __nv_bfloat16 g_Gh[(size_t)NTOT * GDP];
__device__ __align__(16) __nv_bfloat16 g_Gl[(size_t)NTOT * GDP];
__device__ __align__(16) __nv_bfloat16 g_FvTh[FDP * JC];
__device__ __align__(16) __nv_bfloat16 g_FvTl[FDP * JC];
__device__ __align__(16) __nv_bfloat16 g_GvTh[GDP * JC];
__device__ __align__(16) __nv_bfloat16 g_GvTl[GDP * JC];
__device__ float g_nF  [NTOT];
__device__ float g_nG  [NTOT];
__device__ __align__(16) __nv_bfloat16 g_fmb[(size_t)NXC * JC];   // bf16 fm (s2 only)
__device__ float g_colsum[JC];
__device__ float g_mu    [JC];
__device__ float g_scal  [8];

__device__ __forceinline__ void split2(float x, __nv_bfloat16& h, __nv_bfloat16& l) {
    h = __float2bfloat16(x);
    l = __float2bfloat16(x - __bfloat162float(h));
}
__device__ __forceinline__ float fexp2(float x) {
    float r;
    asm("ex2.approx.ftz.f32 %0, %1;" : "=f"(r) : "f"(x));
    return r;
}

// ---------------- prep kernels ----------------------------------------------
__global__ void prep_in_kernel(const float* __restrict__ XY, const float* __restrict__ V) {
    int t = blockIdx.x * blockDim.x + threadIdx.x;
    if (t >= NTOT * 32) return;
    int r = t >> 5, c = t & 31;
    float v = 0.0f;
    if (c < DIMC) {
        int idx = r * DIMC + c;
        v = (r < 2 * NXC) ? XY[idx] : V[(r - 2 * NXC) * DIMC + c];
        g_in0[idx] = v;
    }
    __nv_bfloat16 h, l; split2(v, h, l);
    g_inh[t] = h; g_inl[t] = l;
}
__global__ void pad_all_kernel() {
    int t = blockIdx.x * blockDim.x + threadIdx.x;
    if (t >= NTOT * 20) return;
    int r = t / 20, c = t % 20;
    __nv_bfloat16 z = __float2bfloat16(0.0f);
    size_t o = (size_t)r * PWH + HC + c;
    g_Ah0[o] = z; g_Al0[o] = z; g_Ah1[o] = z; g_Al1[o] = z;
    g_Bh0[o] = z; g_Bl0[o] = z; g_Bh1[o] = z; g_Bl1[o] = z;
    if (c < 12) {
        size_t of = (size_t)r * FDP + 100 + c;
        g_Fh[of] = z; g_Fl[of] = z;
    }
    if (c < 4) {
        size_t og = (size_t)r * GDP + 28 + c;
        g_Gh[og] = z; g_Gl[og] = z;
    }
}
__global__ void init_acc_kernel() {
    int t = threadIdx.x;
    if (t < JC) g_colsum[t] = 0.0f;
    if (t < 8)  g_scal[t]   = 0.0f;
}
struct WPrepArgs {
    const float* W[12];
    int Fi[12];
    int Fo[12];
};
__global__ void prep_w_all(WPrepArgs a) {
    int layer = blockIdx.y;
    int idx = blockIdx.x * blockDim.x + threadIdx.x;
    if (idx >= WOFF) return;
    int k = idx / 320, n = idx - k * 320;
    int Fi = a.Fi[layer], Fo = a.Fo[layer];
    float v = (k < Fi && n < Fo) ? a.W[layer][(size_t)k * Fo + n] : 0.0f;
    __nv_bfloat16 h, l; split2(v, h, l);
    g_Wh[(size_t)layer * WOFF + idx] = h;
    g_Wl[(size_t)layer * WOFF + idx] = l;
}
__global__ void transpose_v_kernel() {
    int t = blockIdx.x * blockDim.x + threadIdx.x;
    if (t < FDP * JC) {
        int k = t >> 10, j = t & 1023;
        size_t src = (size_t)(2 * NXC + j) * FDP + k;
        g_FvTh[t] = g_Fh[src];
        g_FvTl[t] = g_Fl[src];
    }
    if (t < GDP * JC) {
        int k = t >> 10, j = t & 1023;
        size_t src = (size_t)(2 * NXC + j) * GDP + k;
        g_GvTh[t] = g_Gh[src];
        g_GvTl[t] = g_Gl[src];
    }
}

// =============== shared MMA helpers ==========================================
__device__ __forceinline__ uint32_t smem_u32(const void* p) {
    uint32_t a;
    asm("{ .reg .u64 t; cvta.to.shared.u64 t, %1; cvt.u32.u64 %0, t; }" : "=r"(a) : "l"(p));
    return a;
}
__device__ __forceinline__ void ldsm_x4(uint32_t addr, uint32_t r[4]) {
    asm volatile("ldmatrix.sync.aligned.m8n8.x4.shared.b16 {%0,%1,%2,%3}, [%4];"
        : "=r"(r[0]), "=r"(r[1]), "=r"(r[2]), "=r"(r[3]) : "r"(addr));
}
__device__ __forceinline__ void ldsm_x4_t(uint32_t addr, uint32_t r[4]) {
    asm volatile("ldmatrix.sync.aligned.m8n8.x4.trans.shared.b16 {%0,%1,%2,%3}, [%4];"
        : "=r"(r[0]), "=r"(r[1]), "=r"(r[2]), "=r"(r[3]) : "r"(addr));
}
// NOTE: non-volatile — mma.sync has pure register semantics; lets ptxas
// software-pipeline MMAs with subsequent ldsm instead of source order.
__device__ __forceinline__ void mma_bf16(float c[4], const uint32_t a[4],
                                         uint32_t b0, uint32_t b1) {
    asm("mma.sync.aligned.m16n8k16.row.col.f32.bf16.bf16.f32 "
        "{%0,%1,%2,%3}, {%4,%5,%6,%7}, {%8,%9}, {%0,%1,%2,%3};"
        : "+f"(c[0]), "+f"(c[1]), "+f"(c[2]), "+f"(c[3])
        : "r"(a[0]), "r"(a[1]), "r"(a[2]), "r"(a[3]), "r"(b0), "r"(b1));
}
#define CP_ASYNC16(dst_u32, src_ptr) \
    asm volatile("cp.async.cg.shared.global [%0], [%1], 16;" \
        :: "r"(dst_u32), "l"(src_ptr) : "memory")
#define CP_COMMIT() asm volatile("cp.async.commit_group;" ::: "memory")
#define CP_WAIT(n)  asm volatile("cp.async.wait_group %0;" :: "n"(n) : "memory")

// =============== bf16-split GEMM: 3-stage, single sync per chunk =============
#define BMM 128
#define BNN 64
#define BKK 32
#define A_STRIDE 40
#define B_STRIDE 72
#define SM_AH 0
#define SM_AL 15360
#define SM_BH 30720
#define SM_BL 37632
#define GEMM_SMEM_BYTES 89088

__global__ __launch_bounds__(256, 2)
void mma_gemm3(const __nv_bfloat16* __restrict__ AhD, const __nv_bfloat16* __restrict__ AlD,
               const __nv_bfloat16* __restrict__ AhA, const __nv_bfloat16* __restrict__ AlA,
               int PWa,
               const __nv_bfloat16* __restrict__ WhB, const __nv_bfloat16* __restrict__ WlB,
               int layer,
               const float* __restrict__ biasD, const float* __restrict__ biasA,
               int FoD, int FoA,
               __nv_bfloat16* __restrict__ ChD, __nv_bfloat16* __restrict__ ClD,
               __nv_bfloat16* __restrict__ ChA, __nv_bfloat16* __restrict__ ClA,
               int PWcD, int PWcA,
               const float* __restrict__ resA,
               int nC, int doRelu)
{
    extern __shared__ __nv_bfloat16 dyn[];

    const int net = blockIdx.z;
    const __nv_bfloat16* Ah = net ? AhA : AhD;
    const __nv_bfloat16* Al = net ? AlA : AlD;
    const __nv_bfloat16* Wh = WhB + (size_t)(layer + 6 * net) * WOFF;
    const __nv_bfloat16* Wl = WlB + (size_t)(layer + 6 * net) * WOFF;
    const float* bias = net ? biasA : biasD;
    const int Fo  = net ? FoA : FoD;
    __nv_bfloat16* Ch = net ? ChA : ChD;
    __nv_bfloat16* Cl = net ? ClA : ClD;
    const int PWc = net ? PWcA : PWcD;
    const float* res = net ? resA : (const float*)0;

    const int n0 = blockIdx.x * BNN;
    if (n0 >= Fo) return;

    const int tid    = threadIdx.x;
    const int lane   = tid & 31;
    const int wid    = tid >> 5;
    const int warp_m = wid >> 1;
    const int warp_n = wid & 1;
    const int rbase  = blockIdx.y * BMM;

    const int a_row0 = tid >> 2;
    const int a_kk   = (tid & 3) * 8;
    const int bk     = tid >> 3;
    const int bn     = (tid & 7) * 8;

    const uint32_t dyn32 = smem_u32(dyn);
    const int a_row  = warp_m * 32 + (lane & 15);
    const int a_kadd = (lane >> 4) * 8;
    const uint32_t aHiB = dyn32 + (uint32_t)(SM_AH + a_row * A_STRIDE + a_kadd) * 2u;
    const uint32_t aLoB = dyn32 + (uint32_t)(SM_AL + a_row * A_STRIDE + a_kadd) * 2u;
    const int b_k = (lane & 7) + ((lane & 8) ? 8 : 0);
    const int b_n = warp_n * 32 + ((lane & 16) ? 8 : 0);
    const uint32_t bHiB = dyn32 + (uint32_t)(SM_BH + b_k * B_STRIDE + b_n) * 2u;
    const uint32_t bLoB = dyn32 + (uint32_t)(SM_BL + b_k * B_STRIDE + b_n) * 2u;

    const uint32_t dA0 = dyn32 + (uint32_t)(a_row0 * A_STRIDE + a_kk) * 2u;
    const uint32_t dB0 = dyn32 + (uint32_t)(SM_BH + bk * B_STRIDE + bn) * 2u;

    float acc[2][4][4];
    #pragma unroll
    for (int i = 0; i < 2; i++)
        #pragma unroll
        for (int j = 0; j < 4; j++)
            #pragma unroll
            for (int q = 0; q < 4; q++) acc[i][j][q] = 0.0f;

    #define ISSUE_CHUNK(k0, bf) do { \
        uint32_t od = (uint32_t)(bf) * 10240u; \
        uint32_t ob = (uint32_t)(bf) * 4608u; \
        size_t o0 = (size_t)(rbase + a_row0) * PWa + (k0) + a_kk; \
        size_t o1 = (size_t)(rbase + a_row0 + 64) * PWa + (k0) + a_kk; \
        uint32_t d1 = dA0 + od + (uint32_t)(64 * A_STRIDE) * 2u; \
        CP_ASYNC16(dA0 + od,           Ah + o0); \
        CP_ASYNC16(dA0 + od + 30720u,  Al + o0); \
        CP_ASYNC16(d1,                 Ah + o1); \
        CP_ASYNC16(d1 + 30720u,        Al + o1); \
        size_t bo = (size_t)((k0) + bk) * 320 + n0 + bn; \
        CP_ASYNC16(dB0 + ob,           Wh + bo); \
        CP_ASYNC16(dB0 + ob + 13824u,  Wl + bo); \
        CP_COMMIT(); \
    } while (0)

    ISSUE_CHUNK(0, 0);
    if (nC > 1) ISSUE_CHUNK(32, 1);

    for (int c = 0; c < nC; c++) {
        const int buf = c % 3;
        const uint32_t aOff = (uint32_t)buf * 10240u;
        const uint32_t bOff = (uint32_t)buf * 4608u;

        if (c + 1 < nC) { CP_WAIT(1); } else { CP_WAIT(0); }
        __syncthreads();

        #pragma unroll
        for (int ks = 0; ks < 2; ks++) {
            uint32_t Ahr[2][4], Alr[2][4], Bhr[2][4], Blr[2][4];
            #pragma unroll
            for (int mi = 0; mi < 2; mi++) {
                uint32_t off = aOff + (uint32_t)(mi * 16 * A_STRIDE + ks * 16) * 2u;
                ldsm_x4(aHiB + off, Ahr[mi]);
                ldsm_x4(aLoB + off, Alr[mi]);
            }
            #pragma unroll
            for (int np = 0; np < 2; np++) {
                uint32_t off = bOff + (uint32_t)(np * 16 + ks * 16 * B_STRIDE) * 2u;
                ldsm_x4_t(bHiB + off, Bhr[np]);
                ldsm_x4_t(bLoB + off, Blr[np]);
            }
            #pragma unroll
            for (int mi = 0; mi < 2; mi++)
                #pragma unroll
                for (int nj = 0; nj < 4; nj++) {
                    const int np = nj >> 1, hf = (nj & 1) * 2;
                    mma_bf16(acc[mi][nj], Ahr[mi], Bhr[np][hf], Bhr[np][hf + 1]);
                    mma_bf16(acc[mi][nj], Ahr[mi], Blr[np][hf], Blr[np][hf + 1]);
                    mma_bf16(acc[mi][nj], Alr[mi], Bhr[np][hf], Bhr[np][hf + 1]);
                }
        }

        if (c + 2 < nC) ISSUE_CHUNK((c + 2) * BKK, (c + 2) % 3);
    }
    #undef ISSUE_CHUNK

    // epilogue — writes bf16 hi/lo at stride PWc
    #pragma unroll
    for (int mi = 0; mi < 2; mi++)
        #pragma unroll
        for (int nj = 0; nj < 4; nj++) {
            int col = n0 + warp_n * 32 + nj * 8 + (lane & 3) * 2;
            if (col >= Fo) continue;
            float2 b2 = *(const float2*)(bias + col);
            #pragma unroll
            for (int half = 0; half < 2; half++) {
                int row = rbase + warp_m * 32 + mi * 16 + (lane >> 2) + half * 8;
                float vx = acc[mi][nj][half * 2 + 0] + b2.x;
                float vy = acc[mi][nj][half * 2 + 1] + b2.y;
                if (res) {
                    float2 r2 = *(const float2*)(res + (size_t)row * Fo + col);
                    vx += r2.x; vy += r2.y;
                }
                if (doRelu) { vx = fmaxf(vx, 0.0f); vy = fmaxf(vy, 0.0f); }
                __nv_bfloat16 hx, lx, hy, ly;
                split2(vx, hx, lx); split2(vy, hy, ly);
                *(__nv_bfloat162*)(Ch + (size_t)row * PWc + col) = __halves2bfloat162(hx, hy);
                *(__nv_bfloat162*)(Cl + (size_t)row * PWc + col) = __halves2bfloat162(lx, ly);
            }
        }
}

// ---------------- row squared norms from hi/lo bf16 --------------------------
__global__ void row_norms_hl(const __nv_bfloat16* __restrict__ H,
                             const __nv_bfloat16* __restrict__ L,
                             float* __restrict__ out, int D)
{
    int warp = (blockIdx.x * blockDim.x + threadIdx.x) >> 5;
    int lane = threadIdx.x & 31;
    if (warp >= NTOT) return;
    float s = 0.0f;
    for (int k = lane; k < D; k += 32) {
        size_t o = (size_t)warp * D + k;
        float v = __bfloat162float(H[o]) + __bfloat162float(L[o]);
        s += v * v;
    }
    #pragma unroll
    for (int o = 16; o; o >>= 1) s += __shfl_xor_sync(0xffffffffu, s, o);
    if (lane == 0) out[warp] = s;
}

// ---------------- fused fm kernel: disjoint smem, single sync ----------------
#define FMI 64
#define FMJ 128
#define AF_S 120
#define BF_S 136
#define AG_S 40
#define OF_AXH 0
#define OF_AXL 7680
#define OF_AYH 15360
#define OF_AYL 23040
#define OF_BH  30720
#define OF_BL  45952
#define OG_AXH 61184
#define OG_AXL 63744
#define OG_AYH 66304
#define OG_AYL 68864
#define OG_BH  71424
#define OG_BL  75776
#define FM_DYN_BYTES (80128 * 2)

__global__ __launch_bounds__(512)
void fm3_kernel(const float* __restrict__ eps_p, const float* __restrict__ sig_p,
                const float* __restrict__ sig0_p, const float* __restrict__ cst_p)
{
    extern __shared__ __nv_bfloat16 dynb[];
    __shared__ float nfx[64], nfy[64], ngx[64], ngy[64];
    __shared__ float nfv[128], ngv[128];
    __shared__ float scs[128];
    __shared__ float red16[16];

    const int tid    = threadIdx.x;
    const int lane   = tid & 31;
    const int wid    = tid >> 5;
    const int warp_m = wid >> 3;
    const int warp_n = wid & 7;
    const int ibase  = blockIdx.y * FMI;
    const int jbase  = blockIdx.x * FMJ;
    const int XR = ibase, YR = NXC + ibase, VR = 2 * NXC + jbase;

    if (tid < 64) {
        nfx[tid] = g_nF[XR + tid]; nfy[tid] = g_nF[YR + tid];
        ngx[tid] = g_nG[XR + tid]; ngy[tid] = g_nG[YR + tid];
    } else if (tid < 192) {
        int j = tid - 64;
        nfv[j] = g_nF[VR + j]; ngv[j] = g_nG[VR + j];
    } else if (tid < 320) {
        scs[tid - 192] = 0.0f;
    }

    for (int e = tid; e < 896; e += 512) {
        int r = e / 14, kv = (e % 14) * 8;
        *(uint4*)&dynb[OF_AXH + r * AF_S + kv] = *(const uint4*)&g_Fh[(size_t)(XR + r) * FDP + kv];
        *(uint4*)&dynb[OF_AXL + r * AF_S + kv] = *(const uint4*)&g_Fl[(size_t)(XR + r) * FDP + kv];
        *(uint4*)&dynb[OF_AYH + r * AF_S + kv] = *(const uint4*)&g_Fh[(size_t)(YR + r) * FDP + kv];
        *(uint4*)&dynb[OF_AYL + r * AF_S + kv] = *(const uint4*)&g_Fl[(size_t)(YR + r) * FDP + kv];
    }
    for (int e = tid; e < 1792; e += 512) {
        int k = e >> 4, jv = (e & 15) * 8;
        *(uint4*)&dynb[OF_BH + k * BF_S + jv] = *(const uint4*)&g_FvTh[k * 1024 + jbase + jv];
        *(uint4*)&dynb[OF_BL + k * BF_S + jv] = *(const uint4*)&g_FvTl[k * 1024 + jbase + jv];
    }
    if (tid < 256) {
        int r = tid >> 2, kv = (tid & 3) * 8;
        *(uint4*)&dynb[OG_AXH + r * AG_S + kv] = *(const uint4*)&g_Gh[(size_t)(XR + r) * GDP + kv];
        *(uint4*)&dynb[OG_AXL + r * AG_S + kv] = *(const uint4*)&g_Gl[(size_t)(XR + r) * GDP + kv];
        *(uint4*)&dynb[OG_AYH + r * AG_S + kv] = *(const uint4*)&g_Gh[(size_t)(YR + r) * GDP + kv];
        *(uint4*)&dynb[OG_AYL + r * AG_S + kv] = *(const uint4*)&g_Gl[(size_t)(YR + r) * GDP + kv];
    }
    {
        int k = tid >> 4, jv = (tid & 15) * 8;
        *(uint4*)&dynb[OG_BH + k * BF_S + jv] = *(const uint4*)&g_GvTh[k * 1024 + jbase + jv];
        *(uint4*)&dynb[OG_BL + k * BF_S + jv] = *(const uint4*)&g_GvTl[k * 1024 + jbase + jv];
    }
    __syncthreads();

    const uint32_t dyn32 = smem_u32(dynb);
    const int a_row  = warp_m * 32 + (lane & 15);
    const int a_kadd = (lane >> 4) * 8;
    const int b_k    = lane & 15;
    const int b_n    = warp_n * 16 + ((lane & 16) ? 8 : 0);

    float accX[2][2][4], accY[2][2][4];
    #pragma unroll
    for (int i = 0; i < 2; i++)
        #pragma unroll
        for (int j = 0; j < 2; j++)
            #pragma unroll
            for (int q = 0; q < 4; q++) { accX[i][j][q] = 0.0f; accY[i][j][q] = 0.0f; }

    #pragma unroll
    for (int ks = 0; ks < 7; ks++) {
        uint32_t AXh[2][4], AXl[2][4], AYh[2][4], AYl[2][4], Bh[4], Bl[4];
        #pragma unroll
        for (int mi = 0; mi < 2; mi++) {
            uint32_t ao = (uint32_t)((a_row + mi * 16) * AF_S + ks * 16 + a_kadd) * 2u;
            ldsm_x4(dyn32 + OF_AXH * 2u + ao, AXh[mi]);
            ldsm_x4(dyn32 + OF_AXL * 2u + ao, AXl[mi]);
            ldsm_x4(dyn32 + OF_AYH * 2u + ao, AYh[mi]);
            ldsm_x4(dyn32 + OF_AYL * 2u + ao, AYl[mi]);
        }
        {
            uint32_t bo = (uint32_t)((b_k + ks * 16) * BF_S + b_n) * 2u;
            ldsm_x4_t(dyn32 + OF_BH * 2u + bo, Bh);
            ldsm_x4_t(dyn32 + OF_BL * 2u + bo, Bl);
        }
        #pragma unroll
        for (int mi = 0; mi < 2; mi++)
            #pragma unroll
            for (int nj = 0; nj < 2; nj++) {
                const int hf = nj * 2;
                mma_bf16(accX[mi][nj], AXh[mi], Bh[hf], Bh[hf + 1]);
                mma_bf16(accX[mi][nj], AXh[mi], Bl[hf], Bl[hf + 1]);
                mma_bf16(accX[mi][nj], AXl[mi], Bh[hf], Bh[hf + 1]);
                mma_bf16(accY[mi][nj], AYh[mi], Bh[hf], Bh[hf + 1]);
                mma_bf16(accY[mi][nj], AYh[mi], Bl[hf], Bl[hf + 1]);
                mma_bf16(accY[mi][nj], AYl[mi], Bh[hf], Bh[hf + 1]);
            }
    }

    const float LOG2E  = 1.4426950408889634f;
    const float ep     = 1.0f / (1.0f + __expf(-eps_p[0]));
    const float is2    = LOG2E / (sig_p[0]  * sig_p[0]);
    const float is0    = LOG2E / (sig0_p[0] * sig0_p[0]);
    const float cstv   = cst_p[0];
    const float one_ep = 1.0f - ep;

    #pragma unroll
    for (int mi = 0; mi < 2; mi++)
        #pragma unroll
        for (int nj = 0; nj < 2; nj++)
            #pragma unroll
            for (int q = 0; q < 4; q++) {
                int rl = warp_m * 32 + mi * 16 + (lane >> 2) + (q >> 1) * 8;
                int cl = warp_n * 16 + nj * 8 + (lane & 3) * 2 + (q & 1);
                float Dx = fmaxf(nfx[rl] + nfv[cl] - 2.0f * accX[mi][nj][q], 0.0f);
                float Dy = fmaxf(nfy[rl] + nfv[cl] - 2.0f * accY[mi][nj][q], 0.0f);
                accX[mi][nj][q] = fmaf(one_ep, fexp2(-Dx * is0), ep);
                accY[mi][nj][q] = fmaf(one_ep, fexp2(-Dy * is0), ep);
            }

    float gX[2][2][4], gY[2][2][4];
    #pragma unroll
    for (int i = 0; i < 2; i++)
        #pragma unroll
        for (int j = 0; j < 2; j++)
            #pragma unroll
            for (int q = 0; q < 4; q++) { gX[i][j][q] = 0.0f; gY[i][j][q] = 0.0f; }

    #pragma unroll
    for (int ks = 0; ks < 2; ks++) {
        uint32_t AXh[2][4], AXl[2][4], AYh[2][4], AYl[2][4], Bh[4], Bl[4];
        #pragma unroll
        for (int mi = 0; mi < 2; mi++) {
            uint32_t ao = (uint32_t)((a_row + mi * 16) * AG_S + ks * 16 + a_kadd) * 2u;
            ldsm_x4(dyn32 + OG_AXH * 2u + ao, AXh[mi]);
            ldsm_x4(dyn32 + OG_AXL * 2u + ao, AXl[mi]);
            ldsm_x4(dyn32 + OG_AYH * 2u + ao, AYh[mi]);
            ldsm_x4(dyn32 + OG_AYL * 2u + ao, AYl[mi]);
        }
        {
            uint32_t bo = (uint32_t)((b_k + ks * 16) * BF_S + b_n) * 2u;
            ldsm_x4_t(dyn32 + OG_BH * 2u + bo, Bh);
            ldsm_x4_t(dyn32 + OG_BL * 2u + bo, Bl);
        }
        #pragma unroll
        for (int mi = 0; mi < 2; mi++)
            #pragma unroll
            for (int nj = 0; nj < 2; nj++) {
                const int hf = nj * 2;
                mma_bf16(gX[mi][nj], AXh[mi], Bh[hf], Bh[hf + 1]);
                mma_bf16(gX[mi][nj], AXh[mi], Bl[hf], Bl[hf + 1]);
                mma_bf16(gX[mi][nj], AXl[mi], Bh[hf], Bh[hf + 1]);
                mma_bf16(gY[mi][nj], AYh[mi], Bh[hf], Bh[hf + 1]);
                mma_bf16(gY[mi][nj], AYh[mi], Bl[hf], Bl[hf + 1]);
                mma_bf16(gY[mi][nj], AYl[mi], Bh[hf], Bh[hf + 1]);
            }
    }

    const float RS = 0.03125f;
    float csum[4];
    #pragma unroll
    for (int i = 0; i < 4; i++) csum[i] = 0.0f;
    float qacc = 0.0f;

    #pragma unroll
    for (int mi = 0; mi < 2; mi++)
        #pragma unroll
        for (int nj = 0; nj < 2; nj++) {
            float vq[4];
            #pragma unroll
            for (int q = 0; q < 4; q++) {
                int rl = warp_m * 32 + mi * 16 + (lane >> 2) + (q >> 1) * 8;
                int cl = warp_n * 16 + nj * 8 + (lane & 3) * 2 + (q & 1);
                float Dgx = fmaxf(ngx[rl] + ngv[cl] - 2.0f * gX[mi][nj][q], 0.0f);
                float Dgy = fmaxf(ngy[rl] + ngv[cl] - 2.0f * gY[mi][nj][q], 0.0f);
                float KX = cstv * accX[mi][nj][q] * fexp2(-Dgx * is2);
                float KY = cstv * accY[mi][nj][q] * fexp2(-Dgy * is2);
                float v = (KX - KY) * RS;
                vq[q] = v;
                csum[nj * 2 + (q & 1)] += v;
                qacc += v * v;
            }
            int colg = jbase + warp_n * 16 + nj * 8 + (lane & 3) * 2;
            int row0 = ibase + warp_m * 32 + mi * 16 + (lane >> 2);
            *(__nv_bfloat162*)&g_fmb[(size_t)row0 * JC + colg] =
                __floats2bfloat162_rn(vq[0], vq[1]);
            *(__nv_bfloat162*)&g_fmb[(size_t)(row0 + 8) * JC + colg] =
                __floats2bfloat162_rn(vq[2], vq[3]);
        }

    #pragma unroll
    for (int off = 16; off >= 4; off >>= 1)
        #pragma unroll
        for (int c4 = 0; c4 < 4; c4++)
            csum[c4] += __shfl_down_sync(0xffffffffu, csum[c4], off);
    if (lane < 4) {
        #pragma unroll
        for (int c4 = 0; c4 < 4; c4++) {
            int cl = warp_n * 16 + (c4 >> 1) * 8 + lane * 2 + (c4 & 1);
            atomicAdd(&scs[cl], csum[c4]);
        }
    }
    #pragma unroll
    for (int off = 16; off; off >>= 1)
        qacc += __shfl_xor_sync(0xffffffffu, qacc, off);
    if (lane == 0) red16[wid] = qacc;
    __syncthreads();

    if (tid < 128) atomicAdd(&g_colsum[jbase + tid], scs[tid]);
    if (wid == 0) {
        float v = (lane < 16) ? red16[lane] : 0.0f;
        #pragma unroll
        for (int off = 8; off; off >>= 1)
            v += __shfl_xor_sync(0xffffffffu, v, off);
        if (lane == 0) atomicAdd(&g_scal[0], v);
    }
}

// ---------------- mu + sum(mu^2) ----------------------------------------------
__global__ void mu_kernel() {
    __shared__ float red[JC];
    int j = threadIdx.x;
    float m = g_colsum[j] * (1.0f / (float)NXC);
    g_mu[j] = m;
    red[j] = m * m;
    __syncthreads();
    for (int s = 512; s; s >>= 1) {
        if (j < s) red[j] += red[j + s];
        __syncthreads();
    }
    if (j == 0) g_scal[2] = red[0];
}

// ---------------- s_i = fm[i]·mu (bf16 fm) ; accumulate s_i^2 -----------------
__global__ __launch_bounds__(256) void s2_kernel() {
    __shared__ float smu[JC];
    int tid = threadIdx.x;
    for (int e = tid; e < JC; e += 256) smu[e] = g_mu[e];
    __syncthreads();
    int row  = blockIdx.x * 8 + (tid >> 5);
    int lane = tid & 31;
    const __nv_bfloat16* rp = g_fmb + (size_t)row * JC;
    float s = 0.0f;
    #pragma unroll
    for (int t = 0; t < 4; t++) {
        int c = lane * 8 + 256 * t;
        uint4 v = *(const uint4*)(rp + c);
        const __nv_bfloat16* pv = (const __nv_bfloat16*)&v;
        #pragma unroll
        for (int e = 0; e < 8; e++)
            s += __bfloat162float(pv[e]) * smu[c + e];
    }
    #pragma unroll
    for (int o = 16; o; o >>= 1) s += __shfl_xor_sync(0xffffffffu, s, o);
    if (lane == 0) atomicAdd(&g_scal[1], s * s);
}

// ---------------- finalize ------------------------------------------------------
__global__ void finalize_kernel(float* out) {
    double sumfm2 = (double)g_scal[0];
    double sums2  = (double)g_scal[1];
    double summu2 = (double)g_scal[2];
    double nx = (double)NXC;
    double t1 = summu2 * (nx / (nx - 1.0));
    double t2 = sumfm2 / nx / (nx - 1.0);
    double mean = t1 - t2;
    double var  = 4.0 * (sums2 / nx) - 4.0 * summu2 * summu2;
    out[0] = (float)(-(mean / sqrt(var + 1e-6)));
}

// ---------------- launch ---------------------------------------------------------
extern "C" void kernel_launch(void* const* d_in, const int* in_sizes, int n_in,
                              void* d_out, int out_size)
{
    const float* XY = (const float*)d_in[0];
    const float* V  = (const float*)d_in[1];
    const float *dnW[6], *dnb[6], *anW[6], *anb[6];
    for (int i = 0; i < 6; i++) {
        dnW[i] = (const float*)d_in[2 + 2 * i];
        dnb[i] = (const float*)d_in[3 + 2 * i];
        anW[i] = (const float*)d_in[14 + 2 * i];
        anb[i] = (const float*)d_in[15 + 2 * i];
    }
    const float* eps   = (const float*)d_in[26];
    const float* sig   = (const float*)d_in[27];
    const float* sig0  = (const float*)d_in[28];
    const float* cstp  = (const float*)d_in[29];

    float *in0, *nF, *nG;
    __nv_bfloat16 *inh, *inl, *h0, *l0, *h1, *l1, *b0h, *b0l, *b1h, *b1l;
    __nv_bfloat16 *Wh, *Wl, *Fh, *Fl, *Gh, *Gl;
    cudaGetSymbolAddress((void**)&in0, g_in0);
    cudaGetSymbolAddress((void**)&nF,  g_nF);
    cudaGetSymbolAddress((void**)&nG,  g_nG);
    cudaGetSymbolAddress((void**)&inh, g_inh);
    cudaGetSymbolAddress((void**)&inl, g_inl);
    cudaGetSymbolAddress((void**)&h0,  g_Ah0);
    cudaGetSymbolAddress((void**)&l0,  g_Al0);
    cudaGetSymbolAddress((void**)&h1,  g_Ah1);
    cudaGetSymbolAddress((void**)&l1,  g_Al1);
    cudaGetSymbolAddress((void**)&b0h, g_Bh0);
    cudaGetSymbolAddress((void**)&b0l, g_Bl0);
    cudaGetSymbolAddress((void**)&b1h, g_Bh1);
    cudaGetSymbolAddress((void**)&b1l, g_Bl1);
    cudaGetSymbolAddress((void**)&Wh,  g_Wh);
    cudaGetSymbolAddress((void**)&Wl,  g_Wl);
    cudaGetSymbolAddress((void**)&Fh,  g_Fh);
    cudaGetSymbolAddress((void**)&Fl,  g_Fl);
    cudaGetSymbolAddress((void**)&Gh,  g_Gh);
    cudaGetSymbolAddress((void**)&Gl,  g_Gl);

    const int GY = NTOT / BMM;     // 520
    const dim3 blk(256);

    prep_in_kernel<<<(NTOT * 32 + 255) / 256, 256>>>(XY, V);
    pad_all_kernel<<<(NTOT * 20 + 255) / 256, 256>>>();
    init_acc_kernel<<<1, 1024>>>();

    WPrepArgs wa;
    for (int i = 0; i < 6; i++) {
        wa.W[i]     = dnW[i];  wa.W[i + 6] = anW[i];
        wa.Fi[i]    = (i == 0) ? DIMC : HC;
        wa.Fi[i+6]  = (i == 0) ? DIMC : HC;
        wa.Fo[i]    = (i == 5) ? FD : HC;
        wa.Fo[i+6]  = (i == 5) ? GD : HC;
    }
    prep_w_all<<<dim3((WOFF + 255) / 256, 12), 256>>>(wa);

    cudaFuncSetAttribute(mma_gemm3, cudaFuncAttributeMaxDynamicSharedMemorySize,
                         GEMM_SMEM_BYTES);
    const dim3 gH(5, GY, 2);
    const dim3 gL5(2, GY, 2);

    #define GEMM3(grid, AhD,AlD,AhA,AlA, PWa, L, bD,bA, FoD,FoA, ChD,ClD,ChA,ClA, PWcD,PWcA, resA, nC, relu) \
        mma_gemm3<<<grid, blk, GEMM_SMEM_BYTES>>>(AhD,AlD,AhA,AlA, PWa, Wh, Wl, L, \
            bD,bA, FoD,FoA, ChD,ClD,ChA,ClA, PWcD,PWcA, resA, nC, relu)

    GEMM3(gH, inh,inl, inh,inl, 32, 0, dnb[0],anb[0], HC,HC, h0,l0, b0h,b0l, PWH,PWH, (const float*)0, 1, 1);
    GEMM3(gH, h0,l0, b0h,b0l, PWH, 1, dnb[1],anb[1], HC,HC, h1,l1, b1h,b1l, PWH,PWH, (const float*)0, 10, 1);
    GEMM3(gH, h1,l1, b1h,b1l, PWH, 2, dnb[2],anb[2], HC,HC, h0,l0, b0h,b0l, PWH,PWH, (const float*)0, 10, 1);
    GEMM3(gH, h0,l0, b0h,b0l, PWH, 3, dnb[3],anb[3], HC,HC, h1,l1, b1h,b1l, PWH,PWH, (const float*)0, 10, 1);
    GEMM3(gH, h1,l1, b1h,b1l, PWH, 4, dnb[4],anb[4], HC,HC, h0,l0, b0h,b0l, PWH,PWH, (const float*)0, 10, 1);
    GEMM3(gL5, h0,l0, b0h,b0l, PWH, 5, dnb[5],anb[5], FD,GD, Fh,Fl, Gh,Gl, FDP,GDP, in0, 10, 0);

    transpose_v_kernel<<<(FDP * JC + 255) / 256, 256>>>();
    row_norms_hl<<<NTOT / 8, 256>>>(Fh, Fl, nF, FDP);
    row_norms_hl<<<NTOT / 8, 256>>>(Gh, Gl, nG, GDP);

    cudaFuncSetAttribute(fm3_kernel, cudaFuncAttributeMaxDynamicSharedMemorySize,
                         FM_DYN_BYTES);
    fm3_kernel<<<dim3(JC / FMJ, NXC / FMI), 512, FM_DYN_BYTES>>>(eps, sig, sig0, cstp);

    mu_kernel<<<1, JC>>>();
    s2_kernel<<<NXC / 8, 256>>>();
    finalize_kernel<<<1, 1>>>((float*)d_out);
}

// round 13
// speedup vs baseline: 1.1723x; 1.0202x over previous
#include <cuda_runtime.h>
#include <cuda_bf16.h>
#include <math.h>
#include <stdint.h>

// Problem constants
#define NXC   32768
#define NTOT  66560
#define DIMC  28
#define HC    300
#define FD    100
#define GD    28
#define JC    1024

#define PWH   320
#define FDP   112
#define GDP   32
#define WOFF  (320 * 320)

// ---------------- scratch ----------------------------------------------------
__device__ float g_in0 [(size_t)NTOT * DIMC];
__device__ __align__(16) __nv_bfloat16 g_inh[(size_t)NTOT * 32];
__device__ __align__(16) __nv_bfloat16 g_inl[(size_t)NTOT * 32];
__device__ __align__(16) __nv_bfloat16 g_Ah0[(size_t)NTOT * PWH];
__device__ __align__(16) __nv_bfloat16 g_Al0[(size_t)NTOT * PWH];
__device__ __align__(16) __nv_bfloat16 g_Ah1[(size_t)NTOT * PWH];
__device__ __align__(16) __nv_bfloat16 g_Al1[(size_t)NTOT * PWH];
__device__ __align__(16) __nv_bfloat16 g_Bh0[(size_t)NTOT * PWH];
__device__ __align__(16) __nv_bfloat16 g_Bl0[(size_t)NTOT * PWH];
__device__ __align__(16) __nv_bfloat16 g_Bh1[(size_t)NTOT * PWH];
__device__ __align__(16) __nv_bfloat16 g_Bl1[(size_t)NTOT * PWH];
__device__ __align__(16) __nv_bfloat16 g_Wh[12 * WOFF];
__device__ __align__(16) __nv_bfloat16 g_Wl[12 * WOFF];
__device__ __align__(16) __nv_bfloat16 g_Fh[(size_t)NTOT * FDP];
__device__ __align__(16) __nv_bfloat16 g_Fl[(size_t)NTOT * FDP];
__device__ __align__(16) __nv_bfloat16 g_Gh[(size_t)NTOT * GDP];
__device__ __align__(16) __nv_bfloat16 g_Gl[(size_t)NTOT * GDP];
__device__ __align__(16) __nv_bfloat16 g_FvTh[FDP * JC];
__device__ __align__(16) __nv_bfloat16 g_FvTl[FDP * JC];
__device__ __align__(16) __nv_bfloat16 g_GvTh[GDP * JC];
__device__ __align__(16) __nv_bfloat16 g_GvTl[GDP * JC];
__device__ float g_nF  [NTOT];
__device__ float g_nG  [NTOT];
__device__ __align__(16) __nv_bfloat16 g_fmb[(size_t)NXC * JC];   // bf16 fm (s2 only)
__device__ float g_colsum[JC];
__device__ float g_mu    [JC];
__device__ float g_scal  [8];

__device__ __forceinline__ void split2(float x, __nv_bfloat16& h, __nv_bfloat16& l) {
    h = __float2bfloat16(x);
    l = __float2bfloat16(x - __bfloat162float(h));
}
__device__ __forceinline__ float fexp2(float x) {
    float r;
    asm("ex2.approx.ftz.f32 %0, %1;" : "=f"(r) : "f"(x));
    return r;
}

// ---------------- prep kernels ----------------------------------------------
__global__ void prep_in_kernel(const float* __restrict__ XY, const float* __restrict__ V) {
    int t = blockIdx.x * blockDim.x + threadIdx.x;
    if (t >= NTOT * 32) return;
    int r = t >> 5, c = t & 31;
    float v = 0.0f;
    if (c < DIMC) {
        int idx = r * DIMC + c;
        v = (r < 2 * NXC) ? XY[idx] : V[(r - 2 * NXC) * DIMC + c];
        g_in0[idx] = v;
    }
    __nv_bfloat16 h, l; split2(v, h, l);
    g_inh[t] = h; g_inl[t] = l;
}
__global__ void pad_all_kernel() {
    int t = blockIdx.x * blockDim.x + threadIdx.x;
    if (t >= NTOT * 20) return;
    int r = t / 20, c = t % 20;
    __nv_bfloat16 z = __float2bfloat16(0.0f);
    size_t o = (size_t)r * PWH + HC + c;
    g_Ah0[o] = z; g_Al0[o] = z; g_Ah1[o] = z; g_Al1[o] = z;
    g_Bh0[o] = z; g_Bl0[o] = z; g_Bh1[o] = z; g_Bl1[o] = z;
    if (c < 12) {
        size_t of = (size_t)r * FDP + 100 + c;
        g_Fh[of] = z; g_Fl[of] = z;
    }
    if (c < 4) {
        size_t og = (size_t)r * GDP + 28 + c;
        g_Gh[og] = z; g_Gl[og] = z;
    }
}
__global__ void init_acc_kernel() {
    int t = threadIdx.x;
    if (t < JC) g_colsum[t] = 0.0f;
    if (t < 8)  g_scal[t]   = 0.0f;
}
struct WPrepArgs {
    const float* W[12];
    int Fi[12];
    int Fo[12];
};
__global__ void prep_w_all(WPrepArgs a) {
    int layer = blockIdx.y;
    int idx = blockIdx.x * blockDim.x + threadIdx.x;
    if (idx >= WOFF) return;
    int k = idx / 320, n = idx - k * 320;
    int Fi = a.Fi[layer], Fo = a.Fo[layer];
    float v = (k < Fi && n < Fo) ? a.W[layer][(size_t)k * Fo + n] : 0.0f;
    __nv_bfloat16 h, l; split2(v, h, l);
    g_Wh[(size_t)layer * WOFF + idx] = h;
    g_Wl[(size_t)layer * WOFF + idx] = l;
}
__global__ void transpose_v_kernel() {
    int t = blockIdx.x * blockDim.x + threadIdx.x;
    if (t < FDP * JC) {
        int k = t >> 10, j = t & 1023;
        size_t src = (size_t)(2 * NXC + j) * FDP + k;
        g_FvTh[t] = g_Fh[src];
        g_FvTl[t] = g_Fl[src];
    }
    if (t < GDP * JC) {
        int k = t >> 10, j = t & 1023;
        size_t src = (size_t)(2 * NXC + j) * GDP + k;
        g_GvTh[t] = g_Gh[src];
        g_GvTl[t] = g_Gl[src];
    }
}

// =============== shared MMA helpers ==========================================
__device__ __forceinline__ uint32_t smem_u32(const void* p) {
    uint32_t a;
    asm("{ .reg .u64 t; cvta.to.shared.u64 t, %1; cvt.u32.u64 %0, t; }" : "=r"(a) : "l"(p));
    return a;
}
__device__ __forceinline__ void ldsm_x4(uint32_t addr, uint32_t r[4]) {
    asm volatile("ldmatrix.sync.aligned.m8n8.x4.shared.b16 {%0,%1,%2,%3}, [%4];"
        : "=r"(r[0]), "=r"(r[1]), "=r"(r[2]), "=r"(r[3]) : "r"(addr));
}
__device__ __forceinline__ void ldsm_x4_t(uint32_t addr, uint32_t r[4]) {
    asm volatile("ldmatrix.sync.aligned.m8n8.x4.trans.shared.b16 {%0,%1,%2,%3}, [%4];"
        : "=r"(r[0]), "=r"(r[1]), "=r"(r[2]), "=r"(r[3]) : "r"(addr));
}
__device__ __forceinline__ void mma_bf16(float c[4], const uint32_t a[4],
                                         uint32_t b0, uint32_t b1) {
    asm("mma.sync.aligned.m16n8k16.row.col.f32.bf16.bf16.f32 "
        "{%0,%1,%2,%3}, {%4,%5,%6,%7}, {%8,%9}, {%0,%1,%2,%3};"
        : "+f"(c[0]), "+f"(c[1]), "+f"(c[2]), "+f"(c[3])
        : "r"(a[0]), "r"(a[1]), "r"(a[2]), "r"(a[3]), "r"(b0), "r"(b1));
}
#define CP_ASYNC16(dst_u32, src_ptr) \
    asm volatile("cp.async.cg.shared.global [%0], [%1], 16;" \
        :: "r"(dst_u32), "l"(src_ptr) : "memory")
#define CP_COMMIT() asm volatile("cp.async.commit_group;" ::: "memory")
#define CP_WAIT(n)  asm volatile("cp.async.wait_group %0;" :: "n"(n) : "memory")

// ====== bf16-split GEMM: 2-stage, 3 CTAs/SM, issue-before-MMA, 1 sync/chunk ==
#define BMM 128
#define BNN 64
#define BKK 32
#define A_STRIDE 40
#define B_STRIDE 72
// 2 stages: AH 2x5120, AL 2x5120, BH 2x2304, BL 2x2304 (bf16 units)
#define SM_AH 0
#define SM_AL 10240
#define SM_BH 20480
#define SM_BL 25088
#define GEMM_SMEM_BYTES 59392

__global__ __launch_bounds__(256, 3)
void mma_gemm3(const __nv_bfloat16* __restrict__ AhD, const __nv_bfloat16* __restrict__ AlD,
               const __nv_bfloat16* __restrict__ AhA, const __nv_bfloat16* __restrict__ AlA,
               int PWa,
               const __nv_bfloat16* __restrict__ WhB, const __nv_bfloat16* __restrict__ WlB,
               int layer,
               const float* __restrict__ biasD, const float* __restrict__ biasA,
               int FoD, int FoA,
               __nv_bfloat16* __restrict__ ChD, __nv_bfloat16* __restrict__ ClD,
               __nv_bfloat16* __restrict__ ChA, __nv_bfloat16* __restrict__ ClA,
               int PWcD, int PWcA,
               const float* __restrict__ resA,
               int nC, int doRelu)
{
    extern __shared__ __nv_bfloat16 dyn[];

    const int net = blockIdx.z;
    const __nv_bfloat16* Ah = net ? AhA : AhD;
    const __nv_bfloat16* Al = net ? AlA : AlD;
    const __nv_bfloat16* Wh = WhB + (size_t)(layer + 6 * net) * WOFF;
    const __nv_bfloat16* Wl = WlB + (size_t)(layer + 6 * net) * WOFF;
    const float* bias = net ? biasA : biasD;
    const int Fo  = net ? FoA : FoD;
    __nv_bfloat16* Ch = net ? ChA : ChD;
    __nv_bfloat16* Cl = net ? ClA : ClD;
    const int PWc = net ? PWcA : PWcD;
    const float* res = net ? resA : (const float*)0;

    const int n0 = blockIdx.x * BNN;
    if (n0 >= Fo) return;

    const int tid    = threadIdx.x;
    const int lane   = tid & 31;
    const int wid    = tid >> 5;
    const int warp_m = wid >> 1;
    const int warp_n = wid & 1;
    const int rbase  = blockIdx.y * BMM;

    const int a_row0 = tid >> 2;
    const int a_kk   = (tid & 3) * 8;
    const int bk     = tid >> 3;
    const int bn     = (tid & 7) * 8;

    const uint32_t dyn32 = smem_u32(dyn);
    const int a_row  = warp_m * 32 + (lane & 15);
    const int a_kadd = (lane >> 4) * 8;
    const uint32_t aHiB = dyn32 + (uint32_t)(SM_AH + a_row * A_STRIDE + a_kadd) * 2u;
    const uint32_t aLoB = dyn32 + (uint32_t)(SM_AL + a_row * A_STRIDE + a_kadd) * 2u;
    const int b_k = (lane & 7) + ((lane & 8) ? 8 : 0);
    const int b_n = warp_n * 32 + ((lane & 16) ? 8 : 0);
    const uint32_t bHiB = dyn32 + (uint32_t)(SM_BH + b_k * B_STRIDE + b_n) * 2u;
    const uint32_t bLoB = dyn32 + (uint32_t)(SM_BL + b_k * B_STRIDE + b_n) * 2u;

    const uint32_t dA0 = dyn32 + (uint32_t)(a_row0 * A_STRIDE + a_kk) * 2u;
    const uint32_t dB0 = dyn32 + (uint32_t)(SM_BH + bk * B_STRIDE + bn) * 2u;

    float acc[2][4][4];
    #pragma unroll
    for (int i = 0; i < 2; i++)
        #pragma unroll
        for (int j = 0; j < 4; j++)
            #pragma unroll
            for (int q = 0; q < 4; q++) acc[i][j][q] = 0.0f;

    // 2-stage buffers: A byte offset bf*10240, AL at +20480; B bf*4608, BL at +9216
    #define ISSUE_CHUNK(k0, bf) do { \
        uint32_t od = (uint32_t)(bf) * 10240u; \
        uint32_t ob = (uint32_t)(bf) * 4608u; \
        size_t o0 = (size_t)(rbase + a_row0) * PWa + (k0) + a_kk; \
        size_t o1 = (size_t)(rbase + a_row0 + 64) * PWa + (k0) + a_kk; \
        uint32_t d1 = dA0 + od + (uint32_t)(64 * A_STRIDE) * 2u; \
        CP_ASYNC16(dA0 + od,           Ah + o0); \
        CP_ASYNC16(dA0 + od + 20480u,  Al + o0); \
        CP_ASYNC16(d1,                 Ah + o1); \
        CP_ASYNC16(d1 + 20480u,        Al + o1); \
        size_t bo = (size_t)((k0) + bk) * 320 + n0 + bn; \
        CP_ASYNC16(dB0 + ob,           Wh + bo); \
        CP_ASYNC16(dB0 + ob + 9216u,   Wl + bo); \
        CP_COMMIT(); \
    } while (0)

    ISSUE_CHUNK(0, 0);

    for (int c = 0; c < nC; c++) {
        const int buf = c & 1;
        const uint32_t aOff = (uint32_t)buf * 10240u;
        const uint32_t bOff = (uint32_t)buf * 4608u;

        // wait for chunk c's copy; sync also fences MMA(c-1) so the
        // issue below may overwrite buffer (c+1)&1 == (c-1)&1
        CP_WAIT(0);
        __syncthreads();

        // issue chunk c+1 BEFORE this chunk's MMA -> copy overlaps MMA
        if (c + 1 < nC) ISSUE_CHUNK((c + 1) * BKK, (c + 1) & 1);

        #pragma unroll
        for (int ks = 0; ks < 2; ks++) {
            uint32_t Bhr[2][4], Blr[2][4];
            #pragma unroll
            for (int np = 0; np < 2; np++) {
                uint32_t off = bOff + (uint32_t)(np * 16 + ks * 16 * B_STRIDE) * 2u;
                ldsm_x4_t(bHiB + off, Bhr[np]);
                ldsm_x4_t(bLoB + off, Blr[np]);
            }
            #pragma unroll
            for (int mi = 0; mi < 2; mi++) {
                uint32_t Ahr[4], Alr[4];
                uint32_t off = aOff + (uint32_t)(mi * 16 * A_STRIDE + ks * 16) * 2u;
                ldsm_x4(aHiB + off, Ahr);
                ldsm_x4(aLoB + off, Alr);
                #pragma unroll
                for (int nj = 0; nj < 4; nj++) {
                    const int np = nj >> 1, hf = (nj & 1) * 2;
                    mma_bf16(acc[mi][nj], Ahr, Bhr[np][hf], Bhr[np][hf + 1]);
                    mma_bf16(acc[mi][nj], Ahr, Blr[np][hf], Blr[np][hf + 1]);
                    mma_bf16(acc[mi][nj], Alr, Bhr[np][hf], Bhr[np][hf + 1]);
                }
            }
        }
    }
    #undef ISSUE_CHUNK

    // epilogue — writes bf16 hi/lo at stride PWc
    #pragma unroll
    for (int mi = 0; mi < 2; mi++)
        #pragma unroll
        for (int nj = 0; nj < 4; nj++) {
            int col = n0 + warp_n * 32 + nj * 8 + (lane & 3) * 2;
            if (col >= Fo) continue;
            float2 b2 = *(const float2*)(bias + col);
            #pragma unroll
            for (int half = 0; half < 2; half++) {
                int row = rbase + warp_m * 32 + mi * 16 + (lane >> 2) + half * 8;
                float vx = acc[mi][nj][half * 2 + 0] + b2.x;
                float vy = acc[mi][nj][half * 2 + 1] + b2.y;
                if (res) {
                    float2 r2 = *(const float2*)(res + (size_t)row * Fo + col);
                    vx += r2.x; vy += r2.y;
                }
                if (doRelu) { vx = fmaxf(vx, 0.0f); vy = fmaxf(vy, 0.0f); }
                __nv_bfloat16 hx, lx, hy, ly;
                split2(vx, hx, lx); split2(vy, hy, ly);
                *(__nv_bfloat162*)(Ch + (size_t)row * PWc + col) = __halves2bfloat162(hx, hy);
                *(__nv_bfloat162*)(Cl + (size_t)row * PWc + col) = __halves2bfloat162(lx, ly);
            }
        }
}

// ---------------- row squared norms from hi/lo bf16 --------------------------
__global__ void row_norms_hl(const __nv_bfloat16* __restrict__ H,
                             const __nv_bfloat16* __restrict__ L,
                             float* __restrict__ out, int D)
{
    int warp = (blockIdx.x * blockDim.x + threadIdx.x) >> 5;
    int lane = threadIdx.x & 31;
    if (warp >= NTOT) return;
    float s = 0.0f;
    for (int k = lane; k < D; k += 32) {
        size_t o = (size_t)warp * D + k;
        float v = __bfloat162float(H[o]) + __bfloat162float(L[o]);
        s += v * v;
    }
    #pragma unroll
    for (int o = 16; o; o >>= 1) s += __shfl_xor_sync(0xffffffffu, s, o);
    if (lane == 0) out[warp] = s;
}

// ---------------- fused fm kernel: disjoint smem, single sync ----------------
#define FMI 64
#define FMJ 128
#define AF_S 120
#define BF_S 136
#define AG_S 40
#define OF_AXH 0
#define OF_AXL 7680
#define OF_AYH 15360
#define OF_AYL 23040
#define OF_BH  30720
#define OF_BL  45952
#define OG_AXH 61184
#define OG_AXL 63744
#define OG_AYH 66304
#define OG_AYL 68864
#define OG_BH  71424
#define OG_BL  75776
#define FM_DYN_BYTES (80128 * 2)

__global__ __launch_bounds__(512)
void fm3_kernel(const float* __restrict__ eps_p, const float* __restrict__ sig_p,
                const float* __restrict__ sig0_p, const float* __restrict__ cst_p)
{
    extern __shared__ __nv_bfloat16 dynb[];
    __shared__ float nfx[64], nfy[64], ngx[64], ngy[64];
    __shared__ float nfv[128], ngv[128];
    __shared__ float scs[128];
    __shared__ float red16[16];

    const int tid    = threadIdx.x;
    const int lane   = tid & 31;
    const int wid    = tid >> 5;
    const int warp_m = wid >> 3;
    const int warp_n = wid & 7;
    const int ibase  = blockIdx.y * FMI;
    const int jbase  = blockIdx.x * FMJ;
    const int XR = ibase, YR = NXC + ibase, VR = 2 * NXC + jbase;

    if (tid < 64) {
        nfx[tid] = g_nF[XR + tid]; nfy[tid] = g_nF[YR + tid];
        ngx[tid] = g_nG[XR + tid]; ngy[tid] = g_nG[YR + tid];
    } else if (tid < 192) {
        int j = tid - 64;
        nfv[j] = g_nF[VR + j]; ngv[j] = g_nG[VR + j];
    } else if (tid < 320) {
        scs[tid - 192] = 0.0f;
    }

    for (int e = tid; e < 896; e += 512) {
        int r = e / 14, kv = (e % 14) * 8;
        *(uint4*)&dynb[OF_AXH + r * AF_S + kv] = *(const uint4*)&g_Fh[(size_t)(XR + r) * FDP + kv];
        *(uint4*)&dynb[OF_AXL + r * AF_S + kv] = *(const uint4*)&g_Fl[(size_t)(XR + r) * FDP + kv];
        *(uint4*)&dynb[OF_AYH + r * AF_S + kv] = *(const uint4*)&g_Fh[(size_t)(YR + r) * FDP + kv];
        *(uint4*)&dynb[OF_AYL + r * AF_S + kv] = *(const uint4*)&g_Fl[(size_t)(YR + r) * FDP + kv];
    }
    for (int e = tid; e < 1792; e += 512) {
        int k = e >> 4, jv = (e & 15) * 8;
        *(uint4*)&dynb[OF_BH + k * BF_S + jv] = *(const uint4*)&g_FvTh[k * 1024 + jbase + jv];
        *(uint4*)&dynb[OF_BL + k * BF_S + jv] = *(const uint4*)&g_FvTl[k * 1024 + jbase + jv];
    }
    if (tid < 256) {
        int r = tid >> 2, kv = (tid & 3) * 8;
        *(uint4*)&dynb[OG_AXH + r * AG_S + kv] = *(const uint4*)&g_Gh[(size_t)(XR + r) * GDP + kv];
        *(uint4*)&dynb[OG_AXL + r * AG_S + kv] = *(const uint4*)&g_Gl[(size_t)(XR + r) * GDP + kv];
        *(uint4*)&dynb[OG_AYH + r * AG_S + kv] = *(const uint4*)&g_Gh[(size_t)(YR + r) * GDP + kv];
        *(uint4*)&dynb[OG_AYL + r * AG_S + kv] = *(const uint4*)&g_Gl[(size_t)(YR + r) * GDP + kv];
    }
    {
        int k = tid >> 4, jv = (tid & 15) * 8;
        *(uint4*)&dynb[OG_BH + k * BF_S + jv] = *(const uint4*)&g_GvTh[k * 1024 + jbase + jv];
        *(uint4*)&dynb[OG_BL + k * BF_S + jv] = *(const uint4*)&g_GvTl[k * 1024 + jbase + jv];
    }
    __syncthreads();

    const uint32_t dyn32 = smem_u32(dynb);
    const int a_row  = warp_m * 32 + (lane & 15);
    const int a_kadd = (lane >> 4) * 8;
    const int b_k    = lane & 15;
    const int b_n    = warp_n * 16 + ((lane & 16) ? 8 : 0);

    float accX[2][2][4], accY[2][2][4];
    #pragma unroll
    for (int i = 0; i < 2; i++)
        #pragma unroll
        for (int j = 0; j < 2; j++)
            #pragma unroll
            for (int q = 0; q < 4; q++) { accX[i][j][q] = 0.0f; accY[i][j][q] = 0.0f; }

    #pragma unroll
    for (int ks = 0; ks < 7; ks++) {
        uint32_t AXh[2][4], AXl[2][4], AYh[2][4], AYl[2][4], Bh[4], Bl[4];
        #pragma unroll
        for (int mi = 0; mi < 2; mi++) {
            uint32_t ao = (uint32_t)((a_row + mi * 16) * AF_S + ks * 16 + a_kadd) * 2u;
            ldsm_x4(dyn32 + OF_AXH * 2u + ao, AXh[mi]);
            ldsm_x4(dyn32 + OF_AXL * 2u + ao, AXl[mi]);
            ldsm_x4(dyn32 + OF_AYH * 2u + ao, AYh[mi]);
            ldsm_x4(dyn32 + OF_AYL * 2u + ao, AYl[mi]);
        }
        {
            uint32_t bo = (uint32_t)((b_k + ks * 16) * BF_S + b_n) * 2u;
            ldsm_x4_t(dyn32 + OF_BH * 2u + bo, Bh);
            ldsm_x4_t(dyn32 + OF_BL * 2u + bo, Bl);
        }
        #pragma unroll
        for (int mi = 0; mi < 2; mi++)
            #pragma unroll
            for (int nj = 0; nj < 2; nj++) {
                const int hf = nj * 2;
                mma_bf16(accX[mi][nj], AXh[mi], Bh[hf], Bh[hf + 1]);
                mma_bf16(accX[mi][nj], AXh[mi], Bl[hf], Bl[hf + 1]);
                mma_bf16(accX[mi][nj], AXl[mi], Bh[hf], Bh[hf + 1]);
                mma_bf16(accY[mi][nj], AYh[mi], Bh[hf], Bh[hf + 1]);
                mma_bf16(accY[mi][nj], AYh[mi], Bl[hf], Bl[hf + 1]);
                mma_bf16(accY[mi][nj], AYl[mi], Bh[hf], Bh[hf + 1]);
            }
    }

    const float LOG2E  = 1.4426950408889634f;
    const float ep     = 1.0f / (1.0f + __expf(-eps_p[0]));
    const float is2    = LOG2E / (sig_p[0]  * sig_p[0]);
    const float is0    = LOG2E / (sig0_p[0] * sig0_p[0]);
    const float cstv   = cst_p[0];
    const float one_ep = 1.0f - ep;

    #pragma unroll
    for (int mi = 0; mi < 2; mi++)
        #pragma unroll
        for (int nj = 0; nj < 2; nj++)
            #pragma unroll
            for (int q = 0; q < 4; q++) {
                int rl = warp_m * 32 + mi * 16 + (lane >> 2) + (q >> 1) * 8;
                int cl = warp_n * 16 + nj * 8 + (lane & 3) * 2 + (q & 1);
                float Dx = fmaxf(nfx[rl] + nfv[cl] - 2.0f * accX[mi][nj][q], 0.0f);
                float Dy = fmaxf(nfy[rl] + nfv[cl] - 2.0f * accY[mi][nj][q], 0.0f);
                accX[mi][nj][q] = fmaf(one_ep, fexp2(-Dx * is0), ep);
                accY[mi][nj][q] = fmaf(one_ep, fexp2(-Dy * is0), ep);
            }

    float gX[2][2][4], gY[2][2][4];
    #pragma unroll
    for (int i = 0; i < 2; i++)
        #pragma unroll
        for (int j = 0; j < 2; j++)
            #pragma unroll
            for (int q = 0; q < 4; q++) { gX[i][j][q] = 0.0f; gY[i][j][q] = 0.0f; }

    #pragma unroll
    for (int ks = 0; ks < 2; ks++) {
        uint32_t AXh[2][4], AXl[2][4], AYh[2][4], AYl[2][4], Bh[4], Bl[4];
        #pragma unroll
        for (int mi = 0; mi < 2; mi++) {
            uint32_t ao = (uint32_t)((a_row + mi * 16) * AG_S + ks * 16 + a_kadd) * 2u;
            ldsm_x4(dyn32 + OG_AXH * 2u + ao, AXh[mi]);
            ldsm_x4(dyn32 + OG_AXL * 2u + ao, AXl[mi]);
            ldsm_x4(dyn32 + OG_AYH * 2u + ao, AYh[mi]);
            ldsm_x4(dyn32 + OG_AYL * 2u + ao, AYl[mi]);
        }
        {
            uint32_t bo = (uint32_t)((b_k + ks * 16) * BF_S + b_n) * 2u;
            ldsm_x4_t(dyn32 + OG_BH * 2u + bo, Bh);
            ldsm_x4_t(dyn32 + OG_BL * 2u + bo, Bl);
        }
        #pragma unroll
        for (int mi = 0; mi < 2; mi++)
            #pragma unroll
            for (int nj = 0; nj < 2; nj++) {
                const int hf = nj * 2;
                mma_bf16(gX[mi][nj], AXh[mi], Bh[hf], Bh[hf + 1]);
                mma_bf16(gX[mi][nj], AXh[mi], Bl[hf], Bl[hf + 1]);
                mma_bf16(gX[mi][nj], AXl[mi], Bh[hf], Bh[hf + 1]);
                mma_bf16(gY[mi][nj], AYh[mi], Bh[hf], Bh[hf + 1]);
                mma_bf16(gY[mi][nj], AYh[mi], Bl[hf], Bl[hf + 1]);
                mma_bf16(gY[mi][nj], AYl[mi], Bh[hf], Bh[hf + 1]);
            }
    }

    const float RS = 0.03125f;
    float csum[4];
    #pragma unroll
    for (int i = 0; i < 4; i++) csum[i] = 0.0f;
    float qacc = 0.0f;

    #pragma unroll
    for (int mi = 0; mi < 2; mi++)
        #pragma unroll
        for (int nj = 0; nj < 2; nj++) {
            float vq[4];
            #pragma unroll
            for (int q = 0; q < 4; q++) {
                int rl = warp_m * 32 + mi * 16 + (lane >> 2) + (q >> 1) * 8;
                int cl = warp_n * 16 + nj * 8 + (lane & 3) * 2 + (q & 1);
                float Dgx = fmaxf(ngx[rl] + ngv[cl] - 2.0f * gX[mi][nj][q], 0.0f);
                float Dgy = fmaxf(ngy[rl] + ngv[cl] - 2.0f * gY[mi][nj][q], 0.0f);
                float KX = cstv * accX[mi][nj][q] * fexp2(-Dgx * is2);
                float KY = cstv * accY[mi][nj][q] * fexp2(-Dgy * is2);
                float v = (KX - KY) * RS;
                vq[q] = v;
                csum[nj * 2 + (q & 1)] += v;
                qacc += v * v;
            }
            int colg = jbase + warp_n * 16 + nj * 8 + (lane & 3) * 2;
            int row0 = ibase + warp_m * 32 + mi * 16 + (lane >> 2);
            *(__nv_bfloat162*)&g_fmb[(size_t)row0 * JC + colg] =
                __floats2bfloat162_rn(vq[0], vq[1]);
            *(__nv_bfloat162*)&g_fmb[(size_t)(row0 + 8) * JC + colg] =
                __floats2bfloat162_rn(vq[2], vq[3]);
        }

    #pragma unroll
    for (int off = 16; off >= 4; off >>= 1)
        #pragma unroll
        for (int c4 = 0; c4 < 4; c4++)
            csum[c4] += __shfl_down_sync(0xffffffffu, csum[c4], off);
    if (lane < 4) {
        #pragma unroll
        for (int c4 = 0; c4 < 4; c4++) {
            int cl = warp_n * 16 + (c4 >> 1) * 8 + lane * 2 + (c4 & 1);
            atomicAdd(&scs[cl], csum[c4]);
        }
    }
    #pragma unroll
    for (int off = 16; off; off >>= 1)
        qacc += __shfl_xor_sync(0xffffffffu, qacc, off);
    if (lane == 0) red16[wid] = qacc;
    __syncthreads();

    if (tid < 128) atomicAdd(&g_colsum[jbase + tid], scs[tid]);
    if (wid == 0) {
        float v = (lane < 16) ? red16[lane] : 0.0f;
        #pragma unroll
        for (int off = 8; off; off >>= 1)
            v += __shfl_xor_sync(0xffffffffu, v, off);
        if (lane == 0) atomicAdd(&g_scal[0], v);
    }
}

// ---------------- mu + sum(mu^2) ----------------------------------------------
__global__ void mu_kernel() {
    __shared__ float red[JC];
    int j = threadIdx.x;
    float m = g_colsum[j] * (1.0f / (float)NXC);
    g_mu[j] = m;
    red[j] = m * m;
    __syncthreads();
    for (int s = 512; s; s >>= 1) {
        if (j < s) red[j] += red[j + s];
        __syncthreads();
    }
    if (j == 0) g_scal[2] = red[0];
}

// ---------------- s_i = fm[i]·mu (bf16 fm) ; accumulate s_i^2 -----------------
__global__ __launch_bounds__(256) void s2_kernel() {
    __shared__ float smu[JC];
    int tid = threadIdx.x;
    for (int e = tid; e < JC; e += 256) smu[e] = g_mu[e];
    __syncthreads();
    int row  = blockIdx.x * 8 + (tid >> 5);
    int lane = tid & 31;
    const __nv_bfloat16* rp = g_fmb + (size_t)row * JC;
    float s = 0.0f;
    #pragma unroll
    for (int t = 0; t < 4; t++) {
        int c = lane * 8 + 256 * t;
        uint4 v = *(const uint4*)(rp + c);
        const __nv_bfloat16* pv = (const __nv_bfloat16*)&v;
        #pragma unroll
        for (int e = 0; e < 8; e++)
            s += __bfloat162float(pv[e]) * smu[c + e];
    }
    #pragma unroll
    for (int o = 16; o; o >>= 1) s += __shfl_xor_sync(0xffffffffu, s, o);
    if (lane == 0) atomicAdd(&g_scal[1], s * s);
}

// ---------------- finalize ------------------------------------------------------
__global__ void finalize_kernel(float* out) {
    double sumfm2 = (double)g_scal[0];
    double sums2  = (double)g_scal[1];
    double summu2 = (double)g_scal[2];
    double nx = (double)NXC;
    double t1 = summu2 * (nx / (nx - 1.0));
    double t2 = sumfm2 / nx / (nx - 1.0);
    double mean = t1 - t2;
    double var  = 4.0 * (sums2 / nx) - 4.0 * summu2 * summu2;
    out[0] = (float)(-(mean / sqrt(var + 1e-6)));
}

// ---------------- launch ---------------------------------------------------------
extern "C" void kernel_launch(void* const* d_in, const int* in_sizes, int n_in,
                              void* d_out, int out_size)
{
    const float* XY = (const float*)d_in[0];
    const float* V  = (const float*)d_in[1];
    const float *dnW[6], *dnb[6], *anW[6], *anb[6];
    for (int i = 0; i < 6; i++) {
        dnW[i] = (const float*)d_in[2 + 2 * i];
        dnb[i] = (const float*)d_in[3 + 2 * i];
        anW[i] = (const float*)d_in[14 + 2 * i];
        anb[i] = (const float*)d_in[15 + 2 * i];
    }
    const float* eps   = (const float*)d_in[26];
    const float* sig   = (const float*)d_in[27];
    const float* sig0  = (const float*)d_in[28];
    const float* cstp  = (const float*)d_in[29];

    float *in0, *nF, *nG;
    __nv_bfloat16 *inh, *inl, *h0, *l0, *h1, *l1, *b0h, *b0l, *b1h, *b1l;
    __nv_bfloat16 *Wh, *Wl, *Fh, *Fl, *Gh, *Gl;
    cudaGetSymbolAddress((void**)&in0, g_in0);
    cudaGetSymbolAddress((void**)&nF,  g_nF);
    cudaGetSymbolAddress((void**)&nG,  g_nG);
    cudaGetSymbolAddress((void**)&inh, g_inh);
    cudaGetSymbolAddress((void**)&inl, g_inl);
    cudaGetSymbolAddress((void**)&h0,  g_Ah0);
    cudaGetSymbolAddress((void**)&l0,  g_Al0);
    cudaGetSymbolAddress((void**)&h1,  g_Ah1);
    cudaGetSymbolAddress((void**)&l1,  g_Al1);
    cudaGetSymbolAddress((void**)&b0h, g_Bh0);
    cudaGetSymbolAddress((void**)&b0l, g_Bl0);
    cudaGetSymbolAddress((void**)&b1h, g_Bh1);
    cudaGetSymbolAddress((void**)&b1l, g_Bl1);
    cudaGetSymbolAddress((void**)&Wh,  g_Wh);
    cudaGetSymbolAddress((void**)&Wl,  g_Wl);
    cudaGetSymbolAddress((void**)&Fh,  g_Fh);
    cudaGetSymbolAddress((void**)&Fl,  g_Fl);
    cudaGetSymbolAddress((void**)&Gh,  g_Gh);
    cudaGetSymbolAddress((void**)&Gl,  g_Gl);

    const int GY = NTOT / BMM;     // 520
    const dim3 blk(256);

    prep_in_kernel<<<(NTOT * 32 + 255) / 256, 256>>>(XY, V);
    pad_all_kernel<<<(NTOT * 20 + 255) / 256, 256>>>();
    init_acc_kernel<<<1, 1024>>>();

    WPrepArgs wa;
    for (int i = 0; i < 6; i++) {
        wa.W[i]     = dnW[i];  wa.W[i + 6] = anW[i];
        wa.Fi[i]    = (i == 0) ? DIMC : HC;
        wa.Fi[i+6]  = (i == 0) ? DIMC : HC;
        wa.Fo[i]    = (i == 5) ? FD : HC;
        wa.Fo[i+6]  = (i == 5) ? GD : HC;
    }
    prep_w_all<<<dim3((WOFF + 255) / 256, 12), 256>>>(wa);

    cudaFuncSetAttribute(mma_gemm3, cudaFuncAttributeMaxDynamicSharedMemorySize,
                         GEMM_SMEM_BYTES);
    const dim3 gH(5, GY, 2);
    const dim3 gL5(2, GY, 2);

    #define GEMM3(grid, AhD,AlD,AhA,AlA, PWa, L, bD,bA, FoD,FoA, ChD,ClD,ChA,ClA, PWcD,PWcA, resA, nC, relu) \
        mma_gemm3<<<grid, blk, GEMM_SMEM_BYTES>>>(AhD,AlD,AhA,AlA, PWa, Wh, Wl, L, \
            bD,bA, FoD,FoA, ChD,ClD,ChA,ClA, PWcD,PWcA, resA, nC, relu)

    GEMM3(gH, inh,inl, inh,inl, 32, 0, dnb[0],anb[0], HC,HC, h0,l0, b0h,b0l, PWH,PWH, (const float*)0, 1, 1);
    GEMM3(gH, h0,l0, b0h,b0l, PWH, 1, dnb[1],anb[1], HC,HC, h1,l1, b1h,b1l, PWH,PWH, (const float*)0, 10, 1);
    GEMM3(gH, h1,l1, b1h,b1l, PWH, 2, dnb[2],anb[2], HC,HC, h0,l0, b0h,b0l, PWH,PWH, (const float*)0, 10, 1);
    GEMM3(gH, h0,l0, b0h,b0l, PWH, 3, dnb[3],anb[3], HC,HC, h1,l1, b1h,b1l, PWH,PWH, (const float*)0, 10, 1);
    GEMM3(gH, h1,l1, b1h,b1l, PWH, 4, dnb[4],anb[4], HC,HC, h0,l0, b0h,b0l, PWH,PWH, (const float*)0, 10, 1);
    GEMM3(gL5, h0,l0, b0h,b0l, PWH, 5, dnb[5],anb[5], FD,GD, Fh,Fl, Gh,Gl, FDP,GDP, in0, 10, 0);

    transpose_v_kernel<<<(FDP * JC + 255) / 256, 256>>>();
    row_norms_hl<<<NTOT / 8, 256>>>(Fh, Fl, nF, FDP);
    row_norms_hl<<<NTOT / 8, 256>>>(Gh, Gl, nG, GDP);

    cudaFuncSetAttribute(fm3_kernel, cudaFuncAttributeMaxDynamicSharedMemorySize,
                         FM_DYN_BYTES);
    fm3_kernel<<<dim3(JC / FMJ, NXC / FMI), 512, FM_DYN_BYTES>>>(eps, sig, sig0, cstp);

    mu_kernel<<<1, JC>>>();
    s2_kernel<<<NXC / 8, 256>>>();
    finalize_kernel<<<1, 1>>>((float*)d_out);
}

// round 14
// speedup vs baseline: 1.1806x; 1.0071x over previous
#include <cuda_runtime.h>
#include <cuda_bf16.h>
#include <math.h>
#include <stdint.h>

// Problem constants
#define NXC   32768
#define NTOT  66560
#define DIMC  28
#define HC    300
#define FD    100
#define GD    28
#define JC    1024

#define PWH   320
#define FDP   112
#define GDP   32
#define WOFF  (320 * 320)

// ---------------- scratch ----------------------------------------------------
__device__ float g_in0 [(size_t)NTOT * DIMC];
__device__ __align__(16) __nv_bfloat16 g_inh[(size_t)NTOT * 32];
__device__ __align__(16) __nv_bfloat16 g_inl[(size_t)NTOT * 32];
__device__ __align__(16) __nv_bfloat16 g_Ah0[(size_t)NTOT * PWH];
__device__ __align__(16) __nv_bfloat16 g_Al0[(size_t)NTOT * PWH];
__device__ __align__(16) __nv_bfloat16 g_Ah1[(size_t)NTOT * PWH];
__device__ __align__(16) __nv_bfloat16 g_Al1[(size_t)NTOT * PWH];
__device__ __align__(16) __nv_bfloat16 g_Bh0[(size_t)NTOT * PWH];
__device__ __align__(16) __nv_bfloat16 g_Bl0[(size_t)NTOT * PWH];
__device__ __align__(16) __nv_bfloat16 g_Bh1[(size_t)NTOT * PWH];
__device__ __align__(16) __nv_bfloat16 g_Bl1[(size_t)NTOT * PWH];
__device__ __align__(16) __nv_bfloat16 g_Wh[12 * WOFF];
__device__ __align__(16) __nv_bfloat16 g_Wl[12 * WOFF];
__device__ __align__(16) __nv_bfloat16 g_Fh[(size_t)NTOT * FDP];
__device__ __align__(16) __nv_bfloat16 g_Fl[(size_t)NTOT * FDP];
__device__ __align__(16) __nv_bfloat16 g_Gh[(size_t)NTOT * GDP];
__device__ __align__(16) __nv_bfloat16 g_Gl[(size_t)NTOT * GDP];
__device__ __align__(16) __nv_bfloat16 g_FvTh[FDP * JC];
__device__ __align__(16) __nv_bfloat16 g_FvTl[FDP * JC];
__device__ __align__(16) __nv_bfloat16 g_GvTh[GDP * JC];
__device__ __align__(16) __nv_bfloat16 g_GvTl[GDP * JC];
__device__ float g_nF  [NTOT];
__device__ float g_nG  [NTOT];
__device__ __align__(16) __nv_bfloat16 g_fmb[(size_t)NXC * JC];   // bf16 fm (s2 only)
__device__ float g_colsum[JC];
__device__ float g_mu    [JC];
__device__ float g_scal  [8];

__device__ __forceinline__ void split2(float x, __nv_bfloat16& h, __nv_bfloat16& l) {
    h = __float2bfloat16(x);
    l = __float2bfloat16(x - __bfloat162float(h));
}
__device__ __forceinline__ float fexp2(float x) {
    float r;
    asm("ex2.approx.ftz.f32 %0, %1;" : "=f"(r) : "f"(x));
    return r;
}

// ---------------- prep kernels ----------------------------------------------
// fused: concat + bf16 split + all pad zeroing (same row range)
__global__ void prep_in_pad_kernel(const float* __restrict__ XY, const float* __restrict__ V) {
    int t = blockIdx.x * blockDim.x + threadIdx.x;
    if (t >= NTOT * 32) return;
    int r = t >> 5, c = t & 31;
    float v = 0.0f;
    if (c < DIMC) {
        int idx = r * DIMC + c;
        v = (r < 2 * NXC) ? XY[idx] : V[(r - 2 * NXC) * DIMC + c];
        g_in0[idx] = v;
    }
    __nv_bfloat16 h, l; split2(v, h, l);
    g_inh[t] = h; g_inl[t] = l;
    if (c < 20) {
        __nv_bfloat16 z = __float2bfloat16(0.0f);
        size_t o = (size_t)r * PWH + HC + c;
        g_Ah0[o] = z; g_Al0[o] = z; g_Ah1[o] = z; g_Al1[o] = z;
        g_Bh0[o] = z; g_Bl0[o] = z; g_Bh1[o] = z; g_Bl1[o] = z;
        if (c < 12) {
            size_t of = (size_t)r * FDP + 100 + c;
            g_Fh[of] = z; g_Fl[of] = z;
        }
        if (c < 4) {
            size_t og = (size_t)r * GDP + 28 + c;
            g_Gh[og] = z; g_Gl[og] = z;
        }
    }
}
__global__ void init_acc_kernel() {
    int t = threadIdx.x;
    if (t < JC) g_colsum[t] = 0.0f;
    if (t < 8)  g_scal[t]   = 0.0f;
}
struct WPrepArgs {
    const float* W[12];
    int Fi[12];
    int Fo[12];
};
__global__ void prep_w_all(WPrepArgs a) {
    int layer = blockIdx.y;
    int idx = blockIdx.x * blockDim.x + threadIdx.x;
    if (idx >= WOFF) return;
    int k = idx / 320, n = idx - k * 320;
    int Fi = a.Fi[layer], Fo = a.Fo[layer];
    float v = (k < Fi && n < Fo) ? a.W[layer][(size_t)k * Fo + n] : 0.0f;
    __nv_bfloat16 h, l; split2(v, h, l);
    g_Wh[(size_t)layer * WOFF + idx] = h;
    g_Wl[(size_t)layer * WOFF + idx] = l;
}
// fused: both row norms (per warp) + V transpose (extra work on low blocks)
__global__ __launch_bounds__(256)
void post_fg_kernel() {
    int gw   = (blockIdx.x * blockDim.x + threadIdx.x) >> 5;   // global warp
    int lane = threadIdx.x & 31;
    if (gw < NTOT) {
        float sf = 0.0f;
        #pragma unroll 4
        for (int k = lane; k < FDP; k += 32) {
            size_t o = (size_t)gw * FDP + k;
            float v = __bfloat162float(g_Fh[o]) + __bfloat162float(g_Fl[o]);
            sf += v * v;
        }
        float sg;
        {
            size_t o = (size_t)gw * GDP + lane;
            float v = __bfloat162float(g_Gh[o]) + __bfloat162float(g_Gl[o]);
            sg = v * v;
        }
        #pragma unroll
        for (int o = 16; o; o >>= 1) {
            sf += __shfl_xor_sync(0xffffffffu, sf, o);
            sg += __shfl_xor_sync(0xffffffffu, sg, o);
        }
        if (lane == 0) { g_nF[gw] = sf; g_nG[gw] = sg; }
    }
    // transpose V slice: FDP*JC = 114688 elements over first 448 blocks
    int t = blockIdx.x * blockDim.x + threadIdx.x;
    if (t < FDP * JC) {
        int k = t >> 10, j = t & 1023;
        size_t src = (size_t)(2 * NXC + j) * FDP + k;
        g_FvTh[t] = g_Fh[src];
        g_FvTl[t] = g_Fl[src];
    }
    if (t < GDP * JC) {
        int k = t >> 10, j = t & 1023;
        size_t src = (size_t)(2 * NXC + j) * GDP + k;
        g_GvTh[t] = g_Gh[src];
        g_GvTl[t] = g_Gl[src];
    }
}

// =============== shared MMA helpers ==========================================
__device__ __forceinline__ uint32_t smem_u32(const void* p) {
    uint32_t a;
    asm("{ .reg .u64 t; cvta.to.shared.u64 t, %1; cvt.u32.u64 %0, t; }" : "=r"(a) : "l"(p));
    return a;
}
__device__ __forceinline__ void ldsm_x4(uint32_t addr, uint32_t r[4]) {
    asm volatile("ldmatrix.sync.aligned.m8n8.x4.shared.b16 {%0,%1,%2,%3}, [%4];"
        : "=r"(r[0]), "=r"(r[1]), "=r"(r[2]), "=r"(r[3]) : "r"(addr));
}
__device__ __forceinline__ void ldsm_x4_t(uint32_t addr, uint32_t r[4]) {
    asm volatile("ldmatrix.sync.aligned.m8n8.x4.trans.shared.b16 {%0,%1,%2,%3}, [%4];"
        : "=r"(r[0]), "=r"(r[1]), "=r"(r[2]), "=r"(r[3]) : "r"(addr));
}
__device__ __forceinline__ void mma_bf16(float c[4], const uint32_t a[4],
                                         uint32_t b0, uint32_t b1) {
    asm("mma.sync.aligned.m16n8k16.row.col.f32.bf16.bf16.f32 "
        "{%0,%1,%2,%3}, {%4,%5,%6,%7}, {%8,%9}, {%0,%1,%2,%3};"
        : "+f"(c[0]), "+f"(c[1]), "+f"(c[2]), "+f"(c[3])
        : "r"(a[0]), "r"(a[1]), "r"(a[2]), "r"(a[3]), "r"(b0), "r"(b1));
}
#define CP_ASYNC16(dst_u32, src_ptr) \
    asm volatile("cp.async.cg.shared.global [%0], [%1], 16;" \
        :: "r"(dst_u32), "l"(src_ptr) : "memory")
#define CP_COMMIT() asm volatile("cp.async.commit_group;" ::: "memory")
#define CP_WAIT(n)  asm volatile("cp.async.wait_group %0;" :: "n"(n) : "memory")

// ====== bf16-split GEMM: 2-stage, 3 CTAs/SM, issue-before-MMA, 1 sync/chunk ==
#define BMM 128
#define BNN 64
#define BKK 32
#define A_STRIDE 40
#define B_STRIDE 72
#define SM_AH 0
#define SM_AL 10240
#define SM_BH 20480
#define SM_BL 25088
#define GEMM_SMEM_BYTES 59392

__global__ __launch_bounds__(256, 3)
void mma_gemm3(const __nv_bfloat16* __restrict__ AhD, const __nv_bfloat16* __restrict__ AlD,
               const __nv_bfloat16* __restrict__ AhA, const __nv_bfloat16* __restrict__ AlA,
               int PWa,
               const __nv_bfloat16* __restrict__ WhB, const __nv_bfloat16* __restrict__ WlB,
               int layer,
               const float* __restrict__ biasD, const float* __restrict__ biasA,
               int FoD, int FoA,
               __nv_bfloat16* __restrict__ ChD, __nv_bfloat16* __restrict__ ClD,
               __nv_bfloat16* __restrict__ ChA, __nv_bfloat16* __restrict__ ClA,
               int PWcD, int PWcA,
               const float* __restrict__ resA,
               int nC, int doRelu)
{
    extern __shared__ __nv_bfloat16 dyn[];

    const int net = blockIdx.z;
    const __nv_bfloat16* Ah = net ? AhA : AhD;
    const __nv_bfloat16* Al = net ? AlA : AlD;
    const __nv_bfloat16* Wh = WhB + (size_t)(layer + 6 * net) * WOFF;
    const __nv_bfloat16* Wl = WlB + (size_t)(layer + 6 * net) * WOFF;
    const float* bias = net ? biasA : biasD;
    const int Fo  = net ? FoA : FoD;
    __nv_bfloat16* Ch = net ? ChA : ChD;
    __nv_bfloat16* Cl = net ? ClA : ClD;
    const int PWc = net ? PWcA : PWcD;
    const float* res = net ? resA : (const float*)0;

    const int n0 = blockIdx.x * BNN;
    if (n0 >= Fo) return;

    const int tid    = threadIdx.x;
    const int lane   = tid & 31;
    const int wid    = tid >> 5;
    const int warp_m = wid >> 1;
    const int warp_n = wid & 1;
    const int rbase  = blockIdx.y * BMM;

    const int a_row0 = tid >> 2;
    const int a_kk   = (tid & 3) * 8;
    const int bk     = tid >> 3;
    const int bn     = (tid & 7) * 8;

    const uint32_t dyn32 = smem_u32(dyn);
    const int a_row  = warp_m * 32 + (lane & 15);
    const int a_kadd = (lane >> 4) * 8;
    const uint32_t aHiB = dyn32 + (uint32_t)(SM_AH + a_row * A_STRIDE + a_kadd) * 2u;
    const uint32_t aLoB = dyn32 + (uint32_t)(SM_AL + a_row * A_STRIDE + a_kadd) * 2u;
    const int b_k = (lane & 7) + ((lane & 8) ? 8 : 0);
    const int b_n = warp_n * 32 + ((lane & 16) ? 8 : 0);
    const uint32_t bHiB = dyn32 + (uint32_t)(SM_BH + b_k * B_STRIDE + b_n) * 2u;
    const uint32_t bLoB = dyn32 + (uint32_t)(SM_BL + b_k * B_STRIDE + b_n) * 2u;

    const uint32_t dA0 = dyn32 + (uint32_t)(a_row0 * A_STRIDE + a_kk) * 2u;
    const uint32_t dB0 = dyn32 + (uint32_t)(SM_BH + bk * B_STRIDE + bn) * 2u;

    float acc[2][4][4];
    #pragma unroll
    for (int i = 0; i < 2; i++)
        #pragma unroll
        for (int j = 0; j < 4; j++)
            #pragma unroll
            for (int q = 0; q < 4; q++) acc[i][j][q] = 0.0f;

    #define ISSUE_CHUNK(k0, bf) do { \
        uint32_t od = (uint32_t)(bf) * 10240u; \
        uint32_t ob = (uint32_t)(bf) * 4608u; \
        size_t o0 = (size_t)(rbase + a_row0) * PWa + (k0) + a_kk; \
        size_t o1 = (size_t)(rbase + a_row0 + 64) * PWa + (k0) + a_kk; \
        uint32_t d1 = dA0 + od + (uint32_t)(64 * A_STRIDE) * 2u; \
        CP_ASYNC16(dA0 + od,           Ah + o0); \
        CP_ASYNC16(dA0 + od + 20480u,  Al + o0); \
        CP_ASYNC16(d1,                 Ah + o1); \
        CP_ASYNC16(d1 + 20480u,        Al + o1); \
        size_t bo = (size_t)((k0) + bk) * 320 + n0 + bn; \
        CP_ASYNC16(dB0 + ob,           Wh + bo); \
        CP_ASYNC16(dB0 + ob + 9216u,   Wl + bo); \
        CP_COMMIT(); \
    } while (0)

    ISSUE_CHUNK(0, 0);

    for (int c = 0; c < nC; c++) {
        const int buf = c & 1;
        const uint32_t aOff = (uint32_t)buf * 10240u;
        const uint32_t bOff = (uint32_t)buf * 4608u;

        CP_WAIT(0);
        __syncthreads();

        if (c + 1 < nC) ISSUE_CHUNK((c + 1) * BKK, (c + 1) & 1);

        #pragma unroll
        for (int ks = 0; ks < 2; ks++) {
            uint32_t Bhr[2][4], Blr[2][4];
            #pragma unroll
            for (int np = 0; np < 2; np++) {
                uint32_t off = bOff + (uint32_t)(np * 16 + ks * 16 * B_STRIDE) * 2u;
                ldsm_x4_t(bHiB + off, Bhr[np]);
                ldsm_x4_t(bLoB + off, Blr[np]);
            }
            #pragma unroll
            for (int mi = 0; mi < 2; mi++) {
                uint32_t Ahr[4], Alr[4];
                uint32_t off = aOff + (uint32_t)(mi * 16 * A_STRIDE + ks * 16) * 2u;
                ldsm_x4(aHiB + off, Ahr);
                ldsm_x4(aLoB + off, Alr);
                #pragma unroll
                for (int nj = 0; nj < 4; nj++) {
                    const int np = nj >> 1, hf = (nj & 1) * 2;
                    mma_bf16(acc[mi][nj], Ahr, Bhr[np][hf], Bhr[np][hf + 1]);
                    mma_bf16(acc[mi][nj], Ahr, Blr[np][hf], Blr[np][hf + 1]);
                    mma_bf16(acc[mi][nj], Alr, Bhr[np][hf], Bhr[np][hf + 1]);
                }
            }
        }
    }
    #undef ISSUE_CHUNK

    // epilogue — writes bf16 hi/lo at stride PWc
    #pragma unroll
    for (int mi = 0; mi < 2; mi++)
        #pragma unroll
        for (int nj = 0; nj < 4; nj++) {
            int col = n0 + warp_n * 32 + nj * 8 + (lane & 3) * 2;
            if (col >= Fo) continue;
            float2 b2 = *(const float2*)(bias + col);
            #pragma unroll
            for (int half = 0; half < 2; half++) {
                int row = rbase + warp_m * 32 + mi * 16 + (lane >> 2) + half * 8;
                float vx = acc[mi][nj][half * 2 + 0] + b2.x;
                float vy = acc[mi][nj][half * 2 + 1] + b2.y;
                if (res) {
                    float2 r2 = *(const float2*)(res + (size_t)row * Fo + col);
                    vx += r2.x; vy += r2.y;
                }
                if (doRelu) { vx = fmaxf(vx, 0.0f); vy = fmaxf(vy, 0.0f); }
                __nv_bfloat16 hx, lx, hy, ly;
                split2(vx, hx, lx); split2(vy, hy, ly);
                *(__nv_bfloat162*)(Ch + (size_t)row * PWc + col) = __halves2bfloat162(hx, hy);
                *(__nv_bfloat162*)(Cl + (size_t)row * PWc + col) = __halves2bfloat162(lx, ly);
            }
        }
}

// ---------------- fused fm kernel: disjoint smem, single sync ----------------
#define FMI 64
#define FMJ 128
#define AF_S 120
#define BF_S 136
#define AG_S 40
#define OF_AXH 0
#define OF_AXL 7680
#define OF_AYH 15360
#define OF_AYL 23040
#define OF_BH  30720
#define OF_BL  45952
#define OG_AXH 61184
#define OG_AXL 63744
#define OG_AYH 66304
#define OG_AYL 68864
#define OG_BH  71424
#define OG_BL  75776
#define FM_DYN_BYTES (80128 * 2)

__global__ __launch_bounds__(512)
void fm3_kernel(const float* __restrict__ eps_p, const float* __restrict__ sig_p,
                const float* __restrict__ sig0_p, const float* __restrict__ cst_p)
{
    extern __shared__ __nv_bfloat16 dynb[];
    __shared__ float nfx[64], nfy[64], ngx[64], ngy[64];
    __shared__ float nfv[128], ngv[128];
    __shared__ float scs[128];
    __shared__ float red16[16];

    const int tid    = threadIdx.x;
    const int lane   = tid & 31;
    const int wid    = tid >> 5;
    const int warp_m = wid >> 3;
    const int warp_n = wid & 7;
    const int ibase  = blockIdx.y * FMI;
    const int jbase  = blockIdx.x * FMJ;
    const int XR = ibase, YR = NXC + ibase, VR = 2 * NXC + jbase;

    if (tid < 64) {
        nfx[tid] = g_nF[XR + tid]; nfy[tid] = g_nF[YR + tid];
        ngx[tid] = g_nG[XR + tid]; ngy[tid] = g_nG[YR + tid];
    } else if (tid < 192) {
        int j = tid - 64;
        nfv[j] = g_nF[VR + j]; ngv[j] = g_nG[VR + j];
    } else if (tid < 320) {
        scs[tid - 192] = 0.0f;
    }

    for (int e = tid; e < 896; e += 512) {
        int r = e / 14, kv = (e % 14) * 8;
        *(uint4*)&dynb[OF_AXH + r * AF_S + kv] = *(const uint4*)&g_Fh[(size_t)(XR + r) * FDP + kv];
        *(uint4*)&dynb[OF_AXL + r * AF_S + kv] = *(const uint4*)&g_Fl[(size_t)(XR + r) * FDP + kv];
        *(uint4*)&dynb[OF_AYH + r * AF_S + kv] = *(const uint4*)&g_Fh[(size_t)(YR + r) * FDP + kv];
        *(uint4*)&dynb[OF_AYL + r * AF_S + kv] = *(const uint4*)&g_Fl[(size_t)(YR + r) * FDP + kv];
    }
    for (int e = tid; e < 1792; e += 512) {
        int k = e >> 4, jv = (e & 15) * 8;
        *(uint4*)&dynb[OF_BH + k * BF_S + jv] = *(const uint4*)&g_FvTh[k * 1024 + jbase + jv];
        *(uint4*)&dynb[OF_BL + k * BF_S + jv] = *(const uint4*)&g_FvTl[k * 1024 + jbase + jv];
    }
    if (tid < 256) {
        int r = tid >> 2, kv = (tid & 3) * 8;
        *(uint4*)&dynb[OG_AXH + r * AG_S + kv] = *(const uint4*)&g_Gh[(size_t)(XR + r) * GDP + kv];
        *(uint4*)&dynb[OG_AXL + r * AG_S + kv] = *(const uint4*)&g_Gl[(size_t)(XR + r) * GDP + kv];
        *(uint4*)&dynb[OG_AYH + r * AG_S + kv] = *(const uint4*)&g_Gh[(size_t)(YR + r) * GDP + kv];
        *(uint4*)&dynb[OG_AYL + r * AG_S + kv] = *(const uint4*)&g_Gl[(size_t)(YR + r) * GDP + kv];
    }
    {
        int k = tid >> 4, jv = (tid & 15) * 8;
        *(uint4*)&dynb[OG_BH + k * BF_S + jv] = *(const uint4*)&g_GvTh[k * 1024 + jbase + jv];
        *(uint4*)&dynb[OG_BL + k * BF_S + jv] = *(const uint4*)&g_GvTl[k * 1024 + jbase + jv];
    }
    __syncthreads();

    const uint32_t dyn32 = smem_u32(dynb);
    const int a_row  = warp_m * 32 + (lane & 15);
    const int a_kadd = (lane >> 4) * 8;
    const int b_k    = lane & 15;
    const int b_n    = warp_n * 16 + ((lane & 16) ? 8 : 0);

    float accX[2][2][4], accY[2][2][4];
    #pragma unroll
    for (int i = 0; i < 2; i++)
        #pragma unroll
        for (int j = 0; j < 2; j++)
            #pragma unroll
            for (int q = 0; q < 4; q++) { accX[i][j][q] = 0.0f; accY[i][j][q] = 0.0f; }

    #pragma unroll
    for (int ks = 0; ks < 7; ks++) {
        uint32_t AXh[2][4], AXl[2][4], AYh[2][4], AYl[2][4], Bh[4], Bl[4];
        #pragma unroll
        for (int mi = 0; mi < 2; mi++) {
            uint32_t ao = (uint32_t)((a_row + mi * 16) * AF_S + ks * 16 + a_kadd) * 2u;
            ldsm_x4(dyn32 + OF_AXH * 2u + ao, AXh[mi]);
            ldsm_x4(dyn32 + OF_AXL * 2u + ao, AXl[mi]);
            ldsm_x4(dyn32 + OF_AYH * 2u + ao, AYh[mi]);
            ldsm_x4(dyn32 + OF_AYL * 2u + ao, AYl[mi]);
        }
        {
            uint32_t bo = (uint32_t)((b_k + ks * 16) * BF_S + b_n) * 2u;
            ldsm_x4_t(dyn32 + OF_BH * 2u + bo, Bh);
            ldsm_x4_t(dyn32 + OF_BL * 2u + bo, Bl);
        }
        #pragma unroll
        for (int mi = 0; mi < 2; mi++)
            #pragma unroll
            for (int nj = 0; nj < 2; nj++) {
                const int hf = nj * 2;
                mma_bf16(accX[mi][nj], AXh[mi], Bh[hf], Bh[hf + 1]);
                mma_bf16(accX[mi][nj], AXh[mi], Bl[hf], Bl[hf + 1]);
                mma_bf16(accX[mi][nj], AXl[mi], Bh[hf], Bh[hf + 1]);
                mma_bf16(accY[mi][nj], AYh[mi], Bh[hf], Bh[hf + 1]);
                mma_bf16(accY[mi][nj], AYh[mi], Bl[hf], Bl[hf + 1]);
                mma_bf16(accY[mi][nj], AYl[mi], Bh[hf], Bh[hf + 1]);
            }
    }

    const float LOG2E  = 1.4426950408889634f;
    const float ep     = 1.0f / (1.0f + __expf(-eps_p[0]));
    const float is2    = LOG2E / (sig_p[0]  * sig_p[0]);
    const float is0    = LOG2E / (sig0_p[0] * sig0_p[0]);
    const float cstv   = cst_p[0];
    const float one_ep = 1.0f - ep;

    #pragma unroll
    for (int mi = 0; mi < 2; mi++)
        #pragma unroll
        for (int nj = 0; nj < 2; nj++)
            #pragma unroll
            for (int q = 0; q < 4; q++) {
                int rl = warp_m * 32 + mi * 16 + (lane >> 2) + (q >> 1) * 8;
                int cl = warp_n * 16 + nj * 8 + (lane & 3) * 2 + (q & 1);
                float Dx = fmaxf(nfx[rl] + nfv[cl] - 2.0f * accX[mi][nj][q], 0.0f);
                float Dy = fmaxf(nfy[rl] + nfv[cl] - 2.0f * accY[mi][nj][q], 0.0f);
                accX[mi][nj][q] = fmaf(one_ep, fexp2(-Dx * is0), ep);
                accY[mi][nj][q] = fmaf(one_ep, fexp2(-Dy * is0), ep);
            }

    float gX[2][2][4], gY[2][2][4];
    #pragma unroll
    for (int i = 0; i < 2; i++)
        #pragma unroll
        for (int j = 0; j < 2; j++)
            #pragma unroll
            for (int q = 0; q < 4; q++) { gX[i][j][q] = 0.0f; gY[i][j][q] = 0.0f; }

    #pragma unroll
    for (int ks = 0; ks < 2; ks++) {
        uint32_t AXh[2][4], AXl[2][4], AYh[2][4], AYl[2][4], Bh[4], Bl[4];
        #pragma unroll
        for (int mi = 0; mi < 2; mi++) {
            uint32_t ao = (uint32_t)((a_row + mi * 16) * AG_S + ks * 16 + a_kadd) * 2u;
            ldsm_x4(dyn32 + OG_AXH * 2u + ao, AXh[mi]);
            ldsm_x4(dyn32 + OG_AXL * 2u + ao, AXl[mi]);
            ldsm_x4(dyn32 + OG_AYH * 2u + ao, AYh[mi]);
            ldsm_x4(dyn32 + OG_AYL * 2u + ao, AYl[mi]);
        }
        {
            uint32_t bo = (uint32_t)((b_k + ks * 16) * BF_S + b_n) * 2u;
            ldsm_x4_t(dyn32 + OG_BH * 2u + bo, Bh);
            ldsm_x4_t(dyn32 + OG_BL * 2u + bo, Bl);
        }
        #pragma unroll
        for (int mi = 0; mi < 2; mi++)
            #pragma unroll
            for (int nj = 0; nj < 2; nj++) {
                const int hf = nj * 2;
                mma_bf16(gX[mi][nj], AXh[mi], Bh[hf], Bh[hf + 1]);
                mma_bf16(gX[mi][nj], AXh[mi], Bl[hf], Bl[hf + 1]);
                mma_bf16(gX[mi][nj], AXl[mi], Bh[hf], Bh[hf + 1]);
                mma_bf16(gY[mi][nj], AYh[mi], Bh[hf], Bh[hf + 1]);
                mma_bf16(gY[mi][nj], AYh[mi], Bl[hf], Bl[hf + 1]);
                mma_bf16(gY[mi][nj], AYl[mi], Bh[hf], Bh[hf + 1]);
            }
    }

    const float RS = 0.03125f;
    float csum[4];
    #pragma unroll
    for (int i = 0; i < 4; i++) csum[i] = 0.0f;
    float qacc = 0.0f;

    #pragma unroll
    for (int mi = 0; mi < 2; mi++)
        #pragma unroll
        for (int nj = 0; nj < 2; nj++) {
            float vq[4];
            #pragma unroll
            for (int q = 0; q < 4; q++) {
                int rl = warp_m * 32 + mi * 16 + (lane >> 2) + (q >> 1) * 8;
                int cl = warp_n * 16 + nj * 8 + (lane & 3) * 2 + (q & 1);
                float Dgx = fmaxf(ngx[rl] + ngv[cl] - 2.0f * gX[mi][nj][q], 0.0f);
                float Dgy = fmaxf(ngy[rl] + ngv[cl] - 2.0f * gY[mi][nj][q], 0.0f);
                float KX = cstv * accX[mi][nj][q] * fexp2(-Dgx * is2);
                float KY = cstv * accY[mi][nj][q] * fexp2(-Dgy * is2);
                float v = (KX - KY) * RS;
                vq[q] = v;
                csum[nj * 2 + (q & 1)] += v;
                qacc += v * v;
            }
            int colg = jbase + warp_n * 16 + nj * 8 + (lane & 3) * 2;
            int row0 = ibase + warp_m * 32 + mi * 16 + (lane >> 2);
            *(__nv_bfloat162*)&g_fmb[(size_t)row0 * JC + colg] =
                __floats2bfloat162_rn(vq[0], vq[1]);
            *(__nv_bfloat162*)&g_fmb[(size_t)(row0 + 8) * JC + colg] =
                __floats2bfloat162_rn(vq[2], vq[3]);
        }

    #pragma unroll
    for (int off = 16; off >= 4; off >>= 1)
        #pragma unroll
        for (int c4 = 0; c4 < 4; c4++)
            csum[c4] += __shfl_down_sync(0xffffffffu, csum[c4], off);
    if (lane < 4) {
        #pragma unroll
        for (int c4 = 0; c4 < 4; c4++) {
            int cl = warp_n * 16 + (c4 >> 1) * 8 + lane * 2 + (c4 & 1);
            atomicAdd(&scs[cl], csum[c4]);
        }
    }
    #pragma unroll
    for (int off = 16; off; off >>= 1)
        qacc += __shfl_xor_sync(0xffffffffu, qacc, off);
    if (lane == 0) red16[wid] = qacc;
    __syncthreads();

    if (tid < 128) atomicAdd(&g_colsum[jbase + tid], scs[tid]);
    if (wid == 0) {
        float v = (lane < 16) ? red16[lane] : 0.0f;
        #pragma unroll
        for (int off = 8; off; off >>= 1)
            v += __shfl_xor_sync(0xffffffffu, v, off);
        if (lane == 0) atomicAdd(&g_scal[0], v);
    }
}

// ---------------- mu + sum(mu^2) ----------------------------------------------
__global__ void mu_kernel() {
    __shared__ float red[JC];
    int j = threadIdx.x;
    float m = g_colsum[j] * (1.0f / (float)NXC);
    g_mu[j] = m;
    red[j] = m * m;
    __syncthreads();
    for (int s = 512; s; s >>= 1) {
        if (j < s) red[j] += red[j + s];
        __syncthreads();
    }
    if (j == 0) g_scal[2] = red[0];
}

// ---------------- s_i = fm[i]·mu (bf16 fm) ; accumulate s_i^2 -----------------
__global__ __launch_bounds__(256) void s2_kernel() {
    __shared__ float smu[JC];
    int tid = threadIdx.x;
    for (int e = tid; e < JC; e += 256) smu[e] = g_mu[e];
    __syncthreads();
    int row  = blockIdx.x * 8 + (tid >> 5);
    int lane = tid & 31;
    const __nv_bfloat16* rp = g_fmb + (size_t)row * JC;
    float s = 0.0f;
    #pragma unroll
    for (int t = 0; t < 4; t++) {
        int c = lane * 8 + 256 * t;
        uint4 v = *(const uint4*)(rp + c);
        const __nv_bfloat16* pv = (const __nv_bfloat16*)&v;
        #pragma unroll
        for (int e = 0; e < 8; e++)
            s += __bfloat162float(pv[e]) * smu[c + e];
    }
    #pragma unroll
    for (int o = 16; o; o >>= 1) s += __shfl_xor_sync(0xffffffffu, s, o);
    if (lane == 0) atomicAdd(&g_scal[1], s * s);
}

// ---------------- finalize ------------------------------------------------------
__global__ void finalize_kernel(float* out) {
    double sumfm2 = (double)g_scal[0];
    double sums2  = (double)g_scal[1];
    double summu2 = (double)g_scal[2];
    double nx = (double)NXC;
    double t1 = summu2 * (nx / (nx - 1.0));
    double t2 = sumfm2 / nx / (nx - 1.0);
    double mean = t1 - t2;
    double var  = 4.0 * (sums2 / nx) - 4.0 * summu2 * summu2;
    out[0] = (float)(-(mean / sqrt(var + 1e-6)));
}

// ---------------- launch ---------------------------------------------------------
extern "C" void kernel_launch(void* const* d_in, const int* in_sizes, int n_in,
                              void* d_out, int out_size)
{
    const float* XY = (const float*)d_in[0];
    const float* V  = (const float*)d_in[1];
    const float *dnW[6], *dnb[6], *anW[6], *anb[6];
    for (int i = 0; i < 6; i++) {
        dnW[i] = (const float*)d_in[2 + 2 * i];
        dnb[i] = (const float*)d_in[3 + 2 * i];
        anW[i] = (const float*)d_in[14 + 2 * i];
        anb[i] = (const float*)d_in[15 + 2 * i];
    }
    const float* eps   = (const float*)d_in[26];
    const float* sig   = (const float*)d_in[27];
    const float* sig0  = (const float*)d_in[28];
    const float* cstp  = (const float*)d_in[29];

    float *in0;
    __nv_bfloat16 *inh, *inl, *h0, *l0, *h1, *l1, *b0h, *b0l, *b1h, *b1l;
    __nv_bfloat16 *Wh, *Wl, *Fh, *Fl, *Gh, *Gl;
    cudaGetSymbolAddress((void**)&in0, g_in0);
    cudaGetSymbolAddress((void**)&inh, g_inh);
    cudaGetSymbolAddress((void**)&inl, g_inl);
    cudaGetSymbolAddress((void**)&h0,  g_Ah0);
    cudaGetSymbolAddress((void**)&l0,  g_Al0);
    cudaGetSymbolAddress((void**)&h1,  g_Ah1);
    cudaGetSymbolAddress((void**)&l1,  g_Al1);
    cudaGetSymbolAddress((void**)&b0h, g_Bh0);
    cudaGetSymbolAddress((void**)&b0l, g_Bl0);
    cudaGetSymbolAddress((void**)&b1h, g_Bh1);
    cudaGetSymbolAddress((void**)&b1l, g_Bl1);
    cudaGetSymbolAddress((void**)&Wh,  g_Wh);
    cudaGetSymbolAddress((void**)&Wl,  g_Wl);
    cudaGetSymbolAddress((void**)&Fh,  g_Fh);
    cudaGetSymbolAddress((void**)&Fl,  g_Fl);
    cudaGetSymbolAddress((void**)&Gh,  g_Gh);
    cudaGetSymbolAddress((void**)&Gl,  g_Gl);

    const int GY = NTOT / BMM;     // 520
    const dim3 blk(256);

    prep_in_pad_kernel<<<(NTOT * 32 + 255) / 256, 256>>>(XY, V);
    init_acc_kernel<<<1, 1024>>>();

    WPrepArgs wa;
    for (int i = 0; i < 6; i++) {
        wa.W[i]     = dnW[i];  wa.W[i + 6] = anW[i];
        wa.Fi[i]    = (i == 0) ? DIMC : HC;
        wa.Fi[i+6]  = (i == 0) ? DIMC : HC;
        wa.Fo[i]    = (i == 5) ? FD : HC;
        wa.Fo[i+6]  = (i == 5) ? GD : HC;
    }
    prep_w_all<<<dim3((WOFF + 255) / 256, 12), 256>>>(wa);

    cudaFuncSetAttribute(mma_gemm3, cudaFuncAttributeMaxDynamicSharedMemorySize,
                         GEMM_SMEM_BYTES);
    const dim3 gH(5, GY, 2);
    const dim3 gL5(2, GY, 2);

    #define GEMM3(grid, AhD,AlD,AhA,AlA, PWa, L, bD,bA, FoD,FoA, ChD,ClD,ChA,ClA, PWcD,PWcA, resA, nC, relu) \
        mma_gemm3<<<grid, blk, GEMM_SMEM_BYTES>>>(AhD,AlD,AhA,AlA, PWa, Wh, Wl, L, \
            bD,bA, FoD,FoA, ChD,ClD,ChA,ClA, PWcD,PWcA, resA, nC, relu)

    GEMM3(gH, inh,inl, inh,inl, 32, 0, dnb[0],anb[0], HC,HC, h0,l0, b0h,b0l, PWH,PWH, (const float*)0, 1, 1);
    GEMM3(gH, h0,l0, b0h,b0l, PWH, 1, dnb[1],anb[1], HC,HC, h1,l1, b1h,b1l, PWH,PWH, (const float*)0, 10, 1);
    GEMM3(gH, h1,l1, b1h,b1l, PWH, 2, dnb[2],anb[2], HC,HC, h0,l0, b0h,b0l, PWH,PWH, (const float*)0, 10, 1);
    GEMM3(gH, h0,l0, b0h,b0l, PWH, 3, dnb[3],anb[3], HC,HC, h1,l1, b1h,b1l, PWH,PWH, (const float*)0, 10, 1);
    GEMM3(gH, h1,l1, b1h,b1l, PWH, 4, dnb[4],anb[4], HC,HC, h0,l0, b0h,b0l, PWH,PWH, (const float*)0, 10, 1);
    GEMM3(gL5, h0,l0, b0h,b0l, PWH, 5, dnb[5],anb[5], FD,GD, Fh,Fl, Gh,Gl, FDP,GDP, in0, 10, 0);

    // fused norms + V transpose
    post_fg_kernel<<<(NTOT * 32 + 255) / 256, 256>>>();

    cudaFuncSetAttribute(fm3_kernel, cudaFuncAttributeMaxDynamicSharedMemorySize,
                         FM_DYN_BYTES);
    fm3_kernel<<<dim3(JC / FMJ, NXC / FMI), 512, FM_DYN_BYTES>>>(eps, sig, sig0, cstp);

    mu_kernel<<<1, JC>>>();
    s2_kernel<<<NXC / 8, 256>>>();
    finalize_kernel<<<1, 1>>>((float*)d_out);
}